// round 1
// baseline (speedup 1.0000x reference)
#include <cuda_runtime.h>
#include <math.h>

// Problem constants
#define B_   2
#define T_   2048
#define C_   1024
#define H_   16
#define G_   4
#define DQK_ 64
#define DV_  128
#define NT_  (B_ * T_)   // 4096 tokens

// Device scratch (no cudaMalloc allowed)
__device__ float g_q[(size_t)NT_ * (H_ * DQK_)];   // [token][h*64+d]  (post rope/norm/scale)
__device__ float g_k[(size_t)NT_ * (G_ * DQK_)];   // [token][g*64+d]
__device__ float g_v[(size_t)NT_ * (G_ * DV_)];    // [token][g*128+d]
__device__ float g_y[(size_t)NT_ * DV_];           // head-summed attention output

// ---------------------------------------------------------------------------
// Generic fp32 GEMM: C[M,N] = A[M,K] @ B[K,N], row-major, M fixed by grid.y*128
// BM=BN=128, BK=8, 256 threads, 8x8 microtile.
// ---------------------------------------------------------------------------
__global__ __launch_bounds__(256) void sgemm128(
    const float* __restrict__ A, const float* __restrict__ B,
    float* __restrict__ C, int N, int K)
{
    __shared__ float As[8][132];
    __shared__ float Bs[8][132];
    const int tid  = threadIdx.x;
    const int m0   = blockIdx.y * 128;
    const int n0   = blockIdx.x * 128;
    const int arow = tid >> 1;          // 0..127
    const int acol = (tid & 1) << 2;    // 0 or 4
    const int brow = tid >> 5;          // 0..7
    const int bcol = (tid & 31) << 2;   // 0..124
    const int tm   = (tid >> 4) << 3;   // 0..120
    const int tn   = (tid & 15) << 3;   // 0..120

    float acc[8][8];
    #pragma unroll
    for (int i = 0; i < 8; i++)
        #pragma unroll
        for (int j = 0; j < 8; j++) acc[i][j] = 0.f;

    for (int k0 = 0; k0 < K; k0 += 8) {
        float4 av = *(const float4*)(A + (size_t)(m0 + arow) * K + k0 + acol);
        As[acol + 0][arow] = av.x;
        As[acol + 1][arow] = av.y;
        As[acol + 2][arow] = av.z;
        As[acol + 3][arow] = av.w;
        *(float4*)&Bs[brow][bcol] =
            *(const float4*)(B + (size_t)(k0 + brow) * N + n0 + bcol);
        __syncthreads();
        #pragma unroll
        for (int k = 0; k < 8; k++) {
            float ra[8], rb[8];
            #pragma unroll
            for (int i = 0; i < 8; i++) ra[i] = As[k][tm + i];
            #pragma unroll
            for (int j = 0; j < 8; j++) rb[j] = Bs[k][tn + j];
            #pragma unroll
            for (int i = 0; i < 8; i++)
                #pragma unroll
                for (int j = 0; j < 8; j++)
                    acc[i][j] = fmaf(ra[i], rb[j], acc[i][j]);
        }
        __syncthreads();
    }

    #pragma unroll
    for (int i = 0; i < 8; i++)
        #pragma unroll
        for (int j = 0; j < 8; j += 4) {
            float4 v = make_float4(acc[i][j], acc[i][j+1], acc[i][j+2], acc[i][j+3]);
            *(float4*)(C + (size_t)(m0 + tm + i) * N + n0 + tn + j) = v;
        }
}

// ---------------------------------------------------------------------------
// RoPE + L2-norm (+ learned logit scale for q), in-place on g_q / g_k.
// One warp per (token, head). Lane l owns elements l and l+32 (a RoPE pair).
// Angles computed in double so we sit at the "exact" value; the reference's
// own fp32 quantization (~6e-5 rad at t=2047) bounds the residual.
// ---------------------------------------------------------------------------
__global__ void rope_norm_kernel(const float* __restrict__ qnf)
{
    const int warp = (blockIdx.x * blockDim.x + threadIdx.x) >> 5;
    const int lane = threadIdx.x & 31;
    if (warp >= NT_ * 20) return;
    const int token = warp / 20;      // b*2048 + t
    const int slot  = warp % 20;      // 0..15 -> q head, 16..19 -> k group
    const int t     = token & (T_ - 1);

    float* base;
    if (slot < 16) base = g_q + (size_t)token * (H_ * DQK_) + slot * DQK_;
    else           base = g_k + (size_t)token * (G_ * DQK_) + (slot - 16) * DQK_;

    const float x0 = base[lane];
    const float x1 = base[lane + 32];

    const double inv = exp(-(double)lane * (log(10000.0) / 32.0));
    const double ang = (double)t * inv;
    const float c = (float)cos(ang);
    const float s = (float)sin(ang);

    const float r0 = x0 * c - x1 * s;
    const float r1 = x1 * c + x0 * s;

    float ss = r0 * r0 + r1 * r1;
    #pragma unroll
    for (int o = 16; o > 0; o >>= 1) ss += __shfl_xor_sync(0xFFFFFFFFu, ss, o);

    float scale = 1.f / (sqrtf(ss) + 1e-6f);
    if (slot < 16) scale *= qnf[0];   // net logit scale g (sqrt(d) cancels)

    base[lane]      = r0 * scale;
    base[lane + 32] = r1 * scale;
}

__global__ void zero_y_kernel()
{
    const size_t i = (size_t)blockIdx.x * blockDim.x + threadIdx.x;
    if (i < (size_t)NT_ * DV_) g_y[i] = 0.f;
}

// ---------------------------------------------------------------------------
// Flash attention with sink (flash-lobo) + causal mask + GQA + head-sum.
// Block: 256 threads, one (batch, head, 64-query tile).
// Online softmax initialized with the sink: m = lobo[h], l = 1, acc = 0.
// Head-sum merge via atomicAdd into g_y.
// ---------------------------------------------------------------------------
struct AttnSmem {
    float Qs[64][68];
    float Ks[64][68];
    float Ss[64][68];
    float Vs[64][132];
    float m[64];
    float l[64];
    float corr[64];
    float red[4][64];
};

__global__ __launch_bounds__(256) void attn_kernel(const float* __restrict__ lobo)
{
    extern __shared__ char smem_raw[];
    AttnSmem& S = *reinterpret_cast<AttnSmem*>(smem_raw);

    const int tid = threadIdx.x;
    const int qt  = blockIdx.x;          // 0..31  query tile
    const int h   = blockIdx.y;          // 0..15
    const int b   = blockIdx.z;          // 0..1
    const int g   = h >> 2;              // GQA group (repeat_interleave)
    const int q0  = qt * 64;
    const size_t tokbase = (size_t)b * T_;

    // Load Q tile (64x64) — 16 floats/thread
    {
        const int r  = tid >> 2;
        const int kc = (tid & 3) << 4;
        const float* src = g_q + (tokbase + q0 + r) * (H_ * DQK_) + h * DQK_ + kc;
        #pragma unroll
        for (int u = 0; u < 4; u++)
            *(float4*)&S.Qs[r][kc + u * 4] = *(const float4*)(src + u * 4);
    }
    if (tid < 64) { S.m[tid] = lobo[h]; S.l[tid] = 1.f; }

    const int tr = tid >> 4;   // 0..15
    const int tc = tid & 15;   // 0..15
    float acc[4][8];
    #pragma unroll
    for (int i = 0; i < 4; i++)
        #pragma unroll
        for (int j = 0; j < 8; j++) acc[i][j] = 0.f;

    const int nkt = qt + 1;    // causal: key tiles 0..qt
    for (int kt = 0; kt < nkt; ++kt) {
        const int k0 = kt * 64;
        __syncthreads();   // prev iter's consumers done (also covers Q/m/l init)

        // Load K tile (64x64)
        {
            const int c  = tid >> 2;
            const int kc = (tid & 3) << 4;
            const float* src = g_k + (tokbase + k0 + c) * (G_ * DQK_) + g * DQK_ + kc;
            #pragma unroll
            for (int u = 0; u < 4; u++)
                *(float4*)&S.Ks[c][kc + u * 4] = *(const float4*)(src + u * 4);
        }
        // Load V tile (64x128)
        {
            const int c  = tid >> 2;
            const int dc = (tid & 3) << 5;
            const float* src = g_v + (tokbase + k0 + c) * (G_ * DV_) + g * DV_ + dc;
            #pragma unroll
            for (int u = 0; u < 8; u++)
                *(float4*)&S.Vs[c][dc + u * 4] = *(const float4*)(src + u * 4);
        }
        __syncthreads();

        // S = Q K^T (4x4 microtile per thread), mask diagonal tile
        {
            float s[4][4];
            #pragma unroll
            for (int i = 0; i < 4; i++)
                #pragma unroll
                for (int j = 0; j < 4; j++) s[i][j] = 0.f;
            #pragma unroll 4
            for (int k = 0; k < 64; k += 4) {
                float4 qv[4], kv[4];
                #pragma unroll
                for (int i = 0; i < 4; i++) qv[i] = *(const float4*)&S.Qs[tr * 4 + i][k];
                #pragma unroll
                for (int j = 0; j < 4; j++) kv[j] = *(const float4*)&S.Ks[tc * 4 + j][k];
                #pragma unroll
                for (int i = 0; i < 4; i++)
                    #pragma unroll
                    for (int j = 0; j < 4; j++)
                        s[i][j] += qv[i].x * kv[j].x + qv[i].y * kv[j].y
                                 + qv[i].z * kv[j].z + qv[i].w * kv[j].w;
            }
            const bool diag = (kt == qt);
            #pragma unroll
            for (int i = 0; i < 4; i++)
                #pragma unroll
                for (int j = 0; j < 4; j++) {
                    const int r = tr * 4 + i, c = tc * 4 + j;
                    float v = s[i][j];
                    if (diag && c > r) v = -1e30f;
                    S.Ss[r][c] = v;
                }
        }
        __syncthreads();

        // Phase A: partial row max
        {
            const int r = tid & 63, qc = tid >> 6;
            float mx = -1e30f;
            #pragma unroll
            for (int j = 0; j < 16; j++) mx = fmaxf(mx, S.Ss[r][qc * 16 + j]);
            S.red[qc][r] = mx;
        }
        __syncthreads();

        // Phase B: new max + correction factor
        if (tid < 64) {
            const float mo = S.m[tid];
            float mn = mo;
            #pragma unroll
            for (int q = 0; q < 4; q++) mn = fmaxf(mn, S.red[q][tid]);
            S.corr[tid] = __expf(mo - mn);
            S.m[tid] = mn;
        }
        __syncthreads();

        // Phase C: exponentiate in place + partial sums
        {
            const int r = tid & 63, qc = tid >> 6;
            const float mr = S.m[r];
            float sum = 0.f;
            #pragma unroll
            for (int j = 0; j < 16; j++) {
                const float p = __expf(S.Ss[r][qc * 16 + j] - mr);
                S.Ss[r][qc * 16 + j] = p;
                sum += p;
            }
            S.red[qc][r] = sum;
        }
        __syncthreads();

        // Phase D: update l (threads < 64); all threads rescale acc and do PV
        if (tid < 64) {
            float lv = S.l[tid] * S.corr[tid];
            #pragma unroll
            for (int q = 0; q < 4; q++) lv += S.red[q][tid];
            S.l[tid] = lv;
        }
        #pragma unroll
        for (int i = 0; i < 4; i++) {
            const float cf = S.corr[tr * 4 + i];
            #pragma unroll
            for (int j = 0; j < 8; j++) acc[i][j] *= cf;
        }
        #pragma unroll 4
        for (int k = 0; k < 64; k += 4) {
            float4 p[4];
            #pragma unroll
            for (int i = 0; i < 4; i++) p[i] = *(const float4*)&S.Ss[tr * 4 + i][k];
            #pragma unroll
            for (int kk = 0; kk < 4; kk++) {
                const float4 va = *(const float4*)&S.Vs[k + kk][tc * 8];
                const float4 vb = *(const float4*)&S.Vs[k + kk][tc * 8 + 4];
                #pragma unroll
                for (int i = 0; i < 4; i++) {
                    const float pv = (kk == 0) ? p[i].x : (kk == 1) ? p[i].y
                                   : (kk == 2) ? p[i].z : p[i].w;
                    acc[i][0] = fmaf(pv, va.x, acc[i][0]);
                    acc[i][1] = fmaf(pv, va.y, acc[i][1]);
                    acc[i][2] = fmaf(pv, va.z, acc[i][2]);
                    acc[i][3] = fmaf(pv, va.w, acc[i][3]);
                    acc[i][4] = fmaf(pv, vb.x, acc[i][4]);
                    acc[i][5] = fmaf(pv, vb.y, acc[i][5]);
                    acc[i][6] = fmaf(pv, vb.z, acc[i][6]);
                    acc[i][7] = fmaf(pv, vb.w, acc[i][7]);
                }
            }
        }
    }
    __syncthreads();

    // Normalize by l and head-sum merge via atomics
    #pragma unroll
    for (int i = 0; i < 4; i++) {
        const float inv = 1.f / S.l[tr * 4 + i];
        #pragma unroll
        for (int j = 0; j < 8; j++)
            atomicAdd(&g_y[(tokbase + q0 + tr * 4 + i) * DV_ + tc * 8 + j],
                      acc[i][j] * inv);
    }
}

// ---------------------------------------------------------------------------
// Launch
// ---------------------------------------------------------------------------
extern "C" void kernel_launch(void* const* d_in, const int* in_sizes, int n_in,
                              void* d_out, int out_size)
{
    const float* x     = (const float*)d_in[0];
    // d_in[1] = iter_num (unused)
    const float* Wq    = (const float*)d_in[2];
    const float* Wk    = (const float*)d_in[3];
    const float* Wv    = (const float*)d_in[4];
    const float* Wproj = (const float*)d_in[5];
    const float* lobo  = (const float*)d_in[6];
    const float* qnf   = (const float*)d_in[7];
    float* out = (float*)d_out;

    float *q_ptr, *k_ptr, *v_ptr, *y_ptr;
    cudaGetSymbolAddress((void**)&q_ptr, g_q);
    cudaGetSymbolAddress((void**)&k_ptr, g_k);
    cudaGetSymbolAddress((void**)&v_ptr, g_v);
    cudaGetSymbolAddress((void**)&y_ptr, g_y);

    cudaFuncSetAttribute(attn_kernel, cudaFuncAttributeMaxDynamicSharedMemorySize,
                         (int)sizeof(AttnSmem));

    // QKV projections (token-major outputs)
    sgemm128<<<dim3(H_ * DQK_ / 128, NT_ / 128), 256>>>(x, Wq, q_ptr, H_ * DQK_, C_);
    sgemm128<<<dim3(G_ * DQK_ / 128, NT_ / 128), 256>>>(x, Wk, k_ptr, G_ * DQK_, C_);
    sgemm128<<<dim3(G_ * DV_  / 128, NT_ / 128), 256>>>(x, Wv, v_ptr, G_ * DV_, C_);

    // RoPE + qk-norm + logit scale (in place), zero accumulator
    rope_norm_kernel<<<(NT_ * 20) / 8, 256>>>(qnf);
    zero_y_kernel<<<(NT_ * DV_ + 255) / 256, 256>>>();

    // Attention with sink + causal + GQA + head-sum
    attn_kernel<<<dim3(T_ / 64, H_, B_), 256, sizeof(AttnSmem)>>>(lobo);

    // Output projection
    sgemm128<<<dim3(C_ / 128, NT_ / 128), 256>>>(y_ptr, Wproj, out, C_, DV_);
}

// round 2
// speedup vs baseline: 1.2737x; 1.2737x over previous
#include <cuda_runtime.h>
#include <math.h>

// Problem constants
#define B_   2
#define T_   2048
#define C_   1024
#define H_   16
#define G_   4
#define DQK_ 64
#define DV_  128
#define NT_  (B_ * T_)        // 4096 tokens
#define NQKV (H_*DQK_ + G_*DQK_ + G_*DV_)   // 1792
#define KOFF (H_*DQK_)        // 1024
#define VOFF (H_*DQK_ + G_*DQK_) // 1280

// Device scratch (no cudaMalloc allowed)
__device__ float g_w[(size_t)C_ * NQKV];      // packed [Wq|Wk|Wv], [1024][1792]
__device__ float g_qkv[(size_t)NT_ * NQKV];   // fused projection output
__device__ float g_y[(size_t)NT_ * DV_];      // head-summed attention output

// ---------------------------------------------------------------------------
// Pack Wq|Wk|Wv column-wise into g_w  (float4 vectorized; boundaries 1024/1280
// are 4-aligned)
// ---------------------------------------------------------------------------
__global__ void pack_w_kernel(const float* __restrict__ Wq,
                              const float* __restrict__ Wk,
                              const float* __restrict__ Wv)
{
    const int i = blockIdx.x * blockDim.x + threadIdx.x;   // float4 index
    const int per_row = NQKV / 4;                           // 448
    if (i >= C_ * per_row) return;
    const int r = i / per_row;
    const int c4 = (i % per_row) * 4;
    float4 v;
    if (c4 < KOFF)       v = *(const float4*)(Wq + (size_t)r * (H_*DQK_) + c4);
    else if (c4 < VOFF)  v = *(const float4*)(Wk + (size_t)r * (G_*DQK_) + (c4 - KOFF));
    else                 v = *(const float4*)(Wv + (size_t)r * (G_*DV_)  + (c4 - VOFF));
    *(float4*)(g_w + (size_t)r * NQKV + c4) = v;
}

// ---------------------------------------------------------------------------
// Generic fp32 GEMM: C[M,N] = A[M,K] @ B[K,N], row-major.
// BM=BN=128, BK=8, 256 threads, 8x8 microtile.
// ---------------------------------------------------------------------------
__global__ __launch_bounds__(256) void sgemm128(
    const float* __restrict__ A, const float* __restrict__ B,
    float* __restrict__ C, int N, int K)
{
    __shared__ float As[8][132];
    __shared__ float Bs[8][132];
    const int tid  = threadIdx.x;
    const int m0   = blockIdx.y * 128;
    const int n0   = blockIdx.x * 128;
    const int arow = tid >> 1;          // 0..127
    const int acol = (tid & 1) << 2;    // 0 or 4
    const int brow = tid >> 5;          // 0..7
    const int bcol = (tid & 31) << 2;   // 0..124
    const int tm   = (tid >> 4) << 3;   // 0..120
    const int tn   = (tid & 15) << 3;   // 0..120

    float acc[8][8];
    #pragma unroll
    for (int i = 0; i < 8; i++)
        #pragma unroll
        for (int j = 0; j < 8; j++) acc[i][j] = 0.f;

    for (int k0 = 0; k0 < K; k0 += 8) {
        float4 av = *(const float4*)(A + (size_t)(m0 + arow) * K + k0 + acol);
        As[acol + 0][arow] = av.x;
        As[acol + 1][arow] = av.y;
        As[acol + 2][arow] = av.z;
        As[acol + 3][arow] = av.w;
        *(float4*)&Bs[brow][bcol] =
            *(const float4*)(B + (size_t)(k0 + brow) * N + n0 + bcol);
        __syncthreads();
        #pragma unroll
        for (int k = 0; k < 8; k++) {
            float ra[8], rb[8];
            #pragma unroll
            for (int i = 0; i < 8; i++) ra[i] = As[k][tm + i];
            #pragma unroll
            for (int j = 0; j < 8; j++) rb[j] = Bs[k][tn + j];
            #pragma unroll
            for (int i = 0; i < 8; i++)
                #pragma unroll
                for (int j = 0; j < 8; j++)
                    acc[i][j] = fmaf(ra[i], rb[j], acc[i][j]);
        }
        __syncthreads();
    }

    #pragma unroll
    for (int i = 0; i < 8; i++)
        #pragma unroll
        for (int j = 0; j < 8; j += 4) {
            float4 v = make_float4(acc[i][j], acc[i][j+1], acc[i][j+2], acc[i][j+3]);
            *(float4*)(C + (size_t)(m0 + tm + i) * N + n0 + tn + j) = v;
        }
}

// ---------------------------------------------------------------------------
// RoPE + L2-norm (+ learned logit scale for q), in-place on g_qkv.
// One warp per (token, head). Lane l owns elements l and l+32 (a RoPE pair).
// All-fp32 angle path to match the reference's own fp32 computation.
// ---------------------------------------------------------------------------
__global__ void rope_norm_kernel(const float* __restrict__ qnf)
{
    const int warp = (blockIdx.x * blockDim.x + threadIdx.x) >> 5;
    const int lane = threadIdx.x & 31;
    if (warp >= NT_ * 20) return;
    const int token = warp / 20;      // b*2048 + t
    const int slot  = warp % 20;      // 0..15 -> q head, 16..19 -> k group
    const int t     = token & (T_ - 1);

    float* base = g_qkv + (size_t)token * NQKV
                + ((slot < 16) ? slot * DQK_ : KOFF + (slot - 16) * DQK_);

    const float x0 = base[lane];
    const float x1 = base[lane + 32];

    // inv = 10000^(-lane/32), fp32 like the reference
    const float inv = __expf(-(float)lane * 0.28782313662425574f); // ln(1e4)/32
    const float ang = (float)t * inv;
    float s, c;
    sincosf(ang, &s, &c);

    const float r0 = x0 * c - x1 * s;
    const float r1 = x1 * c + x0 * s;

    float ss = r0 * r0 + r1 * r1;
    #pragma unroll
    for (int o = 16; o > 0; o >>= 1) ss += __shfl_xor_sync(0xFFFFFFFFu, ss, o);

    float scale = 1.f / (sqrtf(ss) + 1e-6f);
    if (slot < 16) scale *= qnf[0];   // net logit scale g (sqrt(d) cancels)

    base[lane]      = r0 * scale;
    base[lane + 32] = r1 * scale;
}

__global__ void zero_y_kernel()
{
    const size_t i = (size_t)blockIdx.x * blockDim.x + threadIdx.x;
    if (i < (size_t)NT_ * DV_) g_y[i] = 0.f;
}

// ---------------------------------------------------------------------------
// Flash attention with sink (flash-lobo) + causal mask + GQA + head-sum.
// Block: 256 threads, one (batch, head, 64-query tile).
// Online softmax initialized with the sink: m = lobo[h], l = 1, acc = 0.
// Head-sum merge via atomicAdd into g_y. qt reversed for wave load-balance.
// ---------------------------------------------------------------------------
struct AttnSmem {
    float Qs[64][68];
    float Ks[64][68];
    float Ss[64][68];
    float Vs[64][132];
    float m[64];
    float l[64];
    float corr[64];
    float red[4][64];
};

__global__ __launch_bounds__(256) void attn_kernel(const float* __restrict__ lobo)
{
    extern __shared__ char smem_raw[];
    AttnSmem& S = *reinterpret_cast<AttnSmem*>(smem_raw);

    const int tid = threadIdx.x;
    const int qt  = (gridDim.x - 1 - blockIdx.x);  // long blocks first
    const int h   = blockIdx.y;          // 0..15
    const int b   = blockIdx.z;          // 0..1
    const int g   = h >> 2;              // GQA group (repeat_interleave)
    const int q0  = qt * 64;
    const size_t tokbase = (size_t)b * T_;

    // Load Q tile (64x64) — 16 floats/thread
    {
        const int r  = tid >> 2;
        const int kc = (tid & 3) << 4;
        const float* src = g_qkv + (tokbase + q0 + r) * NQKV + h * DQK_ + kc;
        #pragma unroll
        for (int u = 0; u < 4; u++)
            *(float4*)&S.Qs[r][kc + u * 4] = *(const float4*)(src + u * 4);
    }
    if (tid < 64) { S.m[tid] = lobo[h]; S.l[tid] = 1.f; }

    const int tr = tid >> 4;   // 0..15
    const int tc = tid & 15;   // 0..15
    float acc[4][8];
    #pragma unroll
    for (int i = 0; i < 4; i++)
        #pragma unroll
        for (int j = 0; j < 8; j++) acc[i][j] = 0.f;

    const int nkt = qt + 1;    // causal: key tiles 0..qt
    for (int kt = 0; kt < nkt; ++kt) {
        const int k0 = kt * 64;
        __syncthreads();   // prev iter's consumers done (also covers Q/m/l init)

        // Load K tile (64x64)
        {
            const int c  = tid >> 2;
            const int kc = (tid & 3) << 4;
            const float* src = g_qkv + (tokbase + k0 + c) * NQKV + KOFF + g * DQK_ + kc;
            #pragma unroll
            for (int u = 0; u < 4; u++)
                *(float4*)&S.Ks[c][kc + u * 4] = *(const float4*)(src + u * 4);
        }
        // Load V tile (64x128)
        {
            const int c  = tid >> 2;
            const int dc = (tid & 3) << 5;
            const float* src = g_qkv + (tokbase + k0 + c) * NQKV + VOFF + g * DV_ + dc;
            #pragma unroll
            for (int u = 0; u < 8; u++)
                *(float4*)&S.Vs[c][dc + u * 4] = *(const float4*)(src + u * 4);
        }
        __syncthreads();

        // S = Q K^T (4x4 microtile per thread), mask diagonal tile
        {
            float s[4][4];
            #pragma unroll
            for (int i = 0; i < 4; i++)
                #pragma unroll
                for (int j = 0; j < 4; j++) s[i][j] = 0.f;
            #pragma unroll 4
            for (int k = 0; k < 64; k += 4) {
                float4 qv[4], kv[4];
                #pragma unroll
                for (int i = 0; i < 4; i++) qv[i] = *(const float4*)&S.Qs[tr * 4 + i][k];
                #pragma unroll
                for (int j = 0; j < 4; j++) kv[j] = *(const float4*)&S.Ks[tc * 4 + j][k];
                #pragma unroll
                for (int i = 0; i < 4; i++)
                    #pragma unroll
                    for (int j = 0; j < 4; j++)
                        s[i][j] += qv[i].x * kv[j].x + qv[i].y * kv[j].y
                                 + qv[i].z * kv[j].z + qv[i].w * kv[j].w;
            }
            const bool diag = (kt == qt);
            #pragma unroll
            for (int i = 0; i < 4; i++)
                #pragma unroll
                for (int j = 0; j < 4; j++) {
                    const int r = tr * 4 + i, c = tc * 4 + j;
                    float v = s[i][j];
                    if (diag && c > r) v = -1e30f;
                    S.Ss[r][c] = v;
                }
        }
        __syncthreads();

        // Phase A: partial row max
        {
            const int r = tid & 63, qc = tid >> 6;
            float mx = -1e30f;
            #pragma unroll
            for (int j = 0; j < 16; j++) mx = fmaxf(mx, S.Ss[r][qc * 16 + j]);
            S.red[qc][r] = mx;
        }
        __syncthreads();

        // Phase B: new max + correction factor
        if (tid < 64) {
            const float mo = S.m[tid];
            float mn = mo;
            #pragma unroll
            for (int q = 0; q < 4; q++) mn = fmaxf(mn, S.red[q][tid]);
            S.corr[tid] = __expf(mo - mn);
            S.m[tid] = mn;
        }
        __syncthreads();

        // Phase C: exponentiate in place + partial sums
        {
            const int r = tid & 63, qc = tid >> 6;
            const float mr = S.m[r];
            float sum = 0.f;
            #pragma unroll
            for (int j = 0; j < 16; j++) {
                const float p = __expf(S.Ss[r][qc * 16 + j] - mr);
                S.Ss[r][qc * 16 + j] = p;
                sum += p;
            }
            S.red[qc][r] = sum;
        }
        __syncthreads();

        // Phase D: update l (threads < 64); all threads rescale acc and do PV
        if (tid < 64) {
            float lv = S.l[tid] * S.corr[tid];
            #pragma unroll
            for (int q = 0; q < 4; q++) lv += S.red[q][tid];
            S.l[tid] = lv;
        }
        #pragma unroll
        for (int i = 0; i < 4; i++) {
            const float cf = S.corr[tr * 4 + i];
            #pragma unroll
            for (int j = 0; j < 8; j++) acc[i][j] *= cf;
        }
        #pragma unroll 4
        for (int k = 0; k < 64; k += 4) {
            float4 p[4];
            #pragma unroll
            for (int i = 0; i < 4; i++) p[i] = *(const float4*)&S.Ss[tr * 4 + i][k];
            #pragma unroll
            for (int kk = 0; kk < 4; kk++) {
                const float4 va = *(const float4*)&S.Vs[k + kk][tc * 8];
                const float4 vb = *(const float4*)&S.Vs[k + kk][tc * 8 + 4];
                #pragma unroll
                for (int i = 0; i < 4; i++) {
                    const float pv = (kk == 0) ? p[i].x : (kk == 1) ? p[i].y
                                   : (kk == 2) ? p[i].z : p[i].w;
                    acc[i][0] = fmaf(pv, va.x, acc[i][0]);
                    acc[i][1] = fmaf(pv, va.y, acc[i][1]);
                    acc[i][2] = fmaf(pv, va.z, acc[i][2]);
                    acc[i][3] = fmaf(pv, va.w, acc[i][3]);
                    acc[i][4] = fmaf(pv, vb.x, acc[i][4]);
                    acc[i][5] = fmaf(pv, vb.y, acc[i][5]);
                    acc[i][6] = fmaf(pv, vb.z, acc[i][6]);
                    acc[i][7] = fmaf(pv, vb.w, acc[i][7]);
                }
            }
        }
    }
    __syncthreads();

    // Normalize by l and head-sum merge via atomics
    #pragma unroll
    for (int i = 0; i < 4; i++) {
        const float inv = 1.f / S.l[tr * 4 + i];
        #pragma unroll
        for (int j = 0; j < 8; j++)
            atomicAdd(&g_y[(tokbase + q0 + tr * 4 + i) * DV_ + tc * 8 + j],
                      acc[i][j] * inv);
    }
}

// ---------------------------------------------------------------------------
// Launch
// ---------------------------------------------------------------------------
extern "C" void kernel_launch(void* const* d_in, const int* in_sizes, int n_in,
                              void* d_out, int out_size)
{
    const float* x     = (const float*)d_in[0];
    // d_in[1] = iter_num (unused)
    const float* Wq    = (const float*)d_in[2];
    const float* Wk    = (const float*)d_in[3];
    const float* Wv    = (const float*)d_in[4];
    const float* Wproj = (const float*)d_in[5];
    const float* lobo  = (const float*)d_in[6];
    const float* qnf   = (const float*)d_in[7];
    float* out = (float*)d_out;

    float *qkv_ptr, *y_ptr;
    cudaGetSymbolAddress((void**)&qkv_ptr, g_qkv);
    cudaGetSymbolAddress((void**)&y_ptr, g_y);

    cudaFuncSetAttribute(attn_kernel, cudaFuncAttributeMaxDynamicSharedMemorySize,
                         (int)sizeof(AttnSmem));

    // Pack weights, fused QKV projection (one full-chip GEMM)
    pack_w_kernel<<<(C_ * (NQKV/4) + 255) / 256, 256>>>(Wq, Wk, Wv);
    float* w_ptr;
    cudaGetSymbolAddress((void**)&w_ptr, g_w);
    sgemm128<<<dim3(NQKV / 128, NT_ / 128), 256>>>(x, w_ptr, qkv_ptr, NQKV, C_);

    // RoPE + qk-norm + logit scale (in place), zero accumulator
    rope_norm_kernel<<<(NT_ * 20) / 8, 256>>>(qnf);
    zero_y_kernel<<<(NT_ * DV_ + 255) / 256, 256>>>();

    // Attention with sink + causal + GQA + head-sum
    attn_kernel<<<dim3(T_ / 64, H_, B_), 256, sizeof(AttnSmem)>>>(lobo);

    // Output projection
    sgemm128<<<dim3(C_ / 128, NT_ / 128), 256>>>(y_ptr, Wproj, out, C_, DV_);
}

// round 4
// speedup vs baseline: 4.6309x; 3.6357x over previous
#include <cuda_runtime.h>
#include <cuda_bf16.h>
#include <cuda_fp16.h>
#include <math.h>
#include <stdint.h>

// Problem constants
#define B_   2
#define T_   2048
#define C_   1024
#define H_   16
#define G_   4
#define DQK_ 64
#define DV_  128
#define NT_  (B_ * T_)        // 4096 tokens
#define NQKV (H_*DQK_ + G_*DQK_ + G_*DV_)   // 1792
#define KOFF (H_*DQK_)        // 1024
#define VOFF (H_*DQK_ + G_*DQK_) // 1280

// ---------------------------------------------------------------------------
// Device scratch (no cudaMalloc allowed)
// ---------------------------------------------------------------------------
__device__ __nv_bfloat16 g_xh[(size_t)NT_ * C_];     // x split-bf16 hi
__device__ __nv_bfloat16 g_xl[(size_t)NT_ * C_];     // x split-bf16 lo
__device__ __nv_bfloat16 g_wth[(size_t)NQKV * C_];   // packed W^T [1792][1024] hi
__device__ __nv_bfloat16 g_wtl[(size_t)NQKV * C_];   // lo
__device__ __nv_bfloat16 g_yh[(size_t)NT_ * DV_];    // attn out split hi
__device__ __nv_bfloat16 g_yl[(size_t)NT_ * DV_];    // lo
__device__ __nv_bfloat16 g_pth[(size_t)C_ * DV_];    // Wproj^T [1024][128] hi
__device__ __nv_bfloat16 g_ptl[(size_t)C_ * DV_];    // lo
__device__ float  g_qkv[(size_t)NT_ * NQKV];         // fused projection (fp32)
__device__ __half g_qkvh[(size_t)NT_ * NQKV];        // fp16 q(roped)/k(roped)/v
__device__ float  g_y[(size_t)NT_ * DV_];            // head-summed attn output

// ---------------------------------------------------------------------------
// mma.sync helpers (sm_80+ PTX; valid on compute_103)
// ---------------------------------------------------------------------------
__device__ __forceinline__ void mma_f16(float& d0, float& d1, float& d2, float& d3,
    uint32_t a0, uint32_t a1, uint32_t a2, uint32_t a3, uint32_t b0, uint32_t b1)
{
    asm volatile(
        "mma.sync.aligned.m16n8k16.row.col.f32.f16.f16.f32 "
        "{%0,%1,%2,%3},{%4,%5,%6,%7},{%8,%9},{%0,%1,%2,%3};"
        : "+f"(d0), "+f"(d1), "+f"(d2), "+f"(d3)
        : "r"(a0), "r"(a1), "r"(a2), "r"(a3), "r"(b0), "r"(b1));
}

__device__ __forceinline__ void mma_bf16(float& d0, float& d1, float& d2, float& d3,
    uint32_t a0, uint32_t a1, uint32_t a2, uint32_t a3, uint32_t b0, uint32_t b1)
{
    asm volatile(
        "mma.sync.aligned.m16n8k16.row.col.f32.bf16.bf16.f32 "
        "{%0,%1,%2,%3},{%4,%5,%6,%7},{%8,%9},{%0,%1,%2,%3};"
        : "+f"(d0), "+f"(d1), "+f"(d2), "+f"(d3)
        : "r"(a0), "r"(a1), "r"(a2), "r"(a3), "r"(b0), "r"(b1));
}

// ---------------------------------------------------------------------------
// Split-bf16 GEMM via mma.sync: C[M,N] = (Ah+Al)[M,K] @ (Bh+Bl)[N,K]^T
// CTA 128x128, KTILE=32 stage, 256 threads / 8 warps, warp tile 32x64.
// D = Ah*Bh + Ah*Bl + Al*Bh (ll dropped, ~1e-5 rel).
// ---------------------------------------------------------------------------
__global__ __launch_bounds__(256) void mm_gemm(
    const __nv_bfloat16* __restrict__ Ah, const __nv_bfloat16* __restrict__ Al,
    const __nv_bfloat16* __restrict__ Bh, const __nv_bfloat16* __restrict__ Bl,
    float* __restrict__ Cout, int K, int ldc)
{
    __shared__ __nv_bfloat16 sm[4][128][40];   // Ah, Al, Bh, Bl tiles (pad 40)

    const int tid  = threadIdx.x;
    const int wid  = tid >> 5;
    const int lane = tid & 31;
    const int g8   = lane >> 2;     // 0..7
    const int t4   = lane & 3;      // 0..3
    const int m0   = blockIdx.y * 128;
    const int n0   = blockIdx.x * 128;
    const int ms   = wid & 3;       // m strip (32 rows)
    const int ws   = wid >> 2;      // n strip (64 cols)

    const __nv_bfloat16* srcs[4] = {
        Ah + (size_t)m0 * K, Al + (size_t)m0 * K,
        Bh + (size_t)n0 * K, Bl + (size_t)n0 * K };

    float acc[2][8][4];
    #pragma unroll
    for (int mf = 0; mf < 2; mf++)
        #pragma unroll
        for (int nf = 0; nf < 8; nf++)
            #pragma unroll
            for (int i = 0; i < 4; i++) acc[mf][nf][i] = 0.f;

    const int nst = K >> 5;
    for (int s = 0; s < nst; ++s) {
        const int k0 = s << 5;
        __syncthreads();
        #pragma unroll
        for (int t = 0; t < 8; ++t) {
            const int tl  = t >> 1;
            const int idx = ((t & 1) << 8) + tid;   // 0..511
            const int row = idx >> 2;
            const int ch  = idx & 3;
            uint4 v = *(const uint4*)(srcs[tl] + (size_t)row * K + k0 + ch * 8);
            *(uint4*)&sm[tl][row][ch * 8] = v;
        }
        __syncthreads();

        #pragma unroll
        for (int ks = 0; ks < 2; ++ks) {
            const int cb = ks * 16 + 2 * t4;
            uint32_t ah[2][4], al[2][4];
            #pragma unroll
            for (int mf = 0; mf < 2; ++mf) {
                const int r0 = ms * 32 + mf * 16 + g8;
                ah[mf][0] = *(const uint32_t*)&sm[0][r0    ][cb    ];
                ah[mf][1] = *(const uint32_t*)&sm[0][r0 + 8][cb    ];
                ah[mf][2] = *(const uint32_t*)&sm[0][r0    ][cb + 8];
                ah[mf][3] = *(const uint32_t*)&sm[0][r0 + 8][cb + 8];
                al[mf][0] = *(const uint32_t*)&sm[1][r0    ][cb    ];
                al[mf][1] = *(const uint32_t*)&sm[1][r0 + 8][cb    ];
                al[mf][2] = *(const uint32_t*)&sm[1][r0    ][cb + 8];
                al[mf][3] = *(const uint32_t*)&sm[1][r0 + 8][cb + 8];
            }
            #pragma unroll
            for (int nf = 0; nf < 8; ++nf) {
                const int n = ws * 64 + nf * 8 + g8;
                const uint32_t bh0 = *(const uint32_t*)&sm[2][n][cb];
                const uint32_t bh1 = *(const uint32_t*)&sm[2][n][cb + 8];
                const uint32_t bl0 = *(const uint32_t*)&sm[3][n][cb];
                const uint32_t bl1 = *(const uint32_t*)&sm[3][n][cb + 8];
                #pragma unroll
                for (int mf = 0; mf < 2; ++mf) {
                    float* d = acc[mf][nf];
                    mma_bf16(d[0], d[1], d[2], d[3],
                             ah[mf][0], ah[mf][1], ah[mf][2], ah[mf][3], bh0, bh1);
                    mma_bf16(d[0], d[1], d[2], d[3],
                             ah[mf][0], ah[mf][1], ah[mf][2], ah[mf][3], bl0, bl1);
                    mma_bf16(d[0], d[1], d[2], d[3],
                             al[mf][0], al[mf][1], al[mf][2], al[mf][3], bh0, bh1);
                }
            }
        }
    }

    // Epilogue
    #pragma unroll
    for (int mf = 0; mf < 2; ++mf) {
        const int r = m0 + ms * 32 + mf * 16 + g8;
        #pragma unroll
        for (int nf = 0; nf < 8; ++nf) {
            const int c = n0 + ws * 64 + nf * 8 + 2 * t4;
            *(float2*)(Cout + (size_t)r * ldc + c) =
                make_float2(acc[mf][nf][0], acc[mf][nf][1]);
            *(float2*)(Cout + (size_t)(r + 8) * ldc + c) =
                make_float2(acc[mf][nf][2], acc[mf][nf][3]);
        }
    }
}

// ---------------------------------------------------------------------------
// Conversion / packing kernels
// ---------------------------------------------------------------------------
__global__ void cvt_split(const float* __restrict__ in,
                          __nv_bfloat16* __restrict__ hi,
                          __nv_bfloat16* __restrict__ lo, int n)
{
    const int i = blockIdx.x * blockDim.x + threadIdx.x;
    if (i >= n) return;
    const float x = in[i];
    const __nv_bfloat16 h = __float2bfloat16(x);
    hi[i] = h;
    lo[i] = __float2bfloat16(x - __bfloat162float(h));
}

__global__ void pack_wt(const float* __restrict__ Wq, const float* __restrict__ Wk,
                        const float* __restrict__ Wv)
{
    const int i = blockIdx.x * blockDim.x + threadIdx.x;
    if (i >= NQKV * C_) return;
    const int nn = i / C_;
    const int k  = i % C_;
    float v;
    if (nn < KOFF)      v = Wq[(size_t)k * (H_*DQK_) + nn];
    else if (nn < VOFF) v = Wk[(size_t)k * (G_*DQK_) + (nn - KOFF)];
    else                v = Wv[(size_t)k * (G_*DV_)  + (nn - VOFF)];
    const __nv_bfloat16 h = __float2bfloat16(v);
    g_wth[i] = h;
    g_wtl[i] = __float2bfloat16(v - __bfloat162float(h));
}

__global__ void pack_pt(const float* __restrict__ Wp)
{
    const int i = blockIdx.x * blockDim.x + threadIdx.x;
    if (i >= C_ * DV_) return;
    const int nn = i / DV_;
    const int k  = i % DV_;
    const float v = Wp[(size_t)k * C_ + nn];
    const __nv_bfloat16 h = __float2bfloat16(v);
    g_pth[i] = h;
    g_ptl[i] = __float2bfloat16(v - __bfloat162float(h));
}

// V region: fp32 -> fp16 copy into g_qkvh
__global__ void cvt_vh()
{
    const int i = blockIdx.x * blockDim.x + threadIdx.x;
    if (i >= NT_ * (G_ * DV_)) return;
    const int token = i >> 9;          // / 512
    const int idx   = i & 511;
    const size_t off = (size_t)token * NQKV + VOFF + idx;
    g_qkvh[off] = __float2half(g_qkv[off]);
}

// ---------------------------------------------------------------------------
// RoPE + L2-norm (+ learned logit scale for q); reads fp32 g_qkv, writes fp16
// g_qkvh. One warp per (token, head-slot). fp32 angle path like the reference.
// ---------------------------------------------------------------------------
__global__ void rope_norm_kernel(const float* __restrict__ qnf)
{
    const int warp = (blockIdx.x * blockDim.x + threadIdx.x) >> 5;
    const int lane = threadIdx.x & 31;
    if (warp >= NT_ * 20) return;
    const int token = warp / 20;
    const int slot  = warp % 20;
    const int t     = token & (T_ - 1);

    const size_t off = (size_t)token * NQKV
                     + ((slot < 16) ? slot * DQK_ : KOFF + (slot - 16) * DQK_);
    const float* src = g_qkv + off;
    __half* dst = g_qkvh + off;

    const float x0 = src[lane];
    const float x1 = src[lane + 32];

    const float inv = __expf(-(float)lane * 0.28782313662425574f); // ln(1e4)/32
    const float ang = (float)t * inv;
    float s, c;
    sincosf(ang, &s, &c);

    const float r0 = x0 * c - x1 * s;
    const float r1 = x1 * c + x0 * s;

    float ss = r0 * r0 + r1 * r1;
    #pragma unroll
    for (int o = 16; o > 0; o >>= 1) ss += __shfl_xor_sync(0xFFFFFFFFu, ss, o);

    float scale = 1.f / (sqrtf(ss) + 1e-6f);
    if (slot < 16) scale *= qnf[0];

    dst[lane]      = __float2half(r0 * scale);
    dst[lane + 32] = __float2half(r1 * scale);
}

__global__ void zero_y_kernel()
{
    const size_t i = (size_t)blockIdx.x * blockDim.x + threadIdx.x;
    if (i < (size_t)NT_ * DV_) g_y[i] = 0.f;
}

// ---------------------------------------------------------------------------
// Flash attention: fp16 mma.sync for QK^T and PV; fp32 online softmax in smem;
// sink (flash-lobo) + causal + GQA + head-sum via atomics.
// Block 256 threads / 8 warps; per CTA: one (b, h, 64-query tile).
// QK^T: warp tile 16x32 of S.  PV: warp tile 16x64 of O.
// ---------------------------------------------------------------------------
struct AttnSmem {
    __half Qs[64][72];    // 144B rows (9*16) -> conflict-free frag loads
    __half Ks[64][72];
    __half Ps[64][72];
    __half Vt[128][72];   // V transposed: [dim][key]
    float  Ss[64][68];
    float  m[64];
    float  l[64];
    float  corr[64];
    float  red[4][64];
};

__global__ __launch_bounds__(256) void attn_kernel(const float* __restrict__ lobo)
{
    extern __shared__ char smem_raw[];
    AttnSmem& S = *reinterpret_cast<AttnSmem*>(smem_raw);

    const int tid  = threadIdx.x;
    const int wid  = tid >> 5;
    const int lane = tid & 31;
    const int g8   = lane >> 2;
    const int t4   = lane & 3;
    const int ms   = wid & 3;      // S/O row strip: rows 16*ms
    const int ws   = wid >> 2;     // col strip: S cols 32*ws, O cols 64*ws

    const int qt = (gridDim.x - 1 - blockIdx.x);  // long blocks first
    const int h  = blockIdx.y;
    const int b  = blockIdx.z;
    const int gq = h >> 2;
    const int q0 = qt * 64;
    const size_t tokbase = (size_t)b * T_;

    // Load Q tile (64x64 halves)
    #pragma unroll
    for (int i = 0; i < 8; ++i) {
        const int cid = tid + i * 256;
        const int row = cid >> 5;
        const int dp  = cid & 31;
        const uint32_t v = *(const uint32_t*)
            (g_qkvh + (tokbase + q0 + row) * NQKV + h * DQK_ + 2 * dp);
        *(uint32_t*)&S.Qs[row][2 * dp] = v;
    }
    if (tid < 64) { S.m[tid] = lobo[h]; S.l[tid] = 1.f; }

    float oacc[8][4];
    #pragma unroll
    for (int nf = 0; nf < 8; nf++)
        #pragma unroll
        for (int i = 0; i < 4; i++) oacc[nf][i] = 0.f;

    const int nkt = qt + 1;
    for (int kt = 0; kt < nkt; ++kt) {
        const int k0 = kt * 64;
        __syncthreads();   // prev iter consumers done (covers Q/m/l init too)

        // K tile (64x64)
        #pragma unroll
        for (int i = 0; i < 8; ++i) {
            const int cid = tid + i * 256;
            const int row = cid >> 5;
            const int dp  = cid & 31;
            const uint32_t v = *(const uint32_t*)
                (g_qkvh + (tokbase + k0 + row) * NQKV + KOFF + gq * DQK_ + 2 * dp);
            *(uint32_t*)&S.Ks[row][2 * dp] = v;
        }
        // V tile transposed: Vt[dim][key]
        #pragma unroll
        for (int i = 0; i < 16; ++i) {
            const int cid = tid + i * 256;
            const int dp  = cid & 63;          // dim pair 0..63 (128 dims)
            const int key = cid >> 6;          // 0..63
            const uint32_t v = *(const uint32_t*)
                (g_qkvh + (tokbase + k0 + key) * NQKV + VOFF + gq * DV_ + 2 * dp);
            const __half2 h2 = *(const __half2*)&v;
            S.Vt[2 * dp    ][key] = __low2half(h2);
            S.Vt[2 * dp + 1][key] = __high2half(h2);
        }
        __syncthreads();

        // S = Q K^T via fp16 mma (warp: 16x32)
        {
            float sacc[4][4];
            #pragma unroll
            for (int nf = 0; nf < 4; nf++)
                #pragma unroll
                for (int i = 0; i < 4; i++) sacc[nf][i] = 0.f;

            #pragma unroll
            for (int ks = 0; ks < 4; ++ks) {
                const int cb = ks * 16 + 2 * t4;
                const int r0 = ms * 16 + g8;
                const uint32_t a0 = *(const uint32_t*)&S.Qs[r0    ][cb    ];
                const uint32_t a1 = *(const uint32_t*)&S.Qs[r0 + 8][cb    ];
                const uint32_t a2 = *(const uint32_t*)&S.Qs[r0    ][cb + 8];
                const uint32_t a3 = *(const uint32_t*)&S.Qs[r0 + 8][cb + 8];
                #pragma unroll
                for (int nf = 0; nf < 4; ++nf) {
                    const int n = ws * 32 + nf * 8 + g8;
                    const uint32_t b0 = *(const uint32_t*)&S.Ks[n][cb];
                    const uint32_t b1 = *(const uint32_t*)&S.Ks[n][cb + 8];
                    mma_f16(sacc[nf][0], sacc[nf][1], sacc[nf][2], sacc[nf][3],
                            a0, a1, a2, a3, b0, b1);
                }
            }
            // Write S with causal mask on the diagonal tile
            const bool diag = (kt == qt);
            const int r0 = ms * 16 + g8;
            #pragma unroll
            for (int nf = 0; nf < 4; ++nf) {
                const int c = ws * 32 + nf * 8 + 2 * t4;
                float v0 = sacc[nf][0], v1 = sacc[nf][1];
                float v2 = sacc[nf][2], v3 = sacc[nf][3];
                if (diag) {
                    if (c     > r0)     v0 = -1e30f;
                    if (c + 1 > r0)     v1 = -1e30f;
                    if (c     > r0 + 8) v2 = -1e30f;
                    if (c + 1 > r0 + 8) v3 = -1e30f;
                }
                S.Ss[r0    ][c]     = v0;
                S.Ss[r0    ][c + 1] = v1;
                S.Ss[r0 + 8][c]     = v2;
                S.Ss[r0 + 8][c + 1] = v3;
            }
        }
        __syncthreads();

        // Phase A: partial row max
        {
            const int r = tid & 63, qc = tid >> 6;
            float mx = -1e30f;
            #pragma unroll
            for (int j = 0; j < 16; j++) mx = fmaxf(mx, S.Ss[r][qc * 16 + j]);
            S.red[qc][r] = mx;
        }
        __syncthreads();

        // Phase B: new max + correction factor
        if (tid < 64) {
            const float mo = S.m[tid];
            float mn = mo;
            #pragma unroll
            for (int q = 0; q < 4; q++) mn = fmaxf(mn, S.red[q][tid]);
            S.corr[tid] = __expf(mo - mn);
            S.m[tid] = mn;
        }
        __syncthreads();

        // Phase C: exponentiate -> Ps (half), partial sums
        {
            const int r = tid & 63, qc = tid >> 6;
            const float mr = S.m[r];
            float sum = 0.f;
            #pragma unroll
            for (int j = 0; j < 16; j += 2) {
                const int c = qc * 16 + j;
                const float p0 = __expf(S.Ss[r][c] - mr);
                const float p1 = __expf(S.Ss[r][c + 1] - mr);
                sum += p0 + p1;
                *(__half2*)&S.Ps[r][c] = __floats2half2_rn(p0, p1);
            }
            S.red[qc][r] = sum;
        }
        __syncthreads();

        // Phase D: update l; rescale oacc; PV mma
        if (tid < 64) {
            float lv = S.l[tid] * S.corr[tid];
            #pragma unroll
            for (int q = 0; q < 4; q++) lv += S.red[q][tid];
            S.l[tid] = lv;
        }
        {
            const int r0 = ms * 16 + g8;
            const float c0 = S.corr[r0];
            const float c1 = S.corr[r0 + 8];
            #pragma unroll
            for (int nf = 0; nf < 8; ++nf) {
                oacc[nf][0] *= c0; oacc[nf][1] *= c0;
                oacc[nf][2] *= c1; oacc[nf][3] *= c1;
            }
            #pragma unroll
            for (int ks = 0; ks < 4; ++ks) {
                const int cb = ks * 16 + 2 * t4;
                const uint32_t a0 = *(const uint32_t*)&S.Ps[r0    ][cb    ];
                const uint32_t a1 = *(const uint32_t*)&S.Ps[r0 + 8][cb    ];
                const uint32_t a2 = *(const uint32_t*)&S.Ps[r0    ][cb + 8];
                const uint32_t a3 = *(const uint32_t*)&S.Ps[r0 + 8][cb + 8];
                #pragma unroll
                for (int nf = 0; nf < 8; ++nf) {
                    const int n = ws * 64 + nf * 8 + g8;   // output dim
                    const uint32_t b0 = *(const uint32_t*)&S.Vt[n][cb];
                    const uint32_t b1 = *(const uint32_t*)&S.Vt[n][cb + 8];
                    mma_f16(oacc[nf][0], oacc[nf][1], oacc[nf][2], oacc[nf][3],
                            a0, a1, a2, a3, b0, b1);
                }
            }
        }
    }
    __syncthreads();

    // Normalize by l, head-sum merge via atomics
    {
        const int r0 = ms * 16 + g8;
        const float inv0 = 1.f / S.l[r0];
        const float inv1 = 1.f / S.l[r0 + 8];
        float* dst0 = g_y + (tokbase + q0 + r0) * DV_;
        float* dst1 = g_y + (tokbase + q0 + r0 + 8) * DV_;
        #pragma unroll
        for (int nf = 0; nf < 8; ++nf) {
            const int c = ws * 64 + nf * 8 + 2 * t4;
            atomicAdd(dst0 + c,     oacc[nf][0] * inv0);
            atomicAdd(dst0 + c + 1, oacc[nf][1] * inv0);
            atomicAdd(dst1 + c,     oacc[nf][2] * inv1);
            atomicAdd(dst1 + c + 1, oacc[nf][3] * inv1);
        }
    }
}

// ---------------------------------------------------------------------------
// Launch
// ---------------------------------------------------------------------------
extern "C" void kernel_launch(void* const* d_in, const int* in_sizes, int n_in,
                              void* d_out, int out_size)
{
    const float* x     = (const float*)d_in[0];
    // d_in[1] = iter_num (unused)
    const float* Wq    = (const float*)d_in[2];
    const float* Wk    = (const float*)d_in[3];
    const float* Wv    = (const float*)d_in[4];
    const float* Wproj = (const float*)d_in[5];
    const float* lobo  = (const float*)d_in[6];
    const float* qnf   = (const float*)d_in[7];
    float* out = (float*)d_out;

    __nv_bfloat16 *xh, *xl, *wth, *wtl, *yh, *yl, *pth, *ptl;
    float *qkv_ptr, *y_ptr;
    cudaGetSymbolAddress((void**)&xh, g_xh);
    cudaGetSymbolAddress((void**)&xl, g_xl);
    cudaGetSymbolAddress((void**)&wth, g_wth);
    cudaGetSymbolAddress((void**)&wtl, g_wtl);
    cudaGetSymbolAddress((void**)&yh, g_yh);
    cudaGetSymbolAddress((void**)&yl, g_yl);
    cudaGetSymbolAddress((void**)&pth, g_pth);
    cudaGetSymbolAddress((void**)&ptl, g_ptl);
    cudaGetSymbolAddress((void**)&qkv_ptr, g_qkv);
    cudaGetSymbolAddress((void**)&y_ptr, g_y);

    cudaFuncSetAttribute(attn_kernel, cudaFuncAttributeMaxDynamicSharedMemorySize,
                         (int)sizeof(AttnSmem));

    // Pack/convert inputs to split-bf16
    pack_wt<<<(NQKV * C_ + 255) / 256, 256>>>(Wq, Wk, Wv);
    pack_pt<<<(C_ * DV_ + 255) / 256, 256>>>(Wproj);
    cvt_split<<<(NT_ * C_ + 255) / 256, 256>>>(x, xh, xl, NT_ * C_);

    // Fused QKV projection: [4096,1024] x [1792,1024]^T -> g_qkv (fp32)
    mm_gemm<<<dim3(NQKV / 128, NT_ / 128), 256>>>(xh, xl, wth, wtl,
                                                  qkv_ptr, C_, NQKV);

    // RoPE + qk-norm + logit scale -> fp16 q/k; V -> fp16; zero accumulator
    rope_norm_kernel<<<(NT_ * 20) / 8, 256>>>(qnf);
    cvt_vh<<<(NT_ * (G_ * DV_) + 255) / 256, 256>>>();
    zero_y_kernel<<<(NT_ * DV_ + 255) / 256, 256>>>();

    // Attention (fp16 tensor cores) with sink + causal + GQA + head-sum
    attn_kernel<<<dim3(T_ / 64, H_, B_), 256, sizeof(AttnSmem)>>>(lobo);

    // Output projection: [4096,128] x [1024,128]^T -> out
    cvt_split<<<(NT_ * DV_ + 255) / 256, 256>>>(y_ptr, yh, yl, NT_ * DV_);
    mm_gemm<<<dim3(C_ / 128, NT_ / 128), 256>>>(yh, yl, pth, ptl,
                                                out, DV_, C_);
}

// round 5
// speedup vs baseline: 6.0367x; 1.3036x over previous
#include <cuda_runtime.h>
#include <cuda_bf16.h>
#include <cuda_fp16.h>
#include <math.h>
#include <stdint.h>

// Problem constants
#define B_   2
#define T_   2048
#define C_   1024
#define H_   16
#define G_   4
#define DQK_ 64
#define DV_  128
#define NT_  (B_ * T_)        // 4096 tokens
#define NQKV (H_*DQK_ + G_*DQK_ + G_*DV_)   // 1792
#define KOFF (H_*DQK_)        // 1024
#define VOFF (H_*DQK_ + G_*DQK_) // 1280

// ---------------------------------------------------------------------------
// Device scratch (no cudaMalloc allowed)
// ---------------------------------------------------------------------------
__device__ __nv_bfloat16 g_xh[(size_t)NT_ * C_];     // x split-bf16 hi
__device__ __nv_bfloat16 g_xl[(size_t)NT_ * C_];     // x split-bf16 lo
__device__ __nv_bfloat16 g_wth[(size_t)NQKV * C_];   // packed W^T [1792][1024] hi
__device__ __nv_bfloat16 g_wtl[(size_t)NQKV * C_];   // lo
__device__ __nv_bfloat16 g_yh[(size_t)NT_ * DV_];    // head-summed attn out hi
__device__ __nv_bfloat16 g_yl[(size_t)NT_ * DV_];    // lo
__device__ __nv_bfloat16 g_pth[(size_t)C_ * DV_];    // Wproj^T [1024][128] hi
__device__ __nv_bfloat16 g_ptl[(size_t)C_ * DV_];    // lo
__device__ float  g_qkv[(size_t)NT_ * NQKV];         // fused projection (fp32)
__device__ __half g_qkvh[(size_t)NT_ * NQKV];        // fp16 q(roped)/k(roped)/v
__device__ float  g_yp[(size_t)H_ * NT_ * DV_];      // per-head attn output

// ---------------------------------------------------------------------------
// mma.sync helpers (sm_80+ PTX; valid on compute_103)
// ---------------------------------------------------------------------------
__device__ __forceinline__ void mma_f16(float& d0, float& d1, float& d2, float& d3,
    uint32_t a0, uint32_t a1, uint32_t a2, uint32_t a3, uint32_t b0, uint32_t b1)
{
    asm volatile(
        "mma.sync.aligned.m16n8k16.row.col.f32.f16.f16.f32 "
        "{%0,%1,%2,%3},{%4,%5,%6,%7},{%8,%9},{%0,%1,%2,%3};"
        : "+f"(d0), "+f"(d1), "+f"(d2), "+f"(d3)
        : "r"(a0), "r"(a1), "r"(a2), "r"(a3), "r"(b0), "r"(b1));
}

__device__ __forceinline__ void mma_bf16(float& d0, float& d1, float& d2, float& d3,
    uint32_t a0, uint32_t a1, uint32_t a2, uint32_t a3, uint32_t b0, uint32_t b1)
{
    asm volatile(
        "mma.sync.aligned.m16n8k16.row.col.f32.bf16.bf16.f32 "
        "{%0,%1,%2,%3},{%4,%5,%6,%7},{%8,%9},{%0,%1,%2,%3};"
        : "+f"(d0), "+f"(d1), "+f"(d2), "+f"(d3)
        : "r"(a0), "r"(a1), "r"(a2), "r"(a3), "r"(b0), "r"(b1));
}

__device__ __forceinline__ uint32_t smem_u32(const void* p) {
    uint32_t a;
    asm("{ .reg .u64 t; cvta.to.shared.u64 t, %1; cvt.u32.u64 %0, t; }"
        : "=r"(a) : "l"(p));
    return a;
}

#define CP_ASYNC16(dst, src) \
    asm volatile("cp.async.cg.shared.global [%0], [%1], 16;" \
                 :: "r"(dst), "l"(src) : "memory")
#define CP_COMMIT() asm volatile("cp.async.commit_group;" ::: "memory")
#define CP_WAIT(n)  asm volatile("cp.async.wait_group %0;" :: "n"(n) : "memory")

// ---------------------------------------------------------------------------
// Split-bf16 GEMM: C[M,N] = (Ah+Al)[M,K] @ (Bh+Bl)[N,K]^T
// CTA 128x128, KTILE=32, 256 threads / 8 warps (32x64 warp tile),
// 2-stage cp.async double buffering. D = hh + hl + lh (ll dropped).
// ---------------------------------------------------------------------------
#define MM_SMEM_BYTES (2 * 4 * 128 * 40 * 2)   // 81920

__global__ __launch_bounds__(256) void mm_gemm(
    const __nv_bfloat16* __restrict__ Ah, const __nv_bfloat16* __restrict__ Al,
    const __nv_bfloat16* __restrict__ Bh, const __nv_bfloat16* __restrict__ Bl,
    float* __restrict__ Cout, int K, int ldc)
{
    extern __shared__ __nv_bfloat16 smd[];   // [stage][tile][128][40]

    const int tid  = threadIdx.x;
    const int wid  = tid >> 5;
    const int lane = tid & 31;
    const int g8   = lane >> 2;
    const int t4   = lane & 3;
    const int m0   = blockIdx.y * 128;
    const int n0   = blockIdx.x * 128;
    const int ms   = wid & 3;
    const int ws   = wid >> 2;

    const __nv_bfloat16* srcs[4] = {
        Ah + (size_t)m0 * K, Al + (size_t)m0 * K,
        Bh + (size_t)n0 * K, Bl + (size_t)n0 * K };

    // per-thread fixed addressing for fills
    const int f_row = tid >> 2;        // 0..63 within half-tile pair
    const int f_ch  = tid & 3;         // 16B chunk

    auto issue_stage = [&](int s, int st) {
        const int k0 = s << 5;
        #pragma unroll
        for (int t = 0; t < 8; ++t) {
            const int tl  = t >> 1;
            const int row = ((t & 1) << 6) + f_row;
            const __nv_bfloat16* src = srcs[tl] + (size_t)row * K + k0 + f_ch * 8;
            const uint32_t dst = smem_u32(
                smd + ((size_t)((st * 4 + tl) * 128 + row)) * 40 + f_ch * 8);
            CP_ASYNC16(dst, src);
        }
        CP_COMMIT();
    };

    float acc[2][8][4];
    #pragma unroll
    for (int mf = 0; mf < 2; mf++)
        #pragma unroll
        for (int nf = 0; nf < 8; nf++)
            #pragma unroll
            for (int i = 0; i < 4; i++) acc[mf][nf][i] = 0.f;

    const int nst = K >> 5;
    issue_stage(0, 0);

    for (int s = 0; s < nst; ++s) {
        const int st = s & 1;
        if (s + 1 < nst) { issue_stage(s + 1, (s + 1) & 1); CP_WAIT(1); }
        else             { CP_WAIT(0); }
        __syncthreads();

        const __nv_bfloat16* smb = smd + (size_t)st * 4 * 128 * 40;
        #define SM(tl, r, c) (smb + ((size_t)((tl) * 128 + (r))) * 40 + (c))

        #pragma unroll
        for (int ks = 0; ks < 2; ++ks) {
            const int cb = ks * 16 + 2 * t4;
            uint32_t ah[2][4], al[2][4];
            #pragma unroll
            for (int mf = 0; mf < 2; ++mf) {
                const int r0 = ms * 32 + mf * 16 + g8;
                ah[mf][0] = *(const uint32_t*)SM(0, r0,     cb);
                ah[mf][1] = *(const uint32_t*)SM(0, r0 + 8, cb);
                ah[mf][2] = *(const uint32_t*)SM(0, r0,     cb + 8);
                ah[mf][3] = *(const uint32_t*)SM(0, r0 + 8, cb + 8);
                al[mf][0] = *(const uint32_t*)SM(1, r0,     cb);
                al[mf][1] = *(const uint32_t*)SM(1, r0 + 8, cb);
                al[mf][2] = *(const uint32_t*)SM(1, r0,     cb + 8);
                al[mf][3] = *(const uint32_t*)SM(1, r0 + 8, cb + 8);
            }
            #pragma unroll
            for (int nf = 0; nf < 8; ++nf) {
                const int n = ws * 64 + nf * 8 + g8;
                const uint32_t bh0 = *(const uint32_t*)SM(2, n, cb);
                const uint32_t bh1 = *(const uint32_t*)SM(2, n, cb + 8);
                const uint32_t bl0 = *(const uint32_t*)SM(3, n, cb);
                const uint32_t bl1 = *(const uint32_t*)SM(3, n, cb + 8);
                #pragma unroll
                for (int mf = 0; mf < 2; ++mf) {
                    float* d = acc[mf][nf];
                    mma_bf16(d[0], d[1], d[2], d[3],
                             ah[mf][0], ah[mf][1], ah[mf][2], ah[mf][3], bh0, bh1);
                    mma_bf16(d[0], d[1], d[2], d[3],
                             ah[mf][0], ah[mf][1], ah[mf][2], ah[mf][3], bl0, bl1);
                    mma_bf16(d[0], d[1], d[2], d[3],
                             al[mf][0], al[mf][1], al[mf][2], al[mf][3], bh0, bh1);
                }
            }
        }
        #undef SM
        __syncthreads();
    }

    // Epilogue
    #pragma unroll
    for (int mf = 0; mf < 2; ++mf) {
        const int r = m0 + ms * 32 + mf * 16 + g8;
        #pragma unroll
        for (int nf = 0; nf < 8; ++nf) {
            const int c = n0 + ws * 64 + nf * 8 + 2 * t4;
            *(float2*)(Cout + (size_t)r * ldc + c) =
                make_float2(acc[mf][nf][0], acc[mf][nf][1]);
            *(float2*)(Cout + (size_t)(r + 8) * ldc + c) =
                make_float2(acc[mf][nf][2], acc[mf][nf][3]);
        }
    }
}

// ---------------------------------------------------------------------------
// Conversion / packing kernels
// ---------------------------------------------------------------------------
__global__ void cvt_split(const float* __restrict__ in,
                          __nv_bfloat16* __restrict__ hi,
                          __nv_bfloat16* __restrict__ lo, int n)
{
    const int i = blockIdx.x * blockDim.x + threadIdx.x;
    if (i >= n) return;
    const float x = in[i];
    const __nv_bfloat16 h = __float2bfloat16(x);
    hi[i] = h;
    lo[i] = __float2bfloat16(x - __bfloat162float(h));
}

__global__ void pack_wt(const float* __restrict__ Wq, const float* __restrict__ Wk,
                        const float* __restrict__ Wv)
{
    const int i = blockIdx.x * blockDim.x + threadIdx.x;
    if (i >= NQKV * C_) return;
    const int nn = i / C_;
    const int k  = i % C_;
    float v;
    if (nn < KOFF)      v = Wq[(size_t)k * (H_*DQK_) + nn];
    else if (nn < VOFF) v = Wk[(size_t)k * (G_*DQK_) + (nn - KOFF)];
    else                v = Wv[(size_t)k * (G_*DV_)  + (nn - VOFF)];
    const __nv_bfloat16 h = __float2bfloat16(v);
    g_wth[i] = h;
    g_wtl[i] = __float2bfloat16(v - __bfloat162float(h));
}

__global__ void pack_pt(const float* __restrict__ Wp)
{
    const int i = blockIdx.x * blockDim.x + threadIdx.x;
    if (i >= C_ * DV_) return;
    const int nn = i / DV_;
    const int k  = i % DV_;
    const float v = Wp[(size_t)k * C_ + nn];
    const __nv_bfloat16 h = __float2bfloat16(v);
    g_pth[i] = h;
    g_ptl[i] = __float2bfloat16(v - __bfloat162float(h));
}

// V region: fp32 -> fp16 copy into g_qkvh
__global__ void cvt_vh()
{
    const int i = blockIdx.x * blockDim.x + threadIdx.x;
    if (i >= NT_ * (G_ * DV_)) return;
    const int token = i >> 9;
    const int idx   = i & 511;
    const size_t off = (size_t)token * NQKV + VOFF + idx;
    g_qkvh[off] = __float2half(g_qkv[off]);
}

// Head-sum + bf16 split of attention output -> proj GEMM inputs
__global__ void sum_split_y()
{
    const int i = blockIdx.x * blockDim.x + threadIdx.x;
    if (i >= NT_ * DV_) return;
    float s = 0.f;
    #pragma unroll
    for (int h = 0; h < H_; ++h) s += g_yp[(size_t)h * NT_ * DV_ + i];
    const __nv_bfloat16 hi = __float2bfloat16(s);
    g_yh[i] = hi;
    g_yl[i] = __float2bfloat16(s - __bfloat162float(hi));
}

// ---------------------------------------------------------------------------
// RoPE + L2-norm (+ learned logit scale for q); fp32 in, fp16 out.
// ---------------------------------------------------------------------------
__global__ void rope_norm_kernel(const float* __restrict__ qnf)
{
    const int warp = (blockIdx.x * blockDim.x + threadIdx.x) >> 5;
    const int lane = threadIdx.x & 31;
    if (warp >= NT_ * 20) return;
    const int token = warp / 20;
    const int slot  = warp % 20;
    const int t     = token & (T_ - 1);

    const size_t off = (size_t)token * NQKV
                     + ((slot < 16) ? slot * DQK_ : KOFF + (slot - 16) * DQK_);
    const float* src = g_qkv + off;
    __half* dst = g_qkvh + off;

    const float x0 = src[lane];
    const float x1 = src[lane + 32];

    const float inv = __expf(-(float)lane * 0.28782313662425574f); // ln(1e4)/32
    const float ang = (float)t * inv;
    float s, c;
    sincosf(ang, &s, &c);

    const float r0 = x0 * c - x1 * s;
    const float r1 = x1 * c + x0 * s;

    float ss = r0 * r0 + r1 * r1;
    #pragma unroll
    for (int o = 16; o > 0; o >>= 1) ss += __shfl_xor_sync(0xFFFFFFFFu, ss, o);

    float scale = 1.f / (sqrtf(ss) + 1e-6f);
    if (slot < 16) scale *= qnf[0];

    dst[lane]      = __float2half(r0 * scale);
    dst[lane + 32] = __float2half(r1 * scale);
}

// ---------------------------------------------------------------------------
// Flash attention, FA2-style register softmax.
// CTA: 256 thr / 8 warps, Q-tile 128 (warp w owns rows w*16..w*16+15),
// K-tile 64. S and P live entirely in registers; row stats via quad shuffles.
// Per-head output (no atomics); sink folded into (m,l) init.
// ---------------------------------------------------------------------------
__global__ __launch_bounds__(256) void attn_kernel(const float* __restrict__ lobo)
{
    __shared__ __half Qs[128][72];
    __shared__ __half Ks[64][72];
    __shared__ __half Vt[128][72];   // [dim][key]

    const int tid  = threadIdx.x;
    const int wid  = tid >> 5;
    const int lane = tid & 31;
    const int g8   = lane >> 2;
    const int t4   = lane & 3;

    const int qt = (gridDim.x - 1 - blockIdx.x);  // long blocks first
    const int h  = blockIdx.y;
    const int b  = blockIdx.z;
    const int gq = h >> 2;
    const int q0 = qt * 128;
    const size_t tokbase = (size_t)b * T_;

    // Fill Q tile (128 x 64 halves): 16 half2 per thread
    #pragma unroll
    for (int i = 0; i < 16; ++i) {
        const int cid = tid + i * 256;
        const int row = cid >> 5;
        const int dp  = cid & 31;
        const uint32_t v = *(const uint32_t*)
            (g_qkvh + (tokbase + q0 + row) * NQKV + h * DQK_ + 2 * dp);
        *(uint32_t*)&Qs[row][2 * dp] = v;
    }

    const int rbase = (wid << 4);               // warp's first query row (local)
    const int rg0 = q0 + rbase + g8;            // global row (thread's row 0)
    const int rg1 = rg0 + 8;                    // row 1

    float m0 = lobo[h], m1 = m0;
    float l0 = 1.f, l1 = 1.f;
    float o[16][4];
    #pragma unroll
    for (int nf = 0; nf < 16; nf++)
        #pragma unroll
        for (int i = 0; i < 4; i++) o[nf][i] = 0.f;

    uint32_t qf[4][4];

    const int nkt = (qt + 1) * 2;
    for (int kt = 0; kt < nkt; ++kt) {
        const int k0 = kt * 64;
        __syncthreads();   // Q ready (iter 0) / K,V consumers done (later)

        // Fill K tile (64 x 64): 8 half2 per thread
        #pragma unroll
        for (int i = 0; i < 8; ++i) {
            const int cid = tid + i * 256;
            const int row = cid >> 5;
            const int dp  = cid & 31;
            const uint32_t v = *(const uint32_t*)
                (g_qkvh + (tokbase + k0 + row) * NQKV + KOFF + gq * DQK_ + 2 * dp);
            *(uint32_t*)&Ks[row][2 * dp] = v;
        }
        // Fill V tile transposed: Vt[dim][key]
        #pragma unroll
        for (int i = 0; i < 16; ++i) {
            const int cid = tid + i * 256;
            const int dp  = cid & 63;
            const int key = cid >> 6;
            const uint32_t v = *(const uint32_t*)
                (g_qkvh + (tokbase + k0 + key) * NQKV + VOFF + gq * DV_ + 2 * dp);
            const __half2 h2 = *(const __half2*)&v;
            Vt[2 * dp    ][key] = __low2half(h2);
            Vt[2 * dp + 1][key] = __high2half(h2);
        }
        __syncthreads();

        if (kt == 0) {   // load Q fragments once (Qs stable afterwards)
            #pragma unroll
            for (int kf = 0; kf < 4; ++kf) {
                const int cb = kf * 16 + 2 * t4;
                qf[kf][0] = *(const uint32_t*)&Qs[rbase + g8    ][cb];
                qf[kf][1] = *(const uint32_t*)&Qs[rbase + g8 + 8][cb];
                qf[kf][2] = *(const uint32_t*)&Qs[rbase + g8    ][cb + 8];
                qf[kf][3] = *(const uint32_t*)&Qs[rbase + g8 + 8][cb + 8];
            }
        }

        // S = Q K^T (warp: 16 x 64), fragments in registers
        float s[8][4];
        #pragma unroll
        for (int nf = 0; nf < 8; nf++)
            #pragma unroll
            for (int i = 0; i < 4; i++) s[nf][i] = 0.f;

        #pragma unroll
        for (int kf = 0; kf < 4; ++kf) {
            const int cb = kf * 16 + 2 * t4;
            #pragma unroll
            for (int nf = 0; nf < 8; ++nf) {
                const int n = nf * 8 + g8;
                const uint32_t b0 = *(const uint32_t*)&Ks[n][cb];
                const uint32_t b1 = *(const uint32_t*)&Ks[n][cb + 8];
                mma_f16(s[nf][0], s[nf][1], s[nf][2], s[nf][3],
                        qf[kf][0], qf[kf][1], qf[kf][2], qf[kf][3], b0, b1);
            }
        }

        // Causal mask (only the last two key tiles intersect the diagonal)
        if (kt >= nkt - 2) {
            #pragma unroll
            for (int nf = 0; nf < 8; ++nf) {
                const int c = k0 + nf * 8 + 2 * t4;
                if (c     > rg0) s[nf][0] = -1e30f;
                if (c + 1 > rg0) s[nf][1] = -1e30f;
                if (c     > rg1) s[nf][2] = -1e30f;
                if (c + 1 > rg1) s[nf][3] = -1e30f;
            }
        }

        // Row max (registers + quad shuffles)
        float mx0 = -1e30f, mx1 = -1e30f;
        #pragma unroll
        for (int nf = 0; nf < 8; ++nf) {
            mx0 = fmaxf(mx0, fmaxf(s[nf][0], s[nf][1]));
            mx1 = fmaxf(mx1, fmaxf(s[nf][2], s[nf][3]));
        }
        mx0 = fmaxf(mx0, __shfl_xor_sync(0xFFFFFFFFu, mx0, 1));
        mx0 = fmaxf(mx0, __shfl_xor_sync(0xFFFFFFFFu, mx0, 2));
        mx1 = fmaxf(mx1, __shfl_xor_sync(0xFFFFFFFFu, mx1, 1));
        mx1 = fmaxf(mx1, __shfl_xor_sync(0xFFFFFFFFu, mx1, 2));

        const float mn0 = fmaxf(m0, mx0);
        const float mn1 = fmaxf(m1, mx1);
        const float cr0 = __expf(m0 - mn0);
        const float cr1 = __expf(m1 - mn1);
        m0 = mn0; m1 = mn1;

        // Exponentiate in registers; pack P as fp16 A-fragments
        uint32_t pa[8], pb[8];
        float sum0 = 0.f, sum1 = 0.f;
        #pragma unroll
        for (int nf = 0; nf < 8; ++nf) {
            const float p0 = __expf(s[nf][0] - mn0);
            const float p1 = __expf(s[nf][1] - mn0);
            const float p2 = __expf(s[nf][2] - mn1);
            const float p3 = __expf(s[nf][3] - mn1);
            sum0 += p0 + p1;
            sum1 += p2 + p3;
            const __half2 ha = __floats2half2_rn(p0, p1);
            const __half2 hb = __floats2half2_rn(p2, p3);
            pa[nf] = *(const uint32_t*)&ha;
            pb[nf] = *(const uint32_t*)&hb;
        }
        sum0 += __shfl_xor_sync(0xFFFFFFFFu, sum0, 1);
        sum0 += __shfl_xor_sync(0xFFFFFFFFu, sum0, 2);
        sum1 += __shfl_xor_sync(0xFFFFFFFFu, sum1, 1);
        sum1 += __shfl_xor_sync(0xFFFFFFFFu, sum1, 2);
        l0 = l0 * cr0 + sum0;
        l1 = l1 * cr1 + sum1;

        // Rescale O, then O += P V  (P fragments ARE the mma A-fragments)
        #pragma unroll
        for (int nf = 0; nf < 16; ++nf) {
            o[nf][0] *= cr0; o[nf][1] *= cr0;
            o[nf][2] *= cr1; o[nf][3] *= cr1;
        }
        #pragma unroll
        for (int kf = 0; kf < 4; ++kf) {
            const int cb = kf * 16 + 2 * t4;
            const uint32_t a0 = pa[2 * kf];
            const uint32_t a1 = pb[2 * kf];
            const uint32_t a2 = pa[2 * kf + 1];
            const uint32_t a3 = pb[2 * kf + 1];
            #pragma unroll
            for (int nf = 0; nf < 16; ++nf) {
                const int dv = nf * 8 + g8;
                const uint32_t b0 = *(const uint32_t*)&Vt[dv][cb];
                const uint32_t b1 = *(const uint32_t*)&Vt[dv][cb + 8];
                mma_f16(o[nf][0], o[nf][1], o[nf][2], o[nf][3],
                        a0, a1, a2, a3, b0, b1);
            }
        }
    }

    // Normalize, write per-head output (no atomics)
    {
        const float inv0 = 1.f / l0;
        const float inv1 = 1.f / l1;
        float* dst0 = g_yp + ((size_t)h * NT_ + tokbase + rg0 - 0) * DV_;
        float* dst1 = g_yp + ((size_t)h * NT_ + tokbase + rg1 - 0) * DV_;
        // rg0/rg1 are global in [0,T); add q-independent token base already in rg
        #pragma unroll
        for (int nf = 0; nf < 16; ++nf) {
            const int c = nf * 8 + 2 * t4;
            *(float2*)(dst0 + c) = make_float2(o[nf][0] * inv0, o[nf][1] * inv0);
            *(float2*)(dst1 + c) = make_float2(o[nf][2] * inv1, o[nf][3] * inv1);
        }
    }
}

// ---------------------------------------------------------------------------
// Launch
// ---------------------------------------------------------------------------
extern "C" void kernel_launch(void* const* d_in, const int* in_sizes, int n_in,
                              void* d_out, int out_size)
{
    const float* x     = (const float*)d_in[0];
    // d_in[1] = iter_num (unused)
    const float* Wq    = (const float*)d_in[2];
    const float* Wk    = (const float*)d_in[3];
    const float* Wv    = (const float*)d_in[4];
    const float* Wproj = (const float*)d_in[5];
    const float* lobo  = (const float*)d_in[6];
    const float* qnf   = (const float*)d_in[7];
    float* out = (float*)d_out;

    __nv_bfloat16 *xh, *xl, *wth, *wtl, *yh, *yl, *pth, *ptl;
    float *qkv_ptr;
    cudaGetSymbolAddress((void**)&xh, g_xh);
    cudaGetSymbolAddress((void**)&xl, g_xl);
    cudaGetSymbolAddress((void**)&wth, g_wth);
    cudaGetSymbolAddress((void**)&wtl, g_wtl);
    cudaGetSymbolAddress((void**)&yh, g_yh);
    cudaGetSymbolAddress((void**)&yl, g_yl);
    cudaGetSymbolAddress((void**)&pth, g_pth);
    cudaGetSymbolAddress((void**)&ptl, g_ptl);
    cudaGetSymbolAddress((void**)&qkv_ptr, g_qkv);

    cudaFuncSetAttribute(mm_gemm, cudaFuncAttributeMaxDynamicSharedMemorySize,
                         MM_SMEM_BYTES);

    // Pack/convert inputs to split-bf16
    pack_wt<<<(NQKV * C_ + 255) / 256, 256>>>(Wq, Wk, Wv);
    pack_pt<<<(C_ * DV_ + 255) / 256, 256>>>(Wproj);
    cvt_split<<<(NT_ * C_ + 255) / 256, 256>>>(x, xh, xl, NT_ * C_);

    // Fused QKV projection: [4096,1024] x [1792,1024]^T -> g_qkv (fp32)
    mm_gemm<<<dim3(NQKV / 128, NT_ / 128), 256, MM_SMEM_BYTES>>>(
        xh, xl, wth, wtl, qkv_ptr, C_, NQKV);

    // RoPE + qk-norm + logit scale -> fp16 q/k; V -> fp16
    rope_norm_kernel<<<(NT_ * 20) / 8, 256>>>(qnf);
    cvt_vh<<<(NT_ * (G_ * DV_) + 255) / 256, 256>>>();

    // Attention (register-softmax FA2) -> per-head g_yp
    attn_kernel<<<dim3(T_ / 128, H_, B_), 256>>>(lobo);

    // Head-sum + split, then output projection
    sum_split_y<<<(NT_ * DV_ + 255) / 256, 256>>>();
    mm_gemm<<<dim3(C_ / 128, NT_ / 128), 256, MM_SMEM_BYTES>>>(
        yh, yl, pth, ptl, out, DV_, C_);
}

// round 6
// speedup vs baseline: 7.4141x; 1.2282x over previous
#include <cuda_runtime.h>
#include <cuda_bf16.h>
#include <cuda_fp16.h>
#include <math.h>
#include <stdint.h>

// Problem constants
#define B_   2
#define T_   2048
#define C_   1024
#define H_   16
#define G_   4
#define DQK_ 64
#define DV_  128
#define NT_  (B_ * T_)        // 4096 tokens
#define NQKV (H_*DQK_ + G_*DQK_ + G_*DV_)   // 1792
#define KOFF (H_*DQK_)        // 1024
#define VOFF (H_*DQK_ + G_*DQK_) // 1280
#define LOG2E_ 1.4426950408889634f

// ---------------------------------------------------------------------------
// Device scratch (no cudaMalloc allowed)
// ---------------------------------------------------------------------------
__device__ __nv_bfloat16 g_xh[(size_t)NT_ * C_];     // x split-bf16 hi
__device__ __nv_bfloat16 g_xl[(size_t)NT_ * C_];     // x split-bf16 lo
__device__ __nv_bfloat16 g_wth[(size_t)NQKV * C_];   // packed W^T [1792][1024] hi
__device__ __nv_bfloat16 g_wtl[(size_t)NQKV * C_];   // lo
__device__ __nv_bfloat16 g_yh[(size_t)NT_ * DV_];    // head-summed attn out hi
__device__ __nv_bfloat16 g_yl[(size_t)NT_ * DV_];    // lo
__device__ __nv_bfloat16 g_pth[(size_t)C_ * DV_];    // Wproj^T [1024][128] hi
__device__ __nv_bfloat16 g_ptl[(size_t)C_ * DV_];    // lo
__device__ float  g_qkv[(size_t)NT_ * NQKV];         // fused projection (fp32)
__device__ __half g_qkvh[(size_t)NT_ * NQKV];        // fp16 q(roped)/k(roped)/v
__device__ float  g_yp[(size_t)H_ * NT_ * DV_];      // per-head attn output

// ---------------------------------------------------------------------------
// mma.sync / ldmatrix / cp.async helpers (sm_80+ PTX; valid on compute_103)
// ---------------------------------------------------------------------------
__device__ __forceinline__ void mma_f16(float& d0, float& d1, float& d2, float& d3,
    uint32_t a0, uint32_t a1, uint32_t a2, uint32_t a3, uint32_t b0, uint32_t b1)
{
    asm volatile(
        "mma.sync.aligned.m16n8k16.row.col.f32.f16.f16.f32 "
        "{%0,%1,%2,%3},{%4,%5,%6,%7},{%8,%9},{%0,%1,%2,%3};"
        : "+f"(d0), "+f"(d1), "+f"(d2), "+f"(d3)
        : "r"(a0), "r"(a1), "r"(a2), "r"(a3), "r"(b0), "r"(b1));
}

__device__ __forceinline__ void mma_bf16(float& d0, float& d1, float& d2, float& d3,
    uint32_t a0, uint32_t a1, uint32_t a2, uint32_t a3, uint32_t b0, uint32_t b1)
{
    asm volatile(
        "mma.sync.aligned.m16n8k16.row.col.f32.bf16.bf16.f32 "
        "{%0,%1,%2,%3},{%4,%5,%6,%7},{%8,%9},{%0,%1,%2,%3};"
        : "+f"(d0), "+f"(d1), "+f"(d2), "+f"(d3)
        : "r"(a0), "r"(a1), "r"(a2), "r"(a3), "r"(b0), "r"(b1));
}

__device__ __forceinline__ void ldsm_x4(uint32_t& r0, uint32_t& r1,
                                        uint32_t& r2, uint32_t& r3, uint32_t a)
{
    asm volatile("ldmatrix.sync.aligned.m8n8.x4.shared.b16 {%0,%1,%2,%3}, [%4];"
                 : "=r"(r0), "=r"(r1), "=r"(r2), "=r"(r3) : "r"(a));
}

__device__ __forceinline__ void ldsm_x4_t(uint32_t& r0, uint32_t& r1,
                                          uint32_t& r2, uint32_t& r3, uint32_t a)
{
    asm volatile("ldmatrix.sync.aligned.m8n8.x4.trans.shared.b16 {%0,%1,%2,%3}, [%4];"
                 : "=r"(r0), "=r"(r1), "=r"(r2), "=r"(r3) : "r"(a));
}

__device__ __forceinline__ uint32_t smem_u32(const void* p) {
    uint32_t a;
    asm("{ .reg .u64 t; cvta.to.shared.u64 t, %1; cvt.u32.u64 %0, t; }"
        : "=r"(a) : "l"(p));
    return a;
}

#define CP_ASYNC16(dst, src) \
    asm volatile("cp.async.cg.shared.global [%0], [%1], 16;" \
                 :: "r"(dst), "l"(src) : "memory")
#define CP_COMMIT() asm volatile("cp.async.commit_group;" ::: "memory")
#define CP_WAIT(n)  asm volatile("cp.async.wait_group %0;" :: "n"(n) : "memory")

// ---------------------------------------------------------------------------
// Split-bf16 GEMM: C[M,N] = (Ah+Al)[M,K] @ (Bh+Bl)[N,K]^T     (unchanged)
// ---------------------------------------------------------------------------
#define MM_SMEM_BYTES (2 * 4 * 128 * 40 * 2)   // 81920

__global__ __launch_bounds__(256) void mm_gemm(
    const __nv_bfloat16* __restrict__ Ah, const __nv_bfloat16* __restrict__ Al,
    const __nv_bfloat16* __restrict__ Bh, const __nv_bfloat16* __restrict__ Bl,
    float* __restrict__ Cout, int K, int ldc)
{
    extern __shared__ __nv_bfloat16 smd[];   // [stage][tile][128][40]

    const int tid  = threadIdx.x;
    const int wid  = tid >> 5;
    const int lane = tid & 31;
    const int g8   = lane >> 2;
    const int t4   = lane & 3;
    const int m0   = blockIdx.y * 128;
    const int n0   = blockIdx.x * 128;
    const int ms   = wid & 3;
    const int ws   = wid >> 2;

    const __nv_bfloat16* srcs[4] = {
        Ah + (size_t)m0 * K, Al + (size_t)m0 * K,
        Bh + (size_t)n0 * K, Bl + (size_t)n0 * K };

    const int f_row = tid >> 2;
    const int f_ch  = tid & 3;

    auto issue_stage = [&](int s, int st) {
        const int k0 = s << 5;
        #pragma unroll
        for (int t = 0; t < 8; ++t) {
            const int tl  = t >> 1;
            const int row = ((t & 1) << 6) + f_row;
            const __nv_bfloat16* src = srcs[tl] + (size_t)row * K + k0 + f_ch * 8;
            const uint32_t dst = smem_u32(
                smd + ((size_t)((st * 4 + tl) * 128 + row)) * 40 + f_ch * 8);
            CP_ASYNC16(dst, src);
        }
        CP_COMMIT();
    };

    float acc[2][8][4];
    #pragma unroll
    for (int mf = 0; mf < 2; mf++)
        #pragma unroll
        for (int nf = 0; nf < 8; nf++)
            #pragma unroll
            for (int i = 0; i < 4; i++) acc[mf][nf][i] = 0.f;

    const int nst = K >> 5;
    issue_stage(0, 0);

    for (int s = 0; s < nst; ++s) {
        const int st = s & 1;
        if (s + 1 < nst) { issue_stage(s + 1, (s + 1) & 1); CP_WAIT(1); }
        else             { CP_WAIT(0); }
        __syncthreads();

        const __nv_bfloat16* smb = smd + (size_t)st * 4 * 128 * 40;
        #define SM(tl, r, c) (smb + ((size_t)((tl) * 128 + (r))) * 40 + (c))

        #pragma unroll
        for (int ks = 0; ks < 2; ++ks) {
            const int cb = ks * 16 + 2 * t4;
            uint32_t ah[2][4], al[2][4];
            #pragma unroll
            for (int mf = 0; mf < 2; ++mf) {
                const int r0 = ms * 32 + mf * 16 + g8;
                ah[mf][0] = *(const uint32_t*)SM(0, r0,     cb);
                ah[mf][1] = *(const uint32_t*)SM(0, r0 + 8, cb);
                ah[mf][2] = *(const uint32_t*)SM(0, r0,     cb + 8);
                ah[mf][3] = *(const uint32_t*)SM(0, r0 + 8, cb + 8);
                al[mf][0] = *(const uint32_t*)SM(1, r0,     cb);
                al[mf][1] = *(const uint32_t*)SM(1, r0 + 8, cb);
                al[mf][2] = *(const uint32_t*)SM(1, r0,     cb + 8);
                al[mf][3] = *(const uint32_t*)SM(1, r0 + 8, cb + 8);
            }
            #pragma unroll
            for (int nf = 0; nf < 8; ++nf) {
                const int n = ws * 64 + nf * 8 + g8;
                const uint32_t bh0 = *(const uint32_t*)SM(2, n, cb);
                const uint32_t bh1 = *(const uint32_t*)SM(2, n, cb + 8);
                const uint32_t bl0 = *(const uint32_t*)SM(3, n, cb);
                const uint32_t bl1 = *(const uint32_t*)SM(3, n, cb + 8);
                #pragma unroll
                for (int mf = 0; mf < 2; ++mf) {
                    float* d = acc[mf][nf];
                    mma_bf16(d[0], d[1], d[2], d[3],
                             ah[mf][0], ah[mf][1], ah[mf][2], ah[mf][3], bh0, bh1);
                    mma_bf16(d[0], d[1], d[2], d[3],
                             ah[mf][0], ah[mf][1], ah[mf][2], ah[mf][3], bl0, bl1);
                    mma_bf16(d[0], d[1], d[2], d[3],
                             al[mf][0], al[mf][1], al[mf][2], al[mf][3], bh0, bh1);
                }
            }
        }
        #undef SM
        __syncthreads();
    }

    #pragma unroll
    for (int mf = 0; mf < 2; ++mf) {
        const int r = m0 + ms * 32 + mf * 16 + g8;
        #pragma unroll
        for (int nf = 0; nf < 8; ++nf) {
            const int c = n0 + ws * 64 + nf * 8 + 2 * t4;
            *(float2*)(Cout + (size_t)r * ldc + c) =
                make_float2(acc[mf][nf][0], acc[mf][nf][1]);
            *(float2*)(Cout + (size_t)(r + 8) * ldc + c) =
                make_float2(acc[mf][nf][2], acc[mf][nf][3]);
        }
    }
}

// ---------------------------------------------------------------------------
// Conversion / packing kernels
// ---------------------------------------------------------------------------
__global__ void cvt_split(const float* __restrict__ in,
                          __nv_bfloat16* __restrict__ hi,
                          __nv_bfloat16* __restrict__ lo, int n)
{
    const int i = blockIdx.x * blockDim.x + threadIdx.x;
    if (i >= n) return;
    const float x = in[i];
    const __nv_bfloat16 h = __float2bfloat16(x);
    hi[i] = h;
    lo[i] = __float2bfloat16(x - __bfloat162float(h));
}

__global__ void pack_wt(const float* __restrict__ Wq, const float* __restrict__ Wk,
                        const float* __restrict__ Wv)
{
    const int i = blockIdx.x * blockDim.x + threadIdx.x;
    if (i >= NQKV * C_) return;
    const int nn = i / C_;
    const int k  = i % C_;
    float v;
    if (nn < KOFF)      v = Wq[(size_t)k * (H_*DQK_) + nn];
    else if (nn < VOFF) v = Wk[(size_t)k * (G_*DQK_) + (nn - KOFF)];
    else                v = Wv[(size_t)k * (G_*DV_)  + (nn - VOFF)];
    const __nv_bfloat16 h = __float2bfloat16(v);
    g_wth[i] = h;
    g_wtl[i] = __float2bfloat16(v - __bfloat162float(h));
}

__global__ void pack_pt(const float* __restrict__ Wp)
{
    const int i = blockIdx.x * blockDim.x + threadIdx.x;
    if (i >= C_ * DV_) return;
    const int nn = i / DV_;
    const int k  = i % DV_;
    const float v = Wp[(size_t)k * C_ + nn];
    const __nv_bfloat16 h = __float2bfloat16(v);
    g_pth[i] = h;
    g_ptl[i] = __float2bfloat16(v - __bfloat162float(h));
}

// V region: fp32 -> fp16 copy into g_qkvh
__global__ void cvt_vh()
{
    const int i = blockIdx.x * blockDim.x + threadIdx.x;
    if (i >= NT_ * (G_ * DV_)) return;
    const int token = i >> 9;
    const int idx   = i & 511;
    const size_t off = (size_t)token * NQKV + VOFF + idx;
    g_qkvh[off] = __float2half(g_qkv[off]);
}

// Head-sum + bf16 split of attention output -> proj GEMM inputs
__global__ void sum_split_y()
{
    const int i = blockIdx.x * blockDim.x + threadIdx.x;
    if (i >= NT_ * DV_) return;
    float s = 0.f;
    #pragma unroll
    for (int h = 0; h < H_; ++h) s += g_yp[(size_t)h * NT_ * DV_ + i];
    const __nv_bfloat16 hi = __float2bfloat16(s);
    g_yh[i] = hi;
    g_yl[i] = __float2bfloat16(s - __bfloat162float(hi));
}

// ---------------------------------------------------------------------------
// RoPE + L2-norm; q scale folded with log2e (attention runs in exp2 domain).
// ---------------------------------------------------------------------------
__global__ void rope_norm_kernel(const float* __restrict__ qnf)
{
    const int warp = (blockIdx.x * blockDim.x + threadIdx.x) >> 5;
    const int lane = threadIdx.x & 31;
    if (warp >= NT_ * 20) return;
    const int token = warp / 20;
    const int slot  = warp % 20;
    const int t     = token & (T_ - 1);

    const size_t off = (size_t)token * NQKV
                     + ((slot < 16) ? slot * DQK_ : KOFF + (slot - 16) * DQK_);
    const float* src = g_qkv + off;
    __half* dst = g_qkvh + off;

    const float x0 = src[lane];
    const float x1 = src[lane + 32];

    const float inv = __expf(-(float)lane * 0.28782313662425574f); // ln(1e4)/32
    const float ang = (float)t * inv;
    float s, c;
    sincosf(ang, &s, &c);

    const float r0 = x0 * c - x1 * s;
    const float r1 = x1 * c + x0 * s;

    float ss = r0 * r0 + r1 * r1;
    #pragma unroll
    for (int o = 16; o > 0; o >>= 1) ss += __shfl_xor_sync(0xFFFFFFFFu, ss, o);

    float scale = 1.f / (sqrtf(ss) + 1e-6f);
    if (slot < 16) scale *= qnf[0] * LOG2E_;   // logit scale + base-2 domain

    dst[lane]      = __float2half(r0 * scale);
    dst[lane + 32] = __float2half(r1 * scale);
}

// ---------------------------------------------------------------------------
// Flash attention, FA2 register softmax (exp2 domain), cp.async double-buffered
// K/V, ldmatrix fragment loads. 256 thr / 8 warps; Q-tile 128, K-tile 64.
// ---------------------------------------------------------------------------
struct AttnSmem {
    __half Qs[128][72];       // 144B rows
    __half Ks[2][64][72];     // [key][dim], 144B rows
    __half Vs[2][64][136];    // [key][dim], 272B rows
};
#define ATTN_SMEM ((int)sizeof(AttnSmem))

__global__ __launch_bounds__(256) void attn_kernel(const float* __restrict__ lobo)
{
    extern __shared__ char smem_raw[];
    AttnSmem& S = *reinterpret_cast<AttnSmem*>(smem_raw);

    const int tid  = threadIdx.x;
    const int wid  = tid >> 5;
    const int lane = tid & 31;
    const int g8   = lane >> 2;
    const int t4   = lane & 3;

    const int qt = (gridDim.x - 1 - blockIdx.x);  // long blocks first
    const int h  = blockIdx.y;
    const int b  = blockIdx.z;
    const int gq = h >> 2;
    const int q0 = qt * 128;
    const size_t tokbase = (size_t)b * T_;

    // ldmatrix per-thread address components
    const int krow  = lane & 7;               // K frags (x4, non-trans)
    const int kcol8 = (lane >> 3) * 8;
    const int vrow  = (lane & 7) + ((lane >> 3) & 1) * 8;   // V frags (x4 trans)
    const int vcol8 = (lane >> 4) * 8;

    // Fill Q tile (128 x 64 halves)
    #pragma unroll
    for (int i = 0; i < 16; ++i) {
        const int cid = tid + i * 256;
        const int row = cid >> 5;
        const int dp  = cid & 31;
        const uint32_t v = *(const uint32_t*)
            (g_qkvh + (tokbase + q0 + row) * NQKV + h * DQK_ + 2 * dp);
        *(uint32_t*)&S.Qs[row][2 * dp] = v;
    }

    const int rbase = (wid << 4);
    const int rg0 = q0 + rbase + g8;
    const int rg1 = rg0 + 8;

    float m0 = lobo[h] * LOG2E_, m1 = m0;   // base-2 domain
    float l0 = 1.f, l1 = 1.f;
    float o[16][4];
    #pragma unroll
    for (int nf = 0; nf < 16; nf++)
        #pragma unroll
        for (int i = 0; i < 4; i++) o[nf][i] = 0.f;

    uint32_t qf[4][4];

    const int nkt = (qt + 1) * 2;

    auto issue_kv = [&](int kt) {
        const int st = kt & 1;
        const int k0 = kt * 64;
        #pragma unroll
        for (int j = 0; j < 2; ++j) {       // K: 64 rows x 128B
            const int idx = tid + j * 256;
            const int row = idx >> 3, c = idx & 7;
            CP_ASYNC16(smem_u32(&S.Ks[st][row][c * 8]),
                g_qkvh + (tokbase + k0 + row) * NQKV + KOFF + gq * DQK_ + c * 8);
        }
        #pragma unroll
        for (int j = 0; j < 4; ++j) {       // V: 64 rows x 256B
            const int idx = tid + j * 256;
            const int row = idx >> 4, c = idx & 15;
            CP_ASYNC16(smem_u32(&S.Vs[st][row][c * 8]),
                g_qkvh + (tokbase + k0 + row) * NQKV + VOFF + gq * DV_ + c * 8);
        }
        CP_COMMIT();
    };

    issue_kv(0);
    issue_kv(1);

    for (int kt = 0; kt < nkt; ++kt) {
        const int st = kt & 1;
        if (kt + 1 < nkt) CP_WAIT(1);
        else              CP_WAIT(0);
        __syncthreads();

        if (kt == 0) {   // Q fragments once (Qs stable afterwards)
            #pragma unroll
            for (int kf = 0; kf < 4; ++kf) {
                const int cb = kf * 16 + 2 * t4;
                qf[kf][0] = *(const uint32_t*)&S.Qs[rbase + g8    ][cb];
                qf[kf][1] = *(const uint32_t*)&S.Qs[rbase + g8 + 8][cb];
                qf[kf][2] = *(const uint32_t*)&S.Qs[rbase + g8    ][cb + 8];
                qf[kf][3] = *(const uint32_t*)&S.Qs[rbase + g8 + 8][cb + 8];
            }
        }

        // --- S = Q K^T, K frags via ldmatrix.x4 ---
        float s[8][4];
        #pragma unroll
        for (int nf = 0; nf < 8; nf++)
            #pragma unroll
            for (int i = 0; i < 4; i++) s[nf][i] = 0.f;

        const uint32_t ksb = smem_u32(&S.Ks[st][0][0]);
        #pragma unroll
        for (int kp = 0; kp < 2; ++kp) {        // dims kp*32 .. kp*32+31
            #pragma unroll
            for (int nf = 0; nf < 8; ++nf) {
                uint32_t b0a, b1a, b0b, b1b;
                ldsm_x4(b0a, b1a, b0b, b1b,
                        ksb + (uint32_t)(((nf * 8 + krow) * 72
                                          + kp * 32 + kcol8) * 2));
                mma_f16(s[nf][0], s[nf][1], s[nf][2], s[nf][3],
                        qf[2*kp][0], qf[2*kp][1], qf[2*kp][2], qf[2*kp][3],
                        b0a, b1a);
                mma_f16(s[nf][0], s[nf][1], s[nf][2], s[nf][3],
                        qf[2*kp+1][0], qf[2*kp+1][1], qf[2*kp+1][2], qf[2*kp+1][3],
                        b0b, b1b);
            }
        }

        // Causal mask (last two key tiles only)
        if (kt >= nkt - 2) {
            const int k0 = kt * 64;
            #pragma unroll
            for (int nf = 0; nf < 8; ++nf) {
                const int c = k0 + nf * 8 + 2 * t4;
                if (c     > rg0) s[nf][0] = -1e30f;
                if (c + 1 > rg0) s[nf][1] = -1e30f;
                if (c     > rg1) s[nf][2] = -1e30f;
                if (c + 1 > rg1) s[nf][3] = -1e30f;
            }
        }

        // Row max
        float mx0 = -1e30f, mx1 = -1e30f;
        #pragma unroll
        for (int nf = 0; nf < 8; ++nf) {
            mx0 = fmaxf(mx0, fmaxf(s[nf][0], s[nf][1]));
            mx1 = fmaxf(mx1, fmaxf(s[nf][2], s[nf][3]));
        }
        mx0 = fmaxf(mx0, __shfl_xor_sync(0xFFFFFFFFu, mx0, 1));
        mx0 = fmaxf(mx0, __shfl_xor_sync(0xFFFFFFFFu, mx0, 2));
        mx1 = fmaxf(mx1, __shfl_xor_sync(0xFFFFFFFFu, mx1, 1));
        mx1 = fmaxf(mx1, __shfl_xor_sync(0xFFFFFFFFu, mx1, 2));

        const float mn0 = fmaxf(m0, mx0);
        const float mn1 = fmaxf(m1, mx1);
        const float cr0 = exp2f(m0 - mn0);
        const float cr1 = exp2f(m1 - mn1);
        m0 = mn0; m1 = mn1;

        // Exponentiate (base 2), pack P as A-fragments
        uint32_t pa[8], pb[8];
        float sum0 = 0.f, sum1 = 0.f;
        #pragma unroll
        for (int nf = 0; nf < 8; ++nf) {
            const float p0 = exp2f(s[nf][0] - mn0);
            const float p1 = exp2f(s[nf][1] - mn0);
            const float p2 = exp2f(s[nf][2] - mn1);
            const float p3 = exp2f(s[nf][3] - mn1);
            sum0 += p0 + p1;
            sum1 += p2 + p3;
            const __half2 ha = __floats2half2_rn(p0, p1);
            const __half2 hb = __floats2half2_rn(p2, p3);
            pa[nf] = *(const uint32_t*)&ha;
            pb[nf] = *(const uint32_t*)&hb;
        }
        sum0 += __shfl_xor_sync(0xFFFFFFFFu, sum0, 1);
        sum0 += __shfl_xor_sync(0xFFFFFFFFu, sum0, 2);
        sum1 += __shfl_xor_sync(0xFFFFFFFFu, sum1, 1);
        sum1 += __shfl_xor_sync(0xFFFFFFFFu, sum1, 2);
        l0 = l0 * cr0 + sum0;
        l1 = l1 * cr1 + sum1;

        // Rescale O, then O += P V (V frags via ldmatrix.x4.trans)
        #pragma unroll
        for (int nf = 0; nf < 16; ++nf) {
            o[nf][0] *= cr0; o[nf][1] *= cr0;
            o[nf][2] *= cr1; o[nf][3] *= cr1;
        }
        const uint32_t vsb = smem_u32(&S.Vs[st][0][0]);
        #pragma unroll
        for (int kf = 0; kf < 4; ++kf) {
            const uint32_t a0 = pa[2 * kf];
            const uint32_t a1 = pb[2 * kf];
            const uint32_t a2 = pa[2 * kf + 1];
            const uint32_t a3 = pb[2 * kf + 1];
            #pragma unroll
            for (int np = 0; np < 8; ++np) {    // dim pair groups of 16
                uint32_t b0, b1, b2, b3;
                ldsm_x4_t(b0, b1, b2, b3,
                          vsb + (uint32_t)(((kf * 16 + vrow) * 136
                                            + np * 16 + vcol8) * 2));
                mma_f16(o[2*np][0], o[2*np][1], o[2*np][2], o[2*np][3],
                        a0, a1, a2, a3, b0, b1);
                mma_f16(o[2*np+1][0], o[2*np+1][1], o[2*np+1][2], o[2*np+1][3],
                        a0, a1, a2, a3, b2, b3);
            }
        }

        __syncthreads();
        if (kt + 2 < nkt) issue_kv(kt + 2);
    }

    // Normalize, write per-head output (no atomics)
    {
        const float inv0 = 1.f / l0;
        const float inv1 = 1.f / l1;
        float* dst0 = g_yp + ((size_t)h * NT_ + tokbase + rg0) * DV_;
        float* dst1 = g_yp + ((size_t)h * NT_ + tokbase + rg1) * DV_;
        #pragma unroll
        for (int nf = 0; nf < 16; ++nf) {
            const int c = nf * 8 + 2 * t4;
            *(float2*)(dst0 + c) = make_float2(o[nf][0] * inv0, o[nf][1] * inv0);
            *(float2*)(dst1 + c) = make_float2(o[nf][2] * inv1, o[nf][3] * inv1);
        }
    }
}

// ---------------------------------------------------------------------------
// Launch
// ---------------------------------------------------------------------------
extern "C" void kernel_launch(void* const* d_in, const int* in_sizes, int n_in,
                              void* d_out, int out_size)
{
    const float* x     = (const float*)d_in[0];
    // d_in[1] = iter_num (unused)
    const float* Wq    = (const float*)d_in[2];
    const float* Wk    = (const float*)d_in[3];
    const float* Wv    = (const float*)d_in[4];
    const float* Wproj = (const float*)d_in[5];
    const float* lobo  = (const float*)d_in[6];
    const float* qnf   = (const float*)d_in[7];
    float* out = (float*)d_out;

    __nv_bfloat16 *xh, *xl, *wth, *wtl, *yh, *yl, *pth, *ptl;
    float *qkv_ptr;
    cudaGetSymbolAddress((void**)&xh, g_xh);
    cudaGetSymbolAddress((void**)&xl, g_xl);
    cudaGetSymbolAddress((void**)&wth, g_wth);
    cudaGetSymbolAddress((void**)&wtl, g_wtl);
    cudaGetSymbolAddress((void**)&yh, g_yh);
    cudaGetSymbolAddress((void**)&yl, g_yl);
    cudaGetSymbolAddress((void**)&pth, g_pth);
    cudaGetSymbolAddress((void**)&ptl, g_ptl);
    cudaGetSymbolAddress((void**)&qkv_ptr, g_qkv);

    cudaFuncSetAttribute(mm_gemm, cudaFuncAttributeMaxDynamicSharedMemorySize,
                         MM_SMEM_BYTES);
    cudaFuncSetAttribute(attn_kernel, cudaFuncAttributeMaxDynamicSharedMemorySize,
                         ATTN_SMEM);

    // Pack/convert inputs to split-bf16
    pack_wt<<<(NQKV * C_ + 255) / 256, 256>>>(Wq, Wk, Wv);
    pack_pt<<<(C_ * DV_ + 255) / 256, 256>>>(Wproj);
    cvt_split<<<(NT_ * C_ + 255) / 256, 256>>>(x, xh, xl, NT_ * C_);

    // Fused QKV projection: [4096,1024] x [1792,1024]^T -> g_qkv (fp32)
    mm_gemm<<<dim3(NQKV / 128, NT_ / 128), 256, MM_SMEM_BYTES>>>(
        xh, xl, wth, wtl, qkv_ptr, C_, NQKV);

    // RoPE + qk-norm + logit scale (base-2) -> fp16 q/k; V -> fp16
    rope_norm_kernel<<<(NT_ * 20) / 8, 256>>>(qnf);
    cvt_vh<<<(NT_ * (G_ * DV_) + 255) / 256, 256>>>();

    // Attention (register-softmax FA2, cp.async, ldmatrix) -> per-head g_yp
    attn_kernel<<<dim3(T_ / 128, H_, B_), 256, ATTN_SMEM>>>(lobo);

    // Head-sum + split, then output projection
    sum_split_y<<<(NT_ * DV_ + 255) / 256, 256>>>();
    mm_gemm<<<dim3(C_ / 128, NT_ / 128), 256, MM_SMEM_BYTES>>>(
        yh, yl, pth, ptl, out, DV_, C_);
}

// round 7
// speedup vs baseline: 7.7252x; 1.0420x over previous
#include <cuda_runtime.h>
#include <cuda_bf16.h>
#include <cuda_fp16.h>
#include <math.h>
#include <stdint.h>

// Problem constants
#define B_   2
#define T_   2048
#define C_   1024
#define H_   16
#define G_   4
#define DQK_ 64
#define DV_  128
#define NT_  (B_ * T_)        // 4096 tokens
#define NQKV (H_*DQK_ + G_*DQK_ + G_*DV_)   // 1792
#define KOFF (H_*DQK_)        // 1024
#define VOFF (H_*DQK_ + G_*DQK_) // 1280
#define LOG2E_ 1.4426950408889634f

// ---------------------------------------------------------------------------
// Device scratch (no cudaMalloc allowed)
// ---------------------------------------------------------------------------
__device__ __nv_bfloat16 g_xh[(size_t)NT_ * C_];     // x split-bf16 hi
__device__ __nv_bfloat16 g_xl[(size_t)NT_ * C_];     // x split-bf16 lo
__device__ __nv_bfloat16 g_wth[(size_t)NQKV * C_];   // packed W^T [1792][1024] hi
__device__ __nv_bfloat16 g_wtl[(size_t)NQKV * C_];   // lo
__device__ __nv_bfloat16 g_yh[(size_t)NT_ * DV_];    // head-summed attn out hi
__device__ __nv_bfloat16 g_yl[(size_t)NT_ * DV_];    // lo
__device__ __nv_bfloat16 g_pth[(size_t)C_ * DV_];    // Wproj^T [1024][128] hi
__device__ __nv_bfloat16 g_ptl[(size_t)C_ * DV_];    // lo
__device__ float  g_qkv[(size_t)NT_ * NQKV];         // fused projection (fp32)
__device__ __half g_qkvh[(size_t)NT_ * NQKV];        // fp16 q(roped)/k(roped)/v
__device__ float  g_yp[(size_t)H_ * NT_ * DV_];      // per-head attn output

// ---------------------------------------------------------------------------
// mma.sync / ldmatrix / cp.async helpers (sm_80+ PTX; valid on compute_103)
// ---------------------------------------------------------------------------
__device__ __forceinline__ void mma_f16(float& d0, float& d1, float& d2, float& d3,
    uint32_t a0, uint32_t a1, uint32_t a2, uint32_t a3, uint32_t b0, uint32_t b1)
{
    asm volatile(
        "mma.sync.aligned.m16n8k16.row.col.f32.f16.f16.f32 "
        "{%0,%1,%2,%3},{%4,%5,%6,%7},{%8,%9},{%0,%1,%2,%3};"
        : "+f"(d0), "+f"(d1), "+f"(d2), "+f"(d3)
        : "r"(a0), "r"(a1), "r"(a2), "r"(a3), "r"(b0), "r"(b1));
}

__device__ __forceinline__ void mma_bf16(float& d0, float& d1, float& d2, float& d3,
    uint32_t a0, uint32_t a1, uint32_t a2, uint32_t a3, uint32_t b0, uint32_t b1)
{
    asm volatile(
        "mma.sync.aligned.m16n8k16.row.col.f32.bf16.bf16.f32 "
        "{%0,%1,%2,%3},{%4,%5,%6,%7},{%8,%9},{%0,%1,%2,%3};"
        : "+f"(d0), "+f"(d1), "+f"(d2), "+f"(d3)
        : "r"(a0), "r"(a1), "r"(a2), "r"(a3), "r"(b0), "r"(b1));
}

__device__ __forceinline__ void ldsm_x4(uint32_t& r0, uint32_t& r1,
                                        uint32_t& r2, uint32_t& r3, uint32_t a)
{
    asm volatile("ldmatrix.sync.aligned.m8n8.x4.shared.b16 {%0,%1,%2,%3}, [%4];"
                 : "=r"(r0), "=r"(r1), "=r"(r2), "=r"(r3) : "r"(a));
}

__device__ __forceinline__ void ldsm_x4_t(uint32_t& r0, uint32_t& r1,
                                          uint32_t& r2, uint32_t& r3, uint32_t a)
{
    asm volatile("ldmatrix.sync.aligned.m8n8.x4.trans.shared.b16 {%0,%1,%2,%3}, [%4];"
                 : "=r"(r0), "=r"(r1), "=r"(r2), "=r"(r3) : "r"(a));
}

__device__ __forceinline__ uint32_t smem_u32(const void* p) {
    uint32_t a;
    asm("{ .reg .u64 t; cvta.to.shared.u64 t, %1; cvt.u32.u64 %0, t; }"
        : "=r"(a) : "l"(p));
    return a;
}

#define CP_ASYNC16(dst, src) \
    asm volatile("cp.async.cg.shared.global [%0], [%1], 16;" \
                 :: "r"(dst), "l"(src) : "memory")
#define CP_COMMIT() asm volatile("cp.async.commit_group;" ::: "memory")
#define CP_WAIT(n)  asm volatile("cp.async.wait_group %0;" :: "n"(n) : "memory")

// ---------------------------------------------------------------------------
// Split-bf16 GEMM: C[M,N] = (Ah+Al)[M,K] @ (Bh+Bl)[N,K]^T
// CTA 128x128, KTILE=32, 256 thr / 8 warps (32x64 warp tile), 2-stage cp.async,
// ldmatrix fragment loads, 2 CTAs/SM. D = hh + hl + lh (ll dropped).
// ---------------------------------------------------------------------------
#define MM_SMEM_BYTES (2 * 4 * 128 * 40 * 2)   // 81920
#define MM_TILE_B (128 * 80)                   // 10240 bytes per tile

__global__ __launch_bounds__(256, 2) void mm_gemm(
    const __nv_bfloat16* __restrict__ Ah, const __nv_bfloat16* __restrict__ Al,
    const __nv_bfloat16* __restrict__ Bh, const __nv_bfloat16* __restrict__ Bl,
    float* __restrict__ Cout, int K, int ldc)
{
    extern __shared__ __nv_bfloat16 smd[];   // [stage][tile][128][40]

    const int tid  = threadIdx.x;
    const int wid  = tid >> 5;
    const int lane = tid & 31;
    const int g8   = lane >> 2;
    const int t4   = lane & 3;
    const int m0   = blockIdx.y * 128;
    const int n0   = blockIdx.x * 128;
    const int ms   = wid & 3;
    const int ws   = wid >> 2;

    // ldmatrix per-lane address components (same pattern for A and B frags)
    const int lrow  = (lane & 7) + ((lane >> 3) & 1) * 8;
    const int lcol8 = (lane >> 4) * 8;

    const __nv_bfloat16* srcs[4] = {
        Ah + (size_t)m0 * K, Al + (size_t)m0 * K,
        Bh + (size_t)n0 * K, Bl + (size_t)n0 * K };

    const int f_row = tid >> 2;
    const int f_ch  = tid & 3;

    auto issue_stage = [&](int s, int st) {
        const int k0 = s << 5;
        #pragma unroll
        for (int t = 0; t < 8; ++t) {
            const int tl  = t >> 1;
            const int row = ((t & 1) << 6) + f_row;
            const __nv_bfloat16* src = srcs[tl] + (size_t)row * K + k0 + f_ch * 8;
            const uint32_t dst = smem_u32(
                smd + ((size_t)((st * 4 + tl) * 128 + row)) * 40 + f_ch * 8);
            CP_ASYNC16(dst, src);
        }
        CP_COMMIT();
    };

    float acc[2][8][4];
    #pragma unroll
    for (int mf = 0; mf < 2; mf++)
        #pragma unroll
        for (int nf = 0; nf < 8; nf++)
            #pragma unroll
            for (int i = 0; i < 4; i++) acc[mf][nf][i] = 0.f;

    const uint32_t smb0 = smem_u32(smd);
    const int nst = K >> 5;
    issue_stage(0, 0);

    for (int s = 0; s < nst; ++s) {
        const int st = s & 1;
        if (s + 1 < nst) { issue_stage(s + 1, (s + 1) & 1); CP_WAIT(1); }
        else             { CP_WAIT(0); }
        __syncthreads();

        const uint32_t smb = smb0 + (uint32_t)st * 4 * MM_TILE_B;

        #pragma unroll
        for (int ks = 0; ks < 2; ++ks) {
            const uint32_t colb = (uint32_t)((ks * 16 + lcol8) * 2);

            uint32_t ah[2][4], al[2][4];
            #pragma unroll
            for (int mf = 0; mf < 2; ++mf) {
                const uint32_t r = (uint32_t)(ms * 32 + mf * 16 + lrow) * 80 + colb;
                ldsm_x4(ah[mf][0], ah[mf][1], ah[mf][2], ah[mf][3],
                        smb + 0 * MM_TILE_B + r);
                ldsm_x4(al[mf][0], al[mf][1], al[mf][2], al[mf][3],
                        smb + 1 * MM_TILE_B + r);
            }

            #pragma unroll
            for (int np = 0; np < 4; ++np) {
                const uint32_t nr = (uint32_t)(ws * 64 + np * 16 + lrow) * 80 + colb;
                uint32_t bh[4], bl[4];
                ldsm_x4(bh[0], bh[1], bh[2], bh[3], smb + 2 * MM_TILE_B + nr);
                ldsm_x4(bl[0], bl[1], bl[2], bl[3], smb + 3 * MM_TILE_B + nr);
                #pragma unroll
                for (int e = 0; e < 2; ++e) {
                    const int nf = np * 2 + e;
                    const uint32_t bh0 = bh[e], bh1 = bh[2 + e];
                    const uint32_t bl0 = bl[e], bl1 = bl[2 + e];
                    #pragma unroll
                    for (int mf = 0; mf < 2; ++mf) {
                        float* d = acc[mf][nf];
                        mma_bf16(d[0], d[1], d[2], d[3],
                                 ah[mf][0], ah[mf][1], ah[mf][2], ah[mf][3],
                                 bh0, bh1);
                        mma_bf16(d[0], d[1], d[2], d[3],
                                 ah[mf][0], ah[mf][1], ah[mf][2], ah[mf][3],
                                 bl0, bl1);
                        mma_bf16(d[0], d[1], d[2], d[3],
                                 al[mf][0], al[mf][1], al[mf][2], al[mf][3],
                                 bh0, bh1);
                    }
                }
            }
        }
        __syncthreads();
    }

    #pragma unroll
    for (int mf = 0; mf < 2; ++mf) {
        const int r = m0 + ms * 32 + mf * 16 + g8;
        #pragma unroll
        for (int nf = 0; nf < 8; ++nf) {
            const int c = n0 + ws * 64 + nf * 8 + 2 * t4;
            *(float2*)(Cout + (size_t)r * ldc + c) =
                make_float2(acc[mf][nf][0], acc[mf][nf][1]);
            *(float2*)(Cout + (size_t)(r + 8) * ldc + c) =
                make_float2(acc[mf][nf][2], acc[mf][nf][3]);
        }
    }
}

// ---------------------------------------------------------------------------
// Conversion / packing kernels
// ---------------------------------------------------------------------------
__global__ void cvt_split(const float* __restrict__ in,
                          __nv_bfloat16* __restrict__ hi,
                          __nv_bfloat16* __restrict__ lo, int n)
{
    const int i = blockIdx.x * blockDim.x + threadIdx.x;
    if (i >= n) return;
    const float x = in[i];
    const __nv_bfloat16 h = __float2bfloat16(x);
    hi[i] = h;
    lo[i] = __float2bfloat16(x - __bfloat162float(h));
}

// Coalesced W^T pack: tiled 32x32 transpose, split to bf16 hi/lo.
// grid (C_/32, NQKV/32), block (32, 8).
__global__ void pack_wt_t(const float* __restrict__ Wq,
                          const float* __restrict__ Wk,
                          const float* __restrict__ Wv)
{
    __shared__ float tile[32][33];
    const int tx = threadIdx.x, ty = threadIdx.y;
    const int k0 = blockIdx.x * 32;
    const int n0 = blockIdx.y * 32;

    const float* W; int nw, noff;
    if (n0 < KOFF)      { W = Wq; nw = H_*DQK_; noff = n0; }
    else if (n0 < VOFF) { W = Wk; nw = G_*DQK_; noff = n0 - KOFF; }
    else                { W = Wv; nw = G_*DV_;  noff = n0 - VOFF; }

    #pragma unroll
    for (int j = 0; j < 4; ++j)
        tile[ty + j * 8][tx] = W[(size_t)(k0 + ty + j * 8) * nw + noff + tx];
    __syncthreads();
    #pragma unroll
    for (int j = 0; j < 4; ++j) {
        const float v = tile[tx][ty + j * 8];
        const __nv_bfloat16 h = __float2bfloat16(v);
        const size_t o = (size_t)(n0 + ty + j * 8) * C_ + k0 + tx;
        g_wth[o] = h;
        g_wtl[o] = __float2bfloat16(v - __bfloat162float(h));
    }
}

__global__ void pack_pt(const float* __restrict__ Wp)
{
    const int i = blockIdx.x * blockDim.x + threadIdx.x;
    if (i >= C_ * DV_) return;
    const int nn = i / DV_;
    const int k  = i % DV_;
    const float v = Wp[(size_t)k * C_ + nn];
    const __nv_bfloat16 h = __float2bfloat16(v);
    g_pth[i] = h;
    g_ptl[i] = __float2bfloat16(v - __bfloat162float(h));
}

// V region: fp32 -> fp16 copy into g_qkvh
__global__ void cvt_vh()
{
    const int i = blockIdx.x * blockDim.x + threadIdx.x;
    if (i >= NT_ * (G_ * DV_)) return;
    const int token = i >> 9;
    const int idx   = i & 511;
    const size_t off = (size_t)token * NQKV + VOFF + idx;
    g_qkvh[off] = __float2half(g_qkv[off]);
}

// Head-sum + bf16 split of attention output -> proj GEMM inputs
__global__ void sum_split_y()
{
    const int i = blockIdx.x * blockDim.x + threadIdx.x;
    if (i >= NT_ * DV_) return;
    float s = 0.f;
    #pragma unroll
    for (int h = 0; h < H_; ++h) s += g_yp[(size_t)h * NT_ * DV_ + i];
    const __nv_bfloat16 hi = __float2bfloat16(s);
    g_yh[i] = hi;
    g_yl[i] = __float2bfloat16(s - __bfloat162float(hi));
}

// ---------------------------------------------------------------------------
// RoPE + L2-norm; q scale folded with log2e (attention runs in exp2 domain).
// ---------------------------------------------------------------------------
__global__ void rope_norm_kernel(const float* __restrict__ qnf)
{
    const int warp = (blockIdx.x * blockDim.x + threadIdx.x) >> 5;
    const int lane = threadIdx.x & 31;
    if (warp >= NT_ * 20) return;
    const int token = warp / 20;
    const int slot  = warp % 20;
    const int t     = token & (T_ - 1);

    const size_t off = (size_t)token * NQKV
                     + ((slot < 16) ? slot * DQK_ : KOFF + (slot - 16) * DQK_);
    const float* src = g_qkv + off;
    __half* dst = g_qkvh + off;

    const float x0 = src[lane];
    const float x1 = src[lane + 32];

    const float inv = __expf(-(float)lane * 0.28782313662425574f); // ln(1e4)/32
    const float ang = (float)t * inv;
    float s, c;
    sincosf(ang, &s, &c);

    const float r0 = x0 * c - x1 * s;
    const float r1 = x1 * c + x0 * s;

    float ss = r0 * r0 + r1 * r1;
    #pragma unroll
    for (int o = 16; o > 0; o >>= 1) ss += __shfl_xor_sync(0xFFFFFFFFu, ss, o);

    float scale = 1.f / (sqrtf(ss) + 1e-6f);
    if (slot < 16) scale *= qnf[0] * LOG2E_;   // logit scale + base-2 domain

    dst[lane]      = __float2half(r0 * scale);
    dst[lane + 32] = __float2half(r1 * scale);
}

// ---------------------------------------------------------------------------
// Flash attention, FA2 register softmax (exp2 domain), cp.async double-buffered
// K/V, ldmatrix fragment loads. 256 thr / 8 warps; Q-tile 128, K-tile 64.
// ---------------------------------------------------------------------------
struct AttnSmem {
    __half Qs[128][72];       // 144B rows
    __half Ks[2][64][72];     // [key][dim], 144B rows
    __half Vs[2][64][136];    // [key][dim], 272B rows
};
#define ATTN_SMEM ((int)sizeof(AttnSmem))

__global__ __launch_bounds__(256) void attn_kernel(const float* __restrict__ lobo)
{
    extern __shared__ char smem_raw[];
    AttnSmem& S = *reinterpret_cast<AttnSmem*>(smem_raw);

    const int tid  = threadIdx.x;
    const int wid  = tid >> 5;
    const int lane = tid & 31;
    const int g8   = lane >> 2;
    const int t4   = lane & 3;

    const int qt = (gridDim.x - 1 - blockIdx.x);  // long blocks first
    const int h  = blockIdx.y;
    const int b  = blockIdx.z;
    const int gq = h >> 2;
    const int q0 = qt * 128;
    const size_t tokbase = (size_t)b * T_;

    const int krow  = lane & 7;               // K frags (x4, non-trans)
    const int kcol8 = (lane >> 3) * 8;
    const int vrow  = (lane & 7) + ((lane >> 3) & 1) * 8;   // V frags (x4 trans)
    const int vcol8 = (lane >> 4) * 8;

    // Fill Q tile (128 x 64 halves)
    #pragma unroll
    for (int i = 0; i < 16; ++i) {
        const int cid = tid + i * 256;
        const int row = cid >> 5;
        const int dp  = cid & 31;
        const uint32_t v = *(const uint32_t*)
            (g_qkvh + (tokbase + q0 + row) * NQKV + h * DQK_ + 2 * dp);
        *(uint32_t*)&S.Qs[row][2 * dp] = v;
    }

    const int rbase = (wid << 4);
    const int rg0 = q0 + rbase + g8;
    const int rg1 = rg0 + 8;

    float m0 = lobo[h] * LOG2E_, m1 = m0;   // base-2 domain
    float l0 = 1.f, l1 = 1.f;
    float o[16][4];
    #pragma unroll
    for (int nf = 0; nf < 16; nf++)
        #pragma unroll
        for (int i = 0; i < 4; i++) o[nf][i] = 0.f;

    uint32_t qf[4][4];

    const int nkt = (qt + 1) * 2;

    auto issue_kv = [&](int kt) {
        const int st = kt & 1;
        const int k0 = kt * 64;
        #pragma unroll
        for (int j = 0; j < 2; ++j) {       // K: 64 rows x 128B
            const int idx = tid + j * 256;
            const int row = idx >> 3, c = idx & 7;
            CP_ASYNC16(smem_u32(&S.Ks[st][row][c * 8]),
                g_qkvh + (tokbase + k0 + row) * NQKV + KOFF + gq * DQK_ + c * 8);
        }
        #pragma unroll
        for (int j = 0; j < 4; ++j) {       // V: 64 rows x 256B
            const int idx = tid + j * 256;
            const int row = idx >> 4, c = idx & 15;
            CP_ASYNC16(smem_u32(&S.Vs[st][row][c * 8]),
                g_qkvh + (tokbase + k0 + row) * NQKV + VOFF + gq * DV_ + c * 8);
        }
        CP_COMMIT();
    };

    issue_kv(0);
    issue_kv(1);

    for (int kt = 0; kt < nkt; ++kt) {
        const int st = kt & 1;
        if (kt + 1 < nkt) CP_WAIT(1);
        else              CP_WAIT(0);
        __syncthreads();

        if (kt == 0) {
            #pragma unroll
            for (int kf = 0; kf < 4; ++kf) {
                const int cb = kf * 16 + 2 * t4;
                qf[kf][0] = *(const uint32_t*)&S.Qs[rbase + g8    ][cb];
                qf[kf][1] = *(const uint32_t*)&S.Qs[rbase + g8 + 8][cb];
                qf[kf][2] = *(const uint32_t*)&S.Qs[rbase + g8    ][cb + 8];
                qf[kf][3] = *(const uint32_t*)&S.Qs[rbase + g8 + 8][cb + 8];
            }
        }

        // --- S = Q K^T, K frags via ldmatrix.x4 ---
        float s[8][4];
        #pragma unroll
        for (int nf = 0; nf < 8; nf++)
            #pragma unroll
            for (int i = 0; i < 4; i++) s[nf][i] = 0.f;

        const uint32_t ksb = smem_u32(&S.Ks[st][0][0]);
        #pragma unroll
        for (int kp = 0; kp < 2; ++kp) {
            #pragma unroll
            for (int nf = 0; nf < 8; ++nf) {
                uint32_t b0a, b1a, b0b, b1b;
                ldsm_x4(b0a, b1a, b0b, b1b,
                        ksb + (uint32_t)(((nf * 8 + krow) * 72
                                          + kp * 32 + kcol8) * 2));
                mma_f16(s[nf][0], s[nf][1], s[nf][2], s[nf][3],
                        qf[2*kp][0], qf[2*kp][1], qf[2*kp][2], qf[2*kp][3],
                        b0a, b1a);
                mma_f16(s[nf][0], s[nf][1], s[nf][2], s[nf][3],
                        qf[2*kp+1][0], qf[2*kp+1][1], qf[2*kp+1][2], qf[2*kp+1][3],
                        b0b, b1b);
            }
        }

        if (kt >= nkt - 2) {
            const int k0 = kt * 64;
            #pragma unroll
            for (int nf = 0; nf < 8; ++nf) {
                const int c = k0 + nf * 8 + 2 * t4;
                if (c     > rg0) s[nf][0] = -1e30f;
                if (c + 1 > rg0) s[nf][1] = -1e30f;
                if (c     > rg1) s[nf][2] = -1e30f;
                if (c + 1 > rg1) s[nf][3] = -1e30f;
            }
        }

        float mx0 = -1e30f, mx1 = -1e30f;
        #pragma unroll
        for (int nf = 0; nf < 8; ++nf) {
            mx0 = fmaxf(mx0, fmaxf(s[nf][0], s[nf][1]));
            mx1 = fmaxf(mx1, fmaxf(s[nf][2], s[nf][3]));
        }
        mx0 = fmaxf(mx0, __shfl_xor_sync(0xFFFFFFFFu, mx0, 1));
        mx0 = fmaxf(mx0, __shfl_xor_sync(0xFFFFFFFFu, mx0, 2));
        mx1 = fmaxf(mx1, __shfl_xor_sync(0xFFFFFFFFu, mx1, 1));
        mx1 = fmaxf(mx1, __shfl_xor_sync(0xFFFFFFFFu, mx1, 2));

        const float mn0 = fmaxf(m0, mx0);
        const float mn1 = fmaxf(m1, mx1);
        const float cr0 = exp2f(m0 - mn0);
        const float cr1 = exp2f(m1 - mn1);
        m0 = mn0; m1 = mn1;

        uint32_t pa[8], pb[8];
        float sum0 = 0.f, sum1 = 0.f;
        #pragma unroll
        for (int nf = 0; nf < 8; ++nf) {
            const float p0 = exp2f(s[nf][0] - mn0);
            const float p1 = exp2f(s[nf][1] - mn0);
            const float p2 = exp2f(s[nf][2] - mn1);
            const float p3 = exp2f(s[nf][3] - mn1);
            sum0 += p0 + p1;
            sum1 += p2 + p3;
            const __half2 ha = __floats2half2_rn(p0, p1);
            const __half2 hb = __floats2half2_rn(p2, p3);
            pa[nf] = *(const uint32_t*)&ha;
            pb[nf] = *(const uint32_t*)&hb;
        }
        sum0 += __shfl_xor_sync(0xFFFFFFFFu, sum0, 1);
        sum0 += __shfl_xor_sync(0xFFFFFFFFu, sum0, 2);
        sum1 += __shfl_xor_sync(0xFFFFFFFFu, sum1, 1);
        sum1 += __shfl_xor_sync(0xFFFFFFFFu, sum1, 2);
        l0 = l0 * cr0 + sum0;
        l1 = l1 * cr1 + sum1;

        #pragma unroll
        for (int nf = 0; nf < 16; ++nf) {
            o[nf][0] *= cr0; o[nf][1] *= cr0;
            o[nf][2] *= cr1; o[nf][3] *= cr1;
        }
        const uint32_t vsb = smem_u32(&S.Vs[st][0][0]);
        #pragma unroll
        for (int kf = 0; kf < 4; ++kf) {
            const uint32_t a0 = pa[2 * kf];
            const uint32_t a1 = pb[2 * kf];
            const uint32_t a2 = pa[2 * kf + 1];
            const uint32_t a3 = pb[2 * kf + 1];
            #pragma unroll
            for (int np = 0; np < 8; ++np) {
                uint32_t b0, b1, b2, b3;
                ldsm_x4_t(b0, b1, b2, b3,
                          vsb + (uint32_t)(((kf * 16 + vrow) * 136
                                            + np * 16 + vcol8) * 2));
                mma_f16(o[2*np][0], o[2*np][1], o[2*np][2], o[2*np][3],
                        a0, a1, a2, a3, b0, b1);
                mma_f16(o[2*np+1][0], o[2*np+1][1], o[2*np+1][2], o[2*np+1][3],
                        a0, a1, a2, a3, b2, b3);
            }
        }

        __syncthreads();
        if (kt + 2 < nkt) issue_kv(kt + 2);
    }

    {
        const float inv0 = 1.f / l0;
        const float inv1 = 1.f / l1;
        float* dst0 = g_yp + ((size_t)h * NT_ + tokbase + rg0) * DV_;
        float* dst1 = g_yp + ((size_t)h * NT_ + tokbase + rg1) * DV_;
        #pragma unroll
        for (int nf = 0; nf < 16; ++nf) {
            const int c = nf * 8 + 2 * t4;
            *(float2*)(dst0 + c) = make_float2(o[nf][0] * inv0, o[nf][1] * inv0);
            *(float2*)(dst1 + c) = make_float2(o[nf][2] * inv1, o[nf][3] * inv1);
        }
    }
}

// ---------------------------------------------------------------------------
// Launch
// ---------------------------------------------------------------------------
extern "C" void kernel_launch(void* const* d_in, const int* in_sizes, int n_in,
                              void* d_out, int out_size)
{
    const float* x     = (const float*)d_in[0];
    // d_in[1] = iter_num (unused)
    const float* Wq    = (const float*)d_in[2];
    const float* Wk    = (const float*)d_in[3];
    const float* Wv    = (const float*)d_in[4];
    const float* Wproj = (const float*)d_in[5];
    const float* lobo  = (const float*)d_in[6];
    const float* qnf   = (const float*)d_in[7];
    float* out = (float*)d_out;

    __nv_bfloat16 *xh, *xl, *wth, *wtl, *yh, *yl, *pth, *ptl;
    float *qkv_ptr;
    cudaGetSymbolAddress((void**)&xh, g_xh);
    cudaGetSymbolAddress((void**)&xl, g_xl);
    cudaGetSymbolAddress((void**)&wth, g_wth);
    cudaGetSymbolAddress((void**)&wtl, g_wtl);
    cudaGetSymbolAddress((void**)&yh, g_yh);
    cudaGetSymbolAddress((void**)&yl, g_yl);
    cudaGetSymbolAddress((void**)&pth, g_pth);
    cudaGetSymbolAddress((void**)&ptl, g_ptl);
    cudaGetSymbolAddress((void**)&qkv_ptr, g_qkv);

    cudaFuncSetAttribute(mm_gemm, cudaFuncAttributeMaxDynamicSharedMemorySize,
                         MM_SMEM_BYTES);
    cudaFuncSetAttribute(attn_kernel, cudaFuncAttributeMaxDynamicSharedMemorySize,
                         ATTN_SMEM);

    // Pack/convert inputs to split-bf16
    pack_wt_t<<<dim3(C_ / 32, NQKV / 32), dim3(32, 8)>>>(Wq, Wk, Wv);
    pack_pt<<<(C_ * DV_ + 255) / 256, 256>>>(Wproj);
    cvt_split<<<(NT_ * C_ + 255) / 256, 256>>>(x, xh, xl, NT_ * C_);

    // Fused QKV projection: [4096,1024] x [1792,1024]^T -> g_qkv (fp32)
    mm_gemm<<<dim3(NQKV / 128, NT_ / 128), 256, MM_SMEM_BYTES>>>(
        xh, xl, wth, wtl, qkv_ptr, C_, NQKV);

    // RoPE + qk-norm + logit scale (base-2) -> fp16 q/k; V -> fp16
    rope_norm_kernel<<<(NT_ * 20) / 8, 256>>>(qnf);
    cvt_vh<<<(NT_ * (G_ * DV_) + 255) / 256, 256>>>();

    // Attention (register-softmax FA2, cp.async, ldmatrix) -> per-head g_yp
    attn_kernel<<<dim3(T_ / 128, H_, B_), 256, ATTN_SMEM>>>(lobo);

    // Head-sum + split, then output projection
    sum_split_y<<<(NT_ * DV_ + 255) / 256, 256>>>();
    mm_gemm<<<dim3(C_ / 128, NT_ / 128), 256, MM_SMEM_BYTES>>>(
        yh, yl, pth, ptl, out, DV_, C_);
}

// round 9
// speedup vs baseline: 8.6679x; 1.1220x over previous
#include <cuda_runtime.h>
#include <cuda_bf16.h>
#include <cuda_fp16.h>
#include <math.h>
#include <stdint.h>

// Problem constants
#define B_   2
#define T_   2048
#define C_   1024
#define H_   16
#define G_   4
#define DQK_ 64
#define DV_  128
#define NT_  (B_ * T_)        // 4096 tokens
#define NQKV (H_*DQK_ + G_*DQK_ + G_*DV_)   // 1792
#define KOFF (H_*DQK_)        // 1024
#define VOFF (H_*DQK_ + G_*DQK_) // 1280
#define LOG2E_ 1.4426950408889634f

// ---------------------------------------------------------------------------
// Device scratch (no cudaMalloc allowed)
// ---------------------------------------------------------------------------
__device__ __nv_bfloat16 g_xh[(size_t)NT_ * C_];     // x split-bf16 hi
__device__ __nv_bfloat16 g_xl[(size_t)NT_ * C_];     // x split-bf16 lo
__device__ __nv_bfloat16 g_wth[(size_t)NQKV * C_];   // packed W^T [1792][1024] hi
__device__ __nv_bfloat16 g_wtl[(size_t)NQKV * C_];   // lo
__device__ __nv_bfloat16 g_yh[(size_t)NT_ * DV_];    // head-summed attn out hi
__device__ __nv_bfloat16 g_yl[(size_t)NT_ * DV_];    // lo
__device__ __nv_bfloat16 g_pth[(size_t)C_ * DV_];    // Wproj^T [1024][128] hi
__device__ __nv_bfloat16 g_ptl[(size_t)C_ * DV_];    // lo
__device__ float  g_qkv[(size_t)NT_ * NQKV];         // fused projection (fp32)
__device__ __half g_qkvh[(size_t)NT_ * NQKV];        // fp16 q(roped)/k(roped)/v
__device__ float  g_yp[(size_t)H_ * NT_ * DV_];      // per-head attn output

// ---------------------------------------------------------------------------
// mma.sync / ldmatrix / cp.async helpers (sm_80+ PTX; valid on compute_103)
// ---------------------------------------------------------------------------
__device__ __forceinline__ void mma_f16(float& d0, float& d1, float& d2, float& d3,
    uint32_t a0, uint32_t a1, uint32_t a2, uint32_t a3, uint32_t b0, uint32_t b1)
{
    asm volatile(
        "mma.sync.aligned.m16n8k16.row.col.f32.f16.f16.f32 "
        "{%0,%1,%2,%3},{%4,%5,%6,%7},{%8,%9},{%0,%1,%2,%3};"
        : "+f"(d0), "+f"(d1), "+f"(d2), "+f"(d3)
        : "r"(a0), "r"(a1), "r"(a2), "r"(a3), "r"(b0), "r"(b1));
}

__device__ __forceinline__ void mma_bf16(float& d0, float& d1, float& d2, float& d3,
    uint32_t a0, uint32_t a1, uint32_t a2, uint32_t a3, uint32_t b0, uint32_t b1)
{
    asm volatile(
        "mma.sync.aligned.m16n8k16.row.col.f32.bf16.bf16.f32 "
        "{%0,%1,%2,%3},{%4,%5,%6,%7},{%8,%9},{%0,%1,%2,%3};"
        : "+f"(d0), "+f"(d1), "+f"(d2), "+f"(d3)
        : "r"(a0), "r"(a1), "r"(a2), "r"(a3), "r"(b0), "r"(b1));
}

__device__ __forceinline__ void ldsm_x4(uint32_t& r0, uint32_t& r1,
                                        uint32_t& r2, uint32_t& r3, uint32_t a)
{
    asm volatile("ldmatrix.sync.aligned.m8n8.x4.shared.b16 {%0,%1,%2,%3}, [%4];"
                 : "=r"(r0), "=r"(r1), "=r"(r2), "=r"(r3) : "r"(a));
}

__device__ __forceinline__ void ldsm_x4_t(uint32_t& r0, uint32_t& r1,
                                          uint32_t& r2, uint32_t& r3, uint32_t a)
{
    asm volatile("ldmatrix.sync.aligned.m8n8.x4.trans.shared.b16 {%0,%1,%2,%3}, [%4];"
                 : "=r"(r0), "=r"(r1), "=r"(r2), "=r"(r3) : "r"(a));
}

__device__ __forceinline__ uint32_t smem_u32(const void* p) {
    uint32_t a;
    asm("{ .reg .u64 t; cvta.to.shared.u64 t, %1; cvt.u32.u64 %0, t; }"
        : "=r"(a) : "l"(p));
    return a;
}

#define CP_ASYNC16(dst, src) \
    asm volatile("cp.async.cg.shared.global [%0], [%1], 16;" \
                 :: "r"(dst), "l"(src) : "memory")
#define CP_COMMIT() asm volatile("cp.async.commit_group;" ::: "memory")
#define CP_WAIT(n)  asm volatile("cp.async.wait_group %0;" :: "n"(n) : "memory")

// ---------------------------------------------------------------------------
// Split-bf16 GEMM: C[M,N] = (Ah+Al)[M,K] @ (Bh+Bl)[N,K]^T
// CTA 128x128, KTILE=32, 256 thr / 8 warps (32x64 warp tile),
// 3-stage cp.async pipeline (ONE sync/stage), XOR-swizzled 64B rows
// (chunk ^= (row>>1)&3 -> conflict-free ldmatrix, 16B-aligned cp.async),
// 2 CTAs/SM. D = hh + hl + lh (ll dropped).
// ---------------------------------------------------------------------------
#define MM_TILE_B (128 * 64)                   // 8192 bytes per tile (no pad)
#define MM_STAGE_B (4 * MM_TILE_B)             // 32768 per stage
#define MM_SMEM_BYTES (3 * MM_STAGE_B)         // 98304

__global__ __launch_bounds__(256, 2) void mm_gemm(
    const __nv_bfloat16* __restrict__ Ah, const __nv_bfloat16* __restrict__ Al,
    const __nv_bfloat16* __restrict__ Bh, const __nv_bfloat16* __restrict__ Bl,
    float* __restrict__ Cout, int K, int ldc)
{
    extern __shared__ __nv_bfloat16 smd[];   // [3][4][128][32] swizzled

    const int tid  = threadIdx.x;
    const int wid  = tid >> 5;
    const int lane = tid & 31;
    const int g8   = lane >> 2;
    const int t4   = lane & 3;
    const int m0   = blockIdx.y * 128;
    const int n0   = blockIdx.x * 128;
    const int ms   = wid & 3;
    const int ws   = wid >> 2;

    const int lrow  = (lane & 7) + ((lane >> 3) & 1) * 8;
    const int lcol8 = (lane >> 4) * 8;

    const __nv_bfloat16* srcs[4] = {
        Ah + (size_t)m0 * K, Al + (size_t)m0 * K,
        Bh + (size_t)n0 * K, Bl + (size_t)n0 * K };

    const int f_row = tid >> 2;        // 0..63
    const int f_ch  = tid & 3;         // 16B chunk 0..3

    auto issue_stage = [&](int s, int st) {
        const int k0 = s << 5;
        #pragma unroll
        for (int t = 0; t < 8; ++t) {
            const int tl  = t >> 1;
            const int row = ((t & 1) << 6) + f_row;
            const int cs  = f_ch ^ ((row >> 1) & 3);        // swizzled chunk
            const __nv_bfloat16* src = srcs[tl] + (size_t)row * K + k0 + f_ch * 8;
            const uint32_t dst = smem_u32(
                smd + ((size_t)((st * 4 + tl) * 128 + row)) * 32 + cs * 8);
            CP_ASYNC16(dst, src);
        }
        CP_COMMIT();
    };

    float acc[2][8][4];
    #pragma unroll
    for (int mf = 0; mf < 2; mf++)
        #pragma unroll
        for (int nf = 0; nf < 8; nf++)
            #pragma unroll
            for (int i = 0; i < 4; i++) acc[mf][nf][i] = 0.f;

    const uint32_t smb0 = smem_u32(smd);
    const int nst = K >> 5;
    issue_stage(0, 0);
    if (nst > 1) issue_stage(1, 1);

    int st = 0;
    for (int s = 0; s < nst; ++s) {
        if (s + 1 < nst) CP_WAIT(1);
        else             CP_WAIT(0);
        __syncthreads();
        if (s + 2 < nst) {
            int st2 = st + 2; if (st2 >= 3) st2 -= 3;
            issue_stage(s + 2, st2);
        }

        const uint32_t smb = smb0 + (uint32_t)st * MM_STAGE_B;

        #pragma unroll
        for (int ks = 0; ks < 2; ++ks) {
            const int cb = ks * 2 + (lcol8 >> 3);    // chunk base 0..3

            uint32_t ah[2][4], al[2][4];
            #pragma unroll
            for (int mf = 0; mf < 2; ++mf) {
                const int row = ms * 32 + mf * 16 + lrow;
                const uint32_t off = (uint32_t)(row * 64
                                   + ((cb ^ ((row >> 1) & 3)) << 4));
                ldsm_x4(ah[mf][0], ah[mf][1], ah[mf][2], ah[mf][3],
                        smb + 0 * MM_TILE_B + off);
                ldsm_x4(al[mf][0], al[mf][1], al[mf][2], al[mf][3],
                        smb + 1 * MM_TILE_B + off);
            }

            #pragma unroll
            for (int np = 0; np < 4; ++np) {
                const int row = ws * 64 + np * 16 + lrow;
                const uint32_t off = (uint32_t)(row * 64
                                   + ((cb ^ ((row >> 1) & 3)) << 4));
                uint32_t bh[4], bl[4];
                ldsm_x4(bh[0], bh[1], bh[2], bh[3], smb + 2 * MM_TILE_B + off);
                ldsm_x4(bl[0], bl[1], bl[2], bl[3], smb + 3 * MM_TILE_B + off);
                #pragma unroll
                for (int e = 0; e < 2; ++e) {
                    const int nf = np * 2 + e;
                    const uint32_t bh0 = bh[e], bh1 = bh[2 + e];
                    const uint32_t bl0 = bl[e], bl1 = bl[2 + e];
                    #pragma unroll
                    for (int mf = 0; mf < 2; ++mf) {
                        float* d = acc[mf][nf];
                        mma_bf16(d[0], d[1], d[2], d[3],
                                 ah[mf][0], ah[mf][1], ah[mf][2], ah[mf][3],
                                 bh0, bh1);
                        mma_bf16(d[0], d[1], d[2], d[3],
                                 ah[mf][0], ah[mf][1], ah[mf][2], ah[mf][3],
                                 bl0, bl1);
                        mma_bf16(d[0], d[1], d[2], d[3],
                                 al[mf][0], al[mf][1], al[mf][2], al[mf][3],
                                 bh0, bh1);
                    }
                }
            }
        }
        if (++st >= 3) st -= 3;
    }

    #pragma unroll
    for (int mf = 0; mf < 2; ++mf) {
        const int r = m0 + ms * 32 + mf * 16 + g8;
        #pragma unroll
        for (int nf = 0; nf < 8; ++nf) {
            const int c = n0 + ws * 64 + nf * 8 + 2 * t4;
            *(float2*)(Cout + (size_t)r * ldc + c) =
                make_float2(acc[mf][nf][0], acc[mf][nf][1]);
            *(float2*)(Cout + (size_t)(r + 8) * ldc + c) =
                make_float2(acc[mf][nf][2], acc[mf][nf][3]);
        }
    }
}

// ---------------------------------------------------------------------------
// Conversion / packing kernels
// ---------------------------------------------------------------------------
__global__ void cvt_split(const float* __restrict__ in,
                          __nv_bfloat16* __restrict__ hi,
                          __nv_bfloat16* __restrict__ lo, int n)
{
    const int i = blockIdx.x * blockDim.x + threadIdx.x;
    if (i >= n) return;
    const float x = in[i];
    const __nv_bfloat16 h = __float2bfloat16(x);
    hi[i] = h;
    lo[i] = __float2bfloat16(x - __bfloat162float(h));
}

// Coalesced W^T pack: tiled 32x32 transpose, split to bf16 hi/lo.
__global__ void pack_wt_t(const float* __restrict__ Wq,
                          const float* __restrict__ Wk,
                          const float* __restrict__ Wv)
{
    __shared__ float tile[32][33];
    const int tx = threadIdx.x, ty = threadIdx.y;
    const int k0 = blockIdx.x * 32;
    const int n0 = blockIdx.y * 32;

    const float* W; int nw, noff;
    if (n0 < KOFF)      { W = Wq; nw = H_*DQK_; noff = n0; }
    else if (n0 < VOFF) { W = Wk; nw = G_*DQK_; noff = n0 - KOFF; }
    else                { W = Wv; nw = G_*DV_;  noff = n0 - VOFF; }

    #pragma unroll
    for (int j = 0; j < 4; ++j)
        tile[ty + j * 8][tx] = W[(size_t)(k0 + ty + j * 8) * nw + noff + tx];
    __syncthreads();
    #pragma unroll
    for (int j = 0; j < 4; ++j) {
        const float v = tile[tx][ty + j * 8];
        const __nv_bfloat16 h = __float2bfloat16(v);
        const size_t o = (size_t)(n0 + ty + j * 8) * C_ + k0 + tx;
        g_wth[o] = h;
        g_wtl[o] = __float2bfloat16(v - __bfloat162float(h));
    }
}

__global__ void pack_pt(const float* __restrict__ Wp)
{
    const int i = blockIdx.x * blockDim.x + threadIdx.x;
    if (i >= C_ * DV_) return;
    const int nn = i / DV_;
    const int k  = i % DV_;
    const float v = Wp[(size_t)k * C_ + nn];
    const __nv_bfloat16 h = __float2bfloat16(v);
    g_pth[i] = h;
    g_ptl[i] = __float2bfloat16(v - __bfloat162float(h));
}

// V region: fp32 -> fp16 copy into g_qkvh
__global__ void cvt_vh()
{
    const int i = blockIdx.x * blockDim.x + threadIdx.x;
    if (i >= NT_ * (G_ * DV_)) return;
    const int token = i >> 9;
    const int idx   = i & 511;
    const size_t off = (size_t)token * NQKV + VOFF + idx;
    g_qkvh[off] = __float2half(g_qkv[off]);
}

// Head-sum + bf16 split of attention output -> proj GEMM inputs
__global__ void sum_split_y()
{
    const int i = blockIdx.x * blockDim.x + threadIdx.x;
    if (i >= NT_ * DV_) return;
    float s = 0.f;
    #pragma unroll
    for (int h = 0; h < H_; ++h) s += g_yp[(size_t)h * NT_ * DV_ + i];
    const __nv_bfloat16 hi = __float2bfloat16(s);
    g_yh[i] = hi;
    g_yl[i] = __float2bfloat16(s - __bfloat162float(hi));
}

// ---------------------------------------------------------------------------
// RoPE + L2-norm; q scale folded with log2e (attention runs in exp2 domain).
// ---------------------------------------------------------------------------
__global__ void rope_norm_kernel(const float* __restrict__ qnf)
{
    const int warp = (blockIdx.x * blockDim.x + threadIdx.x) >> 5;
    const int lane = threadIdx.x & 31;
    if (warp >= NT_ * 20) return;
    const int token = warp / 20;
    const int slot  = warp % 20;
    const int t     = token & (T_ - 1);

    const size_t off = (size_t)token * NQKV
                     + ((slot < 16) ? slot * DQK_ : KOFF + (slot - 16) * DQK_);
    const float* src = g_qkv + off;
    __half* dst = g_qkvh + off;

    const float x0 = src[lane];
    const float x1 = src[lane + 32];

    const float inv = __expf(-(float)lane * 0.28782313662425574f); // ln(1e4)/32
    const float ang = (float)t * inv;
    float s, c;
    sincosf(ang, &s, &c);

    const float r0 = x0 * c - x1 * s;
    const float r1 = x1 * c + x0 * s;

    float ss = r0 * r0 + r1 * r1;
    #pragma unroll
    for (int o = 16; o > 0; o >>= 1) ss += __shfl_xor_sync(0xFFFFFFFFu, ss, o);

    float scale = 1.f / (sqrtf(ss) + 1e-6f);
    if (slot < 16) scale *= qnf[0] * LOG2E_;   // logit scale + base-2 domain

    dst[lane]      = __float2half(r0 * scale);
    dst[lane + 32] = __float2half(r1 * scale);
}

// ---------------------------------------------------------------------------
// Flash attention, FA2 register softmax (exp2 domain), cp.async double-buffered
// K/V, ldmatrix fragment loads. 128 thr / 4 warps; Q-tile 64, K-tile 64.
// 3 CTAs/SM for latency hiding.
// ---------------------------------------------------------------------------
struct AttnSmem {
    __half Qs[64][72];        // 144B rows (16B-aligned pitch)
    __half Ks[2][64][72];     // [key][dim]
    __half Vs[2][64][136];    // [key][dim], 272B rows
};
#define ATTN_SMEM ((int)sizeof(AttnSmem))

__global__ __launch_bounds__(128, 3) void attn_kernel(const float* __restrict__ lobo)
{
    extern __shared__ char smem_raw[];
    AttnSmem& S = *reinterpret_cast<AttnSmem*>(smem_raw);

    const int tid  = threadIdx.x;
    const int wid  = tid >> 5;
    const int lane = tid & 31;
    const int g8   = lane >> 2;
    const int t4   = lane & 3;

    const int qt = (gridDim.x - 1 - blockIdx.x);  // long blocks first
    const int h  = blockIdx.y;
    const int b  = blockIdx.z;
    const int gq = h >> 2;
    const int q0 = qt * 64;
    const size_t tokbase = (size_t)b * T_;

    const int krow  = lane & 7;               // K frags (x4, non-trans)
    const int kcol8 = (lane >> 3) * 8;
    const int vrow  = (lane & 7) + ((lane >> 3) & 1) * 8;   // V frags (x4 trans)
    const int vcol8 = (lane >> 4) * 8;

    // Fill Q tile (64 x 64 halves): 16 half2 per thread
    #pragma unroll
    for (int i = 0; i < 16; ++i) {
        const int cid = tid + i * 128;
        const int row = cid >> 5;
        const int dp  = cid & 31;
        const uint32_t v = *(const uint32_t*)
            (g_qkvh + (tokbase + q0 + row) * NQKV + h * DQK_ + 2 * dp);
        *(uint32_t*)&S.Qs[row][2 * dp] = v;
    }

    const int rbase = (wid << 4);
    const int rg0 = q0 + rbase + g8;
    const int rg1 = rg0 + 8;

    float m0 = lobo[h] * LOG2E_, m1 = m0;   // base-2 domain
    float l0 = 1.f, l1 = 1.f;
    float o[16][4];
    #pragma unroll
    for (int nf = 0; nf < 16; nf++)
        #pragma unroll
        for (int i = 0; i < 4; i++) o[nf][i] = 0.f;

    uint32_t qf[4][4];

    const int nkt = qt + 1;

    auto issue_kv = [&](int kt) {
        const int st = kt & 1;
        const int k0 = kt * 64;
        #pragma unroll
        for (int j = 0; j < 4; ++j) {       // K: 64 rows x 128B
            const int idx = tid + j * 128;
            const int row = idx >> 3, c = idx & 7;
            CP_ASYNC16(smem_u32(&S.Ks[st][row][c * 8]),
                g_qkvh + (tokbase + k0 + row) * NQKV + KOFF + gq * DQK_ + c * 8);
        }
        #pragma unroll
        for (int j = 0; j < 8; ++j) {       // V: 64 rows x 256B
            const int idx = tid + j * 128;
            const int row = idx >> 4, c = idx & 15;
            CP_ASYNC16(smem_u32(&S.Vs[st][row][c * 8]),
                g_qkvh + (tokbase + k0 + row) * NQKV + VOFF + gq * DV_ + c * 8);
        }
        CP_COMMIT();
    };

    issue_kv(0);
    if (nkt > 1) issue_kv(1);

    for (int kt = 0; kt < nkt; ++kt) {
        const int st = kt & 1;
        if (kt + 1 < nkt) CP_WAIT(1);
        else              CP_WAIT(0);
        __syncthreads();

        if (kt == 0) {
            #pragma unroll
            for (int kf = 0; kf < 4; ++kf) {
                const int cb = kf * 16 + 2 * t4;
                qf[kf][0] = *(const uint32_t*)&S.Qs[rbase + g8    ][cb];
                qf[kf][1] = *(const uint32_t*)&S.Qs[rbase + g8 + 8][cb];
                qf[kf][2] = *(const uint32_t*)&S.Qs[rbase + g8    ][cb + 8];
                qf[kf][3] = *(const uint32_t*)&S.Qs[rbase + g8 + 8][cb + 8];
            }
        }

        // --- S = Q K^T ---
        float s[8][4];
        #pragma unroll
        for (int nf = 0; nf < 8; nf++)
            #pragma unroll
            for (int i = 0; i < 4; i++) s[nf][i] = 0.f;

        const uint32_t ksb = smem_u32(&S.Ks[st][0][0]);
        #pragma unroll
        for (int kp = 0; kp < 2; ++kp) {
            #pragma unroll
            for (int nf = 0; nf < 8; ++nf) {
                uint32_t b0a, b1a, b0b, b1b;
                ldsm_x4(b0a, b1a, b0b, b1b,
                        ksb + (uint32_t)(((nf * 8 + krow) * 72
                                          + kp * 32 + kcol8) * 2));
                mma_f16(s[nf][0], s[nf][1], s[nf][2], s[nf][3],
                        qf[2*kp][0], qf[2*kp][1], qf[2*kp][2], qf[2*kp][3],
                        b0a, b1a);
                mma_f16(s[nf][0], s[nf][1], s[nf][2], s[nf][3],
                        qf[2*kp+1][0], qf[2*kp+1][1], qf[2*kp+1][2], qf[2*kp+1][3],
                        b0b, b1b);
            }
        }

        if (kt == nkt - 1) {   // diagonal tile
            const int k0 = kt * 64;
            #pragma unroll
            for (int nf = 0; nf < 8; ++nf) {
                const int c = k0 + nf * 8 + 2 * t4;
                if (c     > rg0) s[nf][0] = -1e30f;
                if (c + 1 > rg0) s[nf][1] = -1e30f;
                if (c     > rg1) s[nf][2] = -1e30f;
                if (c + 1 > rg1) s[nf][3] = -1e30f;
            }
        }

        float mx0 = -1e30f, mx1 = -1e30f;
        #pragma unroll
        for (int nf = 0; nf < 8; ++nf) {
            mx0 = fmaxf(mx0, fmaxf(s[nf][0], s[nf][1]));
            mx1 = fmaxf(mx1, fmaxf(s[nf][2], s[nf][3]));
        }
        mx0 = fmaxf(mx0, __shfl_xor_sync(0xFFFFFFFFu, mx0, 1));
        mx0 = fmaxf(mx0, __shfl_xor_sync(0xFFFFFFFFu, mx0, 2));
        mx1 = fmaxf(mx1, __shfl_xor_sync(0xFFFFFFFFu, mx1, 1));
        mx1 = fmaxf(mx1, __shfl_xor_sync(0xFFFFFFFFu, mx1, 2));

        const float mn0 = fmaxf(m0, mx0);
        const float mn1 = fmaxf(m1, mx1);
        const float cr0 = exp2f(m0 - mn0);
        const float cr1 = exp2f(m1 - mn1);
        m0 = mn0; m1 = mn1;

        uint32_t pa[8], pb[8];
        float sum0 = 0.f, sum1 = 0.f;
        #pragma unroll
        for (int nf = 0; nf < 8; ++nf) {
            const float p0 = exp2f(s[nf][0] - mn0);
            const float p1 = exp2f(s[nf][1] - mn0);
            const float p2 = exp2f(s[nf][2] - mn1);
            const float p3 = exp2f(s[nf][3] - mn1);
            sum0 += p0 + p1;
            sum1 += p2 + p3;
            const __half2 ha = __floats2half2_rn(p0, p1);
            const __half2 hb = __floats2half2_rn(p2, p3);
            pa[nf] = *(const uint32_t*)&ha;
            pb[nf] = *(const uint32_t*)&hb;
        }
        sum0 += __shfl_xor_sync(0xFFFFFFFFu, sum0, 1);
        sum0 += __shfl_xor_sync(0xFFFFFFFFu, sum0, 2);
        sum1 += __shfl_xor_sync(0xFFFFFFFFu, sum1, 1);
        sum1 += __shfl_xor_sync(0xFFFFFFFFu, sum1, 2);
        l0 = l0 * cr0 + sum0;
        l1 = l1 * cr1 + sum1;

        #pragma unroll
        for (int nf = 0; nf < 16; ++nf) {
            o[nf][0] *= cr0; o[nf][1] *= cr0;
            o[nf][2] *= cr1; o[nf][3] *= cr1;
        }
        const uint32_t vsb = smem_u32(&S.Vs[st][0][0]);
        #pragma unroll
        for (int kf = 0; kf < 4; ++kf) {
            const uint32_t a0 = pa[2 * kf];
            const uint32_t a1 = pb[2 * kf];
            const uint32_t a2 = pa[2 * kf + 1];
            const uint32_t a3 = pb[2 * kf + 1];
            #pragma unroll
            for (int np = 0; np < 8; ++np) {
                uint32_t b0, b1, b2, b3;
                ldsm_x4_t(b0, b1, b2, b3,
                          vsb + (uint32_t)(((kf * 16 + vrow) * 136
                                            + np * 16 + vcol8) * 2));
                mma_f16(o[2*np][0], o[2*np][1], o[2*np][2], o[2*np][3],
                        a0, a1, a2, a3, b0, b1);
                mma_f16(o[2*np+1][0], o[2*np+1][1], o[2*np+1][2], o[2*np+1][3],
                        a0, a1, a2, a3, b2, b3);
            }
        }

        __syncthreads();
        if (kt + 2 < nkt) issue_kv(kt + 2);
    }

    {
        const float inv0 = 1.f / l0;
        const float inv1 = 1.f / l1;
        float* dst0 = g_yp + ((size_t)h * NT_ + tokbase + rg0) * DV_;
        float* dst1 = g_yp + ((size_t)h * NT_ + tokbase + rg1) * DV_;
        #pragma unroll
        for (int nf = 0; nf < 16; ++nf) {
            const int c = nf * 8 + 2 * t4;
            *(float2*)(dst0 + c) = make_float2(o[nf][0] * inv0, o[nf][1] * inv0);
            *(float2*)(dst1 + c) = make_float2(o[nf][2] * inv1, o[nf][3] * inv1);
        }
    }
}

// ---------------------------------------------------------------------------
// Launch
// ---------------------------------------------------------------------------
extern "C" void kernel_launch(void* const* d_in, const int* in_sizes, int n_in,
                              void* d_out, int out_size)
{
    const float* x     = (const float*)d_in[0];
    // d_in[1] = iter_num (unused)
    const float* Wq    = (const float*)d_in[2];
    const float* Wk    = (const float*)d_in[3];
    const float* Wv    = (const float*)d_in[4];
    const float* Wproj = (const float*)d_in[5];
    const float* lobo  = (const float*)d_in[6];
    const float* qnf   = (const float*)d_in[7];
    float* out = (float*)d_out;

    __nv_bfloat16 *xh, *xl, *wth, *wtl, *yh, *yl, *pth, *ptl;
    float *qkv_ptr;
    cudaGetSymbolAddress((void**)&xh, g_xh);
    cudaGetSymbolAddress((void**)&xl, g_xl);
    cudaGetSymbolAddress((void**)&wth, g_wth);
    cudaGetSymbolAddress((void**)&wtl, g_wtl);
    cudaGetSymbolAddress((void**)&yh, g_yh);
    cudaGetSymbolAddress((void**)&yl, g_yl);
    cudaGetSymbolAddress((void**)&pth, g_pth);
    cudaGetSymbolAddress((void**)&ptl, g_ptl);
    cudaGetSymbolAddress((void**)&qkv_ptr, g_qkv);

    cudaFuncSetAttribute(mm_gemm, cudaFuncAttributeMaxDynamicSharedMemorySize,
                         MM_SMEM_BYTES);
    cudaFuncSetAttribute(attn_kernel, cudaFuncAttributeMaxDynamicSharedMemorySize,
                         ATTN_SMEM);

    // Pack/convert inputs to split-bf16
    pack_wt_t<<<dim3(C_ / 32, NQKV / 32), dim3(32, 8)>>>(Wq, Wk, Wv);
    pack_pt<<<(C_ * DV_ + 255) / 256, 256>>>(Wproj);
    cvt_split<<<(NT_ * C_ + 255) / 256, 256>>>(x, xh, xl, NT_ * C_);

    // Fused QKV projection: [4096,1024] x [1792,1024]^T -> g_qkv (fp32)
    mm_gemm<<<dim3(NQKV / 128, NT_ / 128), 256, MM_SMEM_BYTES>>>(
        xh, xl, wth, wtl, qkv_ptr, C_, NQKV);

    // RoPE + qk-norm + logit scale (base-2) -> fp16 q/k; V -> fp16
    rope_norm_kernel<<<(NT_ * 20) / 8, 256>>>(qnf);
    cvt_vh<<<(NT_ * (G_ * DV_) + 255) / 256, 256>>>();

    // Attention (register-softmax FA2, Q-tile 64, 3 CTAs/SM) -> per-head g_yp
    attn_kernel<<<dim3(T_ / 64, H_, B_), 128, ATTN_SMEM>>>(lobo);

    // Head-sum + split, then output projection
    sum_split_y<<<(NT_ * DV_ + 255) / 256, 256>>>();
    mm_gemm<<<dim3(C_ / 128, NT_ / 128), 256, MM_SMEM_BYTES>>>(
        yh, yl, pth, ptl, out, DV_, C_);
}

// round 10
// speedup vs baseline: 8.7651x; 1.0112x over previous
#include <cuda_runtime.h>
#include <cuda_bf16.h>
#include <cuda_fp16.h>
#include <math.h>
#include <stdint.h>

// Problem constants
#define B_   2
#define T_   2048
#define C_   1024
#define H_   16
#define G_   4
#define DQK_ 64
#define DV_  128
#define NT_  (B_ * T_)        // 4096 tokens
#define NQKV (H_*DQK_ + G_*DQK_ + G_*DV_)   // 1792
#define KOFF (H_*DQK_)        // 1024
#define VOFF (H_*DQK_ + G_*DQK_) // 1280
#define LOG2E_ 1.4426950408889634f

// ---------------------------------------------------------------------------
// Device scratch (no cudaMalloc allowed)
// ---------------------------------------------------------------------------
__device__ __nv_bfloat16 g_xh[(size_t)NT_ * C_];     // x split-bf16 hi
__device__ __nv_bfloat16 g_xl[(size_t)NT_ * C_];     // x split-bf16 lo
__device__ __nv_bfloat16 g_wth[(size_t)NQKV * C_];   // packed W^T [1792][1024] hi
__device__ __nv_bfloat16 g_wtl[(size_t)NQKV * C_];   // lo
__device__ __nv_bfloat16 g_yh[(size_t)NT_ * DV_];    // head-summed attn out hi
__device__ __nv_bfloat16 g_yl[(size_t)NT_ * DV_];    // lo
__device__ __nv_bfloat16 g_pth[(size_t)C_ * DV_];    // Wproj^T [1024][128] hi
__device__ __nv_bfloat16 g_ptl[(size_t)C_ * DV_];    // lo
__device__ float  g_qkv[(size_t)NT_ * NQKV];         // fused projection (fp32)
__device__ __half g_qkvh[(size_t)NT_ * NQKV];        // fp16 q(roped)/k(roped)/v
__device__ float  g_yp[(size_t)H_ * NT_ * DV_];      // per-head attn output
__device__ float2 g_rope[(size_t)T_ * 32];           // (cos,sin) per (t,lane)

// ---------------------------------------------------------------------------
// mma.sync / ldmatrix / cp.async helpers (sm_80+ PTX; valid on compute_103)
// ---------------------------------------------------------------------------
__device__ __forceinline__ void mma_f16(float& d0, float& d1, float& d2, float& d3,
    uint32_t a0, uint32_t a1, uint32_t a2, uint32_t a3, uint32_t b0, uint32_t b1)
{
    asm volatile(
        "mma.sync.aligned.m16n8k16.row.col.f32.f16.f16.f32 "
        "{%0,%1,%2,%3},{%4,%5,%6,%7},{%8,%9},{%0,%1,%2,%3};"
        : "+f"(d0), "+f"(d1), "+f"(d2), "+f"(d3)
        : "r"(a0), "r"(a1), "r"(a2), "r"(a3), "r"(b0), "r"(b1));
}

__device__ __forceinline__ void mma_bf16(float& d0, float& d1, float& d2, float& d3,
    uint32_t a0, uint32_t a1, uint32_t a2, uint32_t a3, uint32_t b0, uint32_t b1)
{
    asm volatile(
        "mma.sync.aligned.m16n8k16.row.col.f32.bf16.bf16.f32 "
        "{%0,%1,%2,%3},{%4,%5,%6,%7},{%8,%9},{%0,%1,%2,%3};"
        : "+f"(d0), "+f"(d1), "+f"(d2), "+f"(d3)
        : "r"(a0), "r"(a1), "r"(a2), "r"(a3), "r"(b0), "r"(b1));
}

__device__ __forceinline__ void ldsm_x4(uint32_t& r0, uint32_t& r1,
                                        uint32_t& r2, uint32_t& r3, uint32_t a)
{
    asm volatile("ldmatrix.sync.aligned.m8n8.x4.shared.b16 {%0,%1,%2,%3}, [%4];"
                 : "=r"(r0), "=r"(r1), "=r"(r2), "=r"(r3) : "r"(a));
}

__device__ __forceinline__ void ldsm_x4_t(uint32_t& r0, uint32_t& r1,
                                          uint32_t& r2, uint32_t& r3, uint32_t a)
{
    asm volatile("ldmatrix.sync.aligned.m8n8.x4.trans.shared.b16 {%0,%1,%2,%3}, [%4];"
                 : "=r"(r0), "=r"(r1), "=r"(r2), "=r"(r3) : "r"(a));
}

__device__ __forceinline__ uint32_t smem_u32(const void* p) {
    uint32_t a;
    asm("{ .reg .u64 t; cvta.to.shared.u64 t, %1; cvt.u32.u64 %0, t; }"
        : "=r"(a) : "l"(p));
    return a;
}

// pack (lo,hi) floats to f16x2 then exp2 in fp16 (MUFU.EX2 on both halves)
__device__ __forceinline__ uint32_t exp2_pack(float lo, float hi) {
    uint32_t r;
    asm("cvt.rn.f16x2.f32 %0, %1, %2;" : "=r"(r) : "f"(hi), "f"(lo));
    asm("ex2.approx.f16x2 %0, %0;" : "+r"(r));
    return r;
}

#define CP_ASYNC16(dst, src) \
    asm volatile("cp.async.cg.shared.global [%0], [%1], 16;" \
                 :: "r"(dst), "l"(src) : "memory")
#define CP_COMMIT() asm volatile("cp.async.commit_group;" ::: "memory")
#define CP_WAIT(n)  asm volatile("cp.async.wait_group %0;" :: "n"(n) : "memory")

// ---------------------------------------------------------------------------
// Split-bf16 GEMM (unchanged from round 9): 3-stage cp.async, XOR swizzle,
// one sync/stage, ldmatrix frags, 2 CTAs/SM. D = hh + hl + lh.
// ---------------------------------------------------------------------------
#define MM_TILE_B (128 * 64)
#define MM_STAGE_B (4 * MM_TILE_B)
#define MM_SMEM_BYTES (3 * MM_STAGE_B)         // 98304

__global__ __launch_bounds__(256, 2) void mm_gemm(
    const __nv_bfloat16* __restrict__ Ah, const __nv_bfloat16* __restrict__ Al,
    const __nv_bfloat16* __restrict__ Bh, const __nv_bfloat16* __restrict__ Bl,
    float* __restrict__ Cout, int K, int ldc)
{
    extern __shared__ __nv_bfloat16 smd[];

    const int tid  = threadIdx.x;
    const int wid  = tid >> 5;
    const int lane = tid & 31;
    const int g8   = lane >> 2;
    const int t4   = lane & 3;
    const int m0   = blockIdx.y * 128;
    const int n0   = blockIdx.x * 128;
    const int ms   = wid & 3;
    const int ws   = wid >> 2;

    const int lrow  = (lane & 7) + ((lane >> 3) & 1) * 8;
    const int lcol8 = (lane >> 4) * 8;

    const __nv_bfloat16* srcs[4] = {
        Ah + (size_t)m0 * K, Al + (size_t)m0 * K,
        Bh + (size_t)n0 * K, Bl + (size_t)n0 * K };

    const int f_row = tid >> 2;
    const int f_ch  = tid & 3;

    auto issue_stage = [&](int s, int st) {
        const int k0 = s << 5;
        #pragma unroll
        for (int t = 0; t < 8; ++t) {
            const int tl  = t >> 1;
            const int row = ((t & 1) << 6) + f_row;
            const int cs  = f_ch ^ ((row >> 1) & 3);
            const __nv_bfloat16* src = srcs[tl] + (size_t)row * K + k0 + f_ch * 8;
            const uint32_t dst = smem_u32(
                smd + ((size_t)((st * 4 + tl) * 128 + row)) * 32 + cs * 8);
            CP_ASYNC16(dst, src);
        }
        CP_COMMIT();
    };

    float acc[2][8][4];
    #pragma unroll
    for (int mf = 0; mf < 2; mf++)
        #pragma unroll
        for (int nf = 0; nf < 8; nf++)
            #pragma unroll
            for (int i = 0; i < 4; i++) acc[mf][nf][i] = 0.f;

    const uint32_t smb0 = smem_u32(smd);
    const int nst = K >> 5;
    issue_stage(0, 0);
    if (nst > 1) issue_stage(1, 1);

    int st = 0;
    for (int s = 0; s < nst; ++s) {
        if (s + 1 < nst) CP_WAIT(1);
        else             CP_WAIT(0);
        __syncthreads();
        if (s + 2 < nst) {
            int st2 = st + 2; if (st2 >= 3) st2 -= 3;
            issue_stage(s + 2, st2);
        }

        const uint32_t smb = smb0 + (uint32_t)st * MM_STAGE_B;

        #pragma unroll
        for (int ks = 0; ks < 2; ++ks) {
            const int cb = ks * 2 + (lcol8 >> 3);

            uint32_t ah[2][4], al[2][4];
            #pragma unroll
            for (int mf = 0; mf < 2; ++mf) {
                const int row = ms * 32 + mf * 16 + lrow;
                const uint32_t off = (uint32_t)(row * 64
                                   + ((cb ^ ((row >> 1) & 3)) << 4));
                ldsm_x4(ah[mf][0], ah[mf][1], ah[mf][2], ah[mf][3],
                        smb + 0 * MM_TILE_B + off);
                ldsm_x4(al[mf][0], al[mf][1], al[mf][2], al[mf][3],
                        smb + 1 * MM_TILE_B + off);
            }

            #pragma unroll
            for (int np = 0; np < 4; ++np) {
                const int row = ws * 64 + np * 16 + lrow;
                const uint32_t off = (uint32_t)(row * 64
                                   + ((cb ^ ((row >> 1) & 3)) << 4));
                uint32_t bh[4], bl[4];
                ldsm_x4(bh[0], bh[1], bh[2], bh[3], smb + 2 * MM_TILE_B + off);
                ldsm_x4(bl[0], bl[1], bl[2], bl[3], smb + 3 * MM_TILE_B + off);
                #pragma unroll
                for (int e = 0; e < 2; ++e) {
                    const int nf = np * 2 + e;
                    const uint32_t bh0 = bh[e], bh1 = bh[2 + e];
                    const uint32_t bl0 = bl[e], bl1 = bl[2 + e];
                    #pragma unroll
                    for (int mf = 0; mf < 2; ++mf) {
                        float* d = acc[mf][nf];
                        mma_bf16(d[0], d[1], d[2], d[3],
                                 ah[mf][0], ah[mf][1], ah[mf][2], ah[mf][3],
                                 bh0, bh1);
                        mma_bf16(d[0], d[1], d[2], d[3],
                                 ah[mf][0], ah[mf][1], ah[mf][2], ah[mf][3],
                                 bl0, bl1);
                        mma_bf16(d[0], d[1], d[2], d[3],
                                 al[mf][0], al[mf][1], al[mf][2], al[mf][3],
                                 bh0, bh1);
                    }
                }
            }
        }
        if (++st >= 3) st -= 3;
    }

    #pragma unroll
    for (int mf = 0; mf < 2; ++mf) {
        const int r = m0 + ms * 32 + mf * 16 + g8;
        #pragma unroll
        for (int nf = 0; nf < 8; ++nf) {
            const int c = n0 + ws * 64 + nf * 8 + 2 * t4;
            *(float2*)(Cout + (size_t)r * ldc + c) =
                make_float2(acc[mf][nf][0], acc[mf][nf][1]);
            *(float2*)(Cout + (size_t)(r + 8) * ldc + c) =
                make_float2(acc[mf][nf][2], acc[mf][nf][3]);
        }
    }
}

// ---------------------------------------------------------------------------
// Conversion / packing kernels
// ---------------------------------------------------------------------------
__global__ void cvt_split(const float* __restrict__ in,
                          __nv_bfloat16* __restrict__ hi,
                          __nv_bfloat16* __restrict__ lo, int n)
{
    const int i = blockIdx.x * blockDim.x + threadIdx.x;
    if (i >= n) return;
    const float x = in[i];
    const __nv_bfloat16 h = __float2bfloat16(x);
    hi[i] = h;
    lo[i] = __float2bfloat16(x - __bfloat162float(h));
}

__global__ void pack_wt_t(const float* __restrict__ Wq,
                          const float* __restrict__ Wk,
                          const float* __restrict__ Wv)
{
    __shared__ float tile[32][33];
    const int tx = threadIdx.x, ty = threadIdx.y;
    const int k0 = blockIdx.x * 32;
    const int n0 = blockIdx.y * 32;

    const float* W; int nw, noff;
    if (n0 < KOFF)      { W = Wq; nw = H_*DQK_; noff = n0; }
    else if (n0 < VOFF) { W = Wk; nw = G_*DQK_; noff = n0 - KOFF; }
    else                { W = Wv; nw = G_*DV_;  noff = n0 - VOFF; }

    #pragma unroll
    for (int j = 0; j < 4; ++j)
        tile[ty + j * 8][tx] = W[(size_t)(k0 + ty + j * 8) * nw + noff + tx];
    __syncthreads();
    #pragma unroll
    for (int j = 0; j < 4; ++j) {
        const float v = tile[tx][ty + j * 8];
        const __nv_bfloat16 h = __float2bfloat16(v);
        const size_t o = (size_t)(n0 + ty + j * 8) * C_ + k0 + tx;
        g_wth[o] = h;
        g_wtl[o] = __float2bfloat16(v - __bfloat162float(h));
    }
}

__global__ void pack_pt(const float* __restrict__ Wp)
{
    const int i = blockIdx.x * blockDim.x + threadIdx.x;
    if (i >= C_ * DV_) return;
    const int nn = i / DV_;
    const int k  = i % DV_;
    const float v = Wp[(size_t)k * C_ + nn];
    const __nv_bfloat16 h = __float2bfloat16(v);
    g_pth[i] = h;
    g_ptl[i] = __float2bfloat16(v - __bfloat162float(h));
}

__global__ void cvt_vh()
{
    const int i = blockIdx.x * blockDim.x + threadIdx.x;
    if (i >= NT_ * (G_ * DV_)) return;
    const int token = i >> 9;
    const int idx   = i & 511;
    const size_t off = (size_t)token * NQKV + VOFF + idx;
    g_qkvh[off] = __float2half(g_qkv[off]);
}

__global__ void sum_split_y()
{
    const int i = blockIdx.x * blockDim.x + threadIdx.x;
    if (i >= NT_ * DV_) return;
    float s = 0.f;
    #pragma unroll
    for (int h = 0; h < H_; ++h) s += g_yp[(size_t)h * NT_ * DV_ + i];
    const __nv_bfloat16 hi = __float2bfloat16(s);
    g_yh[i] = hi;
    g_yl[i] = __float2bfloat16(s - __bfloat162float(hi));
}

// ---------------------------------------------------------------------------
// RoPE table: one accurate sincosf per distinct (t, lane) pair.
// ---------------------------------------------------------------------------
__global__ void gen_rope()
{
    const int i = blockIdx.x * blockDim.x + threadIdx.x;
    if (i >= T_ * 32) return;
    const int t = i >> 5, lane = i & 31;
    const float inv = __expf(-(float)lane * 0.28782313662425574f); // ln(1e4)/32
    const float ang = (float)t * inv;
    float s, c;
    sincosf(ang, &s, &c);
    g_rope[i] = make_float2(c, s);
}

// RoPE + L2-norm; q scale folded with log2e (attention runs in exp2 domain).
__global__ void rope_norm_kernel(const float* __restrict__ qnf)
{
    const int warp = (blockIdx.x * blockDim.x + threadIdx.x) >> 5;
    const int lane = threadIdx.x & 31;
    if (warp >= NT_ * 20) return;
    const int token = warp / 20;
    const int slot  = warp % 20;
    const int t     = token & (T_ - 1);

    const size_t off = (size_t)token * NQKV
                     + ((slot < 16) ? slot * DQK_ : KOFF + (slot - 16) * DQK_);
    const float* src = g_qkv + off;
    __half* dst = g_qkvh + off;

    const float x0 = src[lane];
    const float x1 = src[lane + 32];

    const float2 cs = g_rope[(t << 5) + lane];
    const float c = cs.x, s = cs.y;

    const float r0 = x0 * c - x1 * s;
    const float r1 = x1 * c + x0 * s;

    float ss = r0 * r0 + r1 * r1;
    #pragma unroll
    for (int o = 16; o > 0; o >>= 1) ss += __shfl_xor_sync(0xFFFFFFFFu, ss, o);

    float scale = 1.f / (sqrtf(ss) + 1e-6f);
    if (slot < 16) scale *= qnf[0] * LOG2E_;   // logit scale + base-2 domain

    dst[lane]      = __float2half(r0 * scale);
    dst[lane + 32] = __float2half(r1 * scale);
}

// ---------------------------------------------------------------------------
// Flash attention, FA2 register softmax (exp2 domain, f16x2 MUFU path,
// ones-MMA row sums, ballot-gated rescale). 128 thr / 4 warps; Q-tile 64,
// K-tile 64, cp.async double-buffered K/V, 3 CTAs/SM.
// ---------------------------------------------------------------------------
struct AttnSmem {
    __half Qs[64][72];
    __half Ks[2][64][72];
    __half Vs[2][64][136];
};
#define ATTN_SMEM ((int)sizeof(AttnSmem))

__global__ __launch_bounds__(128, 3) void attn_kernel(const float* __restrict__ lobo)
{
    extern __shared__ char smem_raw[];
    AttnSmem& S = *reinterpret_cast<AttnSmem*>(smem_raw);

    const int tid  = threadIdx.x;
    const int wid  = tid >> 5;
    const int lane = tid & 31;
    const int g8   = lane >> 2;
    const int t4   = lane & 3;

    const int qt = (gridDim.x - 1 - blockIdx.x);  // long blocks first
    const int h  = blockIdx.y;
    const int b  = blockIdx.z;
    const int gq = h >> 2;
    const int q0 = qt * 64;
    const size_t tokbase = (size_t)b * T_;

    const int krow  = lane & 7;
    const int kcol8 = (lane >> 3) * 8;
    const int vrow  = (lane & 7) + ((lane >> 3) & 1) * 8;
    const int vcol8 = (lane >> 4) * 8;

    // Fill Q tile (64 x 64 halves)
    #pragma unroll
    for (int i = 0; i < 16; ++i) {
        const int cid = tid + i * 128;
        const int row = cid >> 5;
        const int dp  = cid & 31;
        const uint32_t v = *(const uint32_t*)
            (g_qkvh + (tokbase + q0 + row) * NQKV + h * DQK_ + 2 * dp);
        *(uint32_t*)&S.Qs[row][2 * dp] = v;
    }

    const int rbase = (wid << 4);
    const int rg0 = q0 + rbase + g8;
    const int rg1 = rg0 + 8;

    float m0 = lobo[h] * LOG2E_, m1 = m0;   // base-2 domain
    float l0 = 1.f, l1 = 1.f;
    float o[16][4];
    #pragma unroll
    for (int nf = 0; nf < 16; nf++)
        #pragma unroll
        for (int i = 0; i < 4; i++) o[nf][i] = 0.f;

    uint32_t qf[4][4];
    const uint32_t ONES = 0x3C003C00u;   // half2(1,1)

    const int nkt = qt + 1;

    auto issue_kv = [&](int kt) {
        const int st = kt & 1;
        const int k0 = kt * 64;
        #pragma unroll
        for (int j = 0; j < 4; ++j) {
            const int idx = tid + j * 128;
            const int row = idx >> 3, c = idx & 7;
            CP_ASYNC16(smem_u32(&S.Ks[st][row][c * 8]),
                g_qkvh + (tokbase + k0 + row) * NQKV + KOFF + gq * DQK_ + c * 8);
        }
        #pragma unroll
        for (int j = 0; j < 8; ++j) {
            const int idx = tid + j * 128;
            const int row = idx >> 4, c = idx & 15;
            CP_ASYNC16(smem_u32(&S.Vs[st][row][c * 8]),
                g_qkvh + (tokbase + k0 + row) * NQKV + VOFF + gq * DV_ + c * 8);
        }
        CP_COMMIT();
    };

    issue_kv(0);
    if (nkt > 1) issue_kv(1);

    for (int kt = 0; kt < nkt; ++kt) {
        const int st = kt & 1;
        if (kt + 1 < nkt) CP_WAIT(1);
        else              CP_WAIT(0);
        __syncthreads();

        if (kt == 0) {
            #pragma unroll
            for (int kf = 0; kf < 4; ++kf) {
                const int cb = kf * 16 + 2 * t4;
                qf[kf][0] = *(const uint32_t*)&S.Qs[rbase + g8    ][cb];
                qf[kf][1] = *(const uint32_t*)&S.Qs[rbase + g8 + 8][cb];
                qf[kf][2] = *(const uint32_t*)&S.Qs[rbase + g8    ][cb + 8];
                qf[kf][3] = *(const uint32_t*)&S.Qs[rbase + g8 + 8][cb + 8];
            }
        }

        // --- S = Q K^T ---
        float s[8][4];
        #pragma unroll
        for (int nf = 0; nf < 8; nf++)
            #pragma unroll
            for (int i = 0; i < 4; i++) s[nf][i] = 0.f;

        const uint32_t ksb = smem_u32(&S.Ks[st][0][0]);
        #pragma unroll
        for (int kp = 0; kp < 2; ++kp) {
            #pragma unroll
            for (int nf = 0; nf < 8; ++nf) {
                uint32_t b0a, b1a, b0b, b1b;
                ldsm_x4(b0a, b1a, b0b, b1b,
                        ksb + (uint32_t)(((nf * 8 + krow) * 72
                                          + kp * 32 + kcol8) * 2));
                mma_f16(s[nf][0], s[nf][1], s[nf][2], s[nf][3],
                        qf[2*kp][0], qf[2*kp][1], qf[2*kp][2], qf[2*kp][3],
                        b0a, b1a);
                mma_f16(s[nf][0], s[nf][1], s[nf][2], s[nf][3],
                        qf[2*kp+1][0], qf[2*kp+1][1], qf[2*kp+1][2], qf[2*kp+1][3],
                        b0b, b1b);
            }
        }

        if (kt == nkt - 1) {   // diagonal tile
            const int k0 = kt * 64;
            #pragma unroll
            for (int nf = 0; nf < 8; ++nf) {
                const int c = k0 + nf * 8 + 2 * t4;
                if (c     > rg0) s[nf][0] = -1e30f;
                if (c + 1 > rg0) s[nf][1] = -1e30f;
                if (c     > rg1) s[nf][2] = -1e30f;
                if (c + 1 > rg1) s[nf][3] = -1e30f;
            }
        }

        // Row max (registers + quad shuffles)
        float mx0 = -1e30f, mx1 = -1e30f;
        #pragma unroll
        for (int nf = 0; nf < 8; ++nf) {
            mx0 = fmaxf(mx0, fmaxf(s[nf][0], s[nf][1]));
            mx1 = fmaxf(mx1, fmaxf(s[nf][2], s[nf][3]));
        }
        mx0 = fmaxf(mx0, __shfl_xor_sync(0xFFFFFFFFu, mx0, 1));
        mx0 = fmaxf(mx0, __shfl_xor_sync(0xFFFFFFFFu, mx0, 2));
        mx1 = fmaxf(mx1, __shfl_xor_sync(0xFFFFFFFFu, mx1, 1));
        mx1 = fmaxf(mx1, __shfl_xor_sync(0xFFFFFFFFu, mx1, 2));

        const float mn0 = fmaxf(m0, mx0);
        const float mn1 = fmaxf(m1, mx1);
        const float cr0 = exp2f(m0 - mn0);
        const float cr1 = exp2f(m1 - mn1);
        m0 = mn0; m1 = mn1;

        // P = exp2(S - m) via packed fp16 MUFU
        uint32_t pa[8], pb[8];
        #pragma unroll
        for (int nf = 0; nf < 8; ++nf) {
            pa[nf] = exp2_pack(s[nf][0] - mn0, s[nf][1] - mn0);
            pb[nf] = exp2_pack(s[nf][2] - mn1, s[nf][3] - mn1);
        }

        // Row sums via ones-MMA (exact fp32, no shuffles)
        float sf0 = 0.f, sf1 = 0.f, sf2 = 0.f, sf3 = 0.f;
        #pragma unroll
        for (int kf = 0; kf < 4; ++kf)
            mma_f16(sf0, sf1, sf2, sf3,
                    pa[2*kf], pb[2*kf], pa[2*kf+1], pb[2*kf+1], ONES, ONES);
        l0 = l0 * cr0 + sf0;
        l1 = l1 * cr1 + sf2;

        // Rescale O only if any row's max moved (warp-uniform branch)
        if (__ballot_sync(0xFFFFFFFFu, (cr0 < 1.f) || (cr1 < 1.f))) {
            #pragma unroll
            for (int nf = 0; nf < 16; ++nf) {
                o[nf][0] *= cr0; o[nf][1] *= cr0;
                o[nf][2] *= cr1; o[nf][3] *= cr1;
            }
        }

        // O += P V
        const uint32_t vsb = smem_u32(&S.Vs[st][0][0]);
        #pragma unroll
        for (int kf = 0; kf < 4; ++kf) {
            const uint32_t a0 = pa[2 * kf];
            const uint32_t a1 = pb[2 * kf];
            const uint32_t a2 = pa[2 * kf + 1];
            const uint32_t a3 = pb[2 * kf + 1];
            #pragma unroll
            for (int np = 0; np < 8; ++np) {
                uint32_t b0, b1, b2, b3;
                ldsm_x4_t(b0, b1, b2, b3,
                          vsb + (uint32_t)(((kf * 16 + vrow) * 136
                                            + np * 16 + vcol8) * 2));
                mma_f16(o[2*np][0], o[2*np][1], o[2*np][2], o[2*np][3],
                        a0, a1, a2, a3, b0, b1);
                mma_f16(o[2*np+1][0], o[2*np+1][1], o[2*np+1][2], o[2*np+1][3],
                        a0, a1, a2, a3, b2, b3);
            }
        }

        __syncthreads();
        if (kt + 2 < nkt) issue_kv(kt + 2);
    }

    {
        const float inv0 = 1.f / l0;
        const float inv1 = 1.f / l1;
        float* dst0 = g_yp + ((size_t)h * NT_ + tokbase + rg0) * DV_;
        float* dst1 = g_yp + ((size_t)h * NT_ + tokbase + rg1) * DV_;
        #pragma unroll
        for (int nf = 0; nf < 16; ++nf) {
            const int c = nf * 8 + 2 * t4;
            *(float2*)(dst0 + c) = make_float2(o[nf][0] * inv0, o[nf][1] * inv0);
            *(float2*)(dst1 + c) = make_float2(o[nf][2] * inv1, o[nf][3] * inv1);
        }
    }
}

// ---------------------------------------------------------------------------
// Launch
// ---------------------------------------------------------------------------
extern "C" void kernel_launch(void* const* d_in, const int* in_sizes, int n_in,
                              void* d_out, int out_size)
{
    const float* x     = (const float*)d_in[0];
    // d_in[1] = iter_num (unused)
    const float* Wq    = (const float*)d_in[2];
    const float* Wk    = (const float*)d_in[3];
    const float* Wv    = (const float*)d_in[4];
    const float* Wproj = (const float*)d_in[5];
    const float* lobo  = (const float*)d_in[6];
    const float* qnf   = (const float*)d_in[7];
    float* out = (float*)d_out;

    __nv_bfloat16 *xh, *xl, *wth, *wtl, *yh, *yl, *pth, *ptl;
    float *qkv_ptr;
    cudaGetSymbolAddress((void**)&xh, g_xh);
    cudaGetSymbolAddress((void**)&xl, g_xl);
    cudaGetSymbolAddress((void**)&wth, g_wth);
    cudaGetSymbolAddress((void**)&wtl, g_wtl);
    cudaGetSymbolAddress((void**)&yh, g_yh);
    cudaGetSymbolAddress((void**)&yl, g_yl);
    cudaGetSymbolAddress((void**)&pth, g_pth);
    cudaGetSymbolAddress((void**)&ptl, g_ptl);
    cudaGetSymbolAddress((void**)&qkv_ptr, g_qkv);

    cudaFuncSetAttribute(mm_gemm, cudaFuncAttributeMaxDynamicSharedMemorySize,
                         MM_SMEM_BYTES);
    cudaFuncSetAttribute(attn_kernel, cudaFuncAttributeMaxDynamicSharedMemorySize,
                         ATTN_SMEM);

    // Pack/convert inputs to split-bf16; build rope table
    gen_rope<<<(T_ * 32 + 255) / 256, 256>>>();
    pack_wt_t<<<dim3(C_ / 32, NQKV / 32), dim3(32, 8)>>>(Wq, Wk, Wv);
    pack_pt<<<(C_ * DV_ + 255) / 256, 256>>>(Wproj);
    cvt_split<<<(NT_ * C_ + 255) / 256, 256>>>(x, xh, xl, NT_ * C_);

    // Fused QKV projection: [4096,1024] x [1792,1024]^T -> g_qkv (fp32)
    mm_gemm<<<dim3(NQKV / 128, NT_ / 128), 256, MM_SMEM_BYTES>>>(
        xh, xl, wth, wtl, qkv_ptr, C_, NQKV);

    // RoPE + qk-norm + logit scale (base-2) -> fp16 q/k; V -> fp16
    rope_norm_kernel<<<(NT_ * 20) / 8, 256>>>(qnf);
    cvt_vh<<<(NT_ * (G_ * DV_) + 255) / 256, 256>>>();

    // Attention (register-softmax FA2, Q-tile 64, 3 CTAs/SM) -> per-head g_yp
    attn_kernel<<<dim3(T_ / 64, H_, B_), 128, ATTN_SMEM>>>(lobo);

    // Head-sum + split, then output projection
    sum_split_y<<<(NT_ * DV_ + 255) / 256, 256>>>();
    mm_gemm<<<dim3(C_ / 128, NT_ / 128), 256, MM_SMEM_BYTES>>>(
        yh, yl, pth, ptl, out, DV_, C_);
}

// round 11
// speedup vs baseline: 9.1489x; 1.0438x over previous
#include <cuda_runtime.h>
#include <cuda_bf16.h>
#include <cuda_fp16.h>
#include <math.h>
#include <stdint.h>

// Problem constants
#define B_   2
#define T_   2048
#define C_   1024
#define H_   16
#define G_   4
#define DQK_ 64
#define DV_  128
#define NT_  (B_ * T_)        // 4096 tokens
#define NQKV (H_*DQK_ + G_*DQK_ + G_*DV_)   // 1792
#define KOFF (H_*DQK_)        // 1024
#define VOFF (H_*DQK_ + G_*DQK_) // 1280
#define LOG2E_ 1.4426950408889634f

// ---------------------------------------------------------------------------
// Device scratch (no cudaMalloc allowed)
// ---------------------------------------------------------------------------
__device__ __nv_bfloat16 g_xh[(size_t)NT_ * C_];     // x split-bf16 hi
__device__ __nv_bfloat16 g_xl[(size_t)NT_ * C_];     // x split-bf16 lo
__device__ __nv_bfloat16 g_wth[(size_t)NQKV * C_];   // packed W^T [1792][1024] hi
__device__ __nv_bfloat16 g_wtl[(size_t)NQKV * C_];   // lo
__device__ __nv_bfloat16 g_yh[(size_t)NT_ * DV_];    // head-summed attn out hi
__device__ __nv_bfloat16 g_yl[(size_t)NT_ * DV_];    // lo
__device__ __nv_bfloat16 g_pth[(size_t)C_ * DV_];    // Wproj^T [1024][128] hi
__device__ __nv_bfloat16 g_ptl[(size_t)C_ * DV_];    // lo
__device__ float  g_qkv[(size_t)NT_ * NQKV];         // fused projection (fp32)
__device__ __half g_qkvh[(size_t)NT_ * NQKV];        // fp16 q(roped)/k(roped)/v
__device__ float  g_yp[(size_t)H_ * NT_ * DV_];      // per-head attn output
__device__ float2 g_rope[(size_t)T_ * 32];           // (cos,sin) per (t,lane)

// ---------------------------------------------------------------------------
// mma.sync / ldmatrix / cp.async helpers (sm_80+ PTX; valid on compute_103)
// ---------------------------------------------------------------------------
__device__ __forceinline__ void mma_f16(float& d0, float& d1, float& d2, float& d3,
    uint32_t a0, uint32_t a1, uint32_t a2, uint32_t a3, uint32_t b0, uint32_t b1)
{
    asm volatile(
        "mma.sync.aligned.m16n8k16.row.col.f32.f16.f16.f32 "
        "{%0,%1,%2,%3},{%4,%5,%6,%7},{%8,%9},{%0,%1,%2,%3};"
        : "+f"(d0), "+f"(d1), "+f"(d2), "+f"(d3)
        : "r"(a0), "r"(a1), "r"(a2), "r"(a3), "r"(b0), "r"(b1));
}

__device__ __forceinline__ void mma_bf16(float& d0, float& d1, float& d2, float& d3,
    uint32_t a0, uint32_t a1, uint32_t a2, uint32_t a3, uint32_t b0, uint32_t b1)
{
    asm volatile(
        "mma.sync.aligned.m16n8k16.row.col.f32.bf16.bf16.f32 "
        "{%0,%1,%2,%3},{%4,%5,%6,%7},{%8,%9},{%0,%1,%2,%3};"
        : "+f"(d0), "+f"(d1), "+f"(d2), "+f"(d3)
        : "r"(a0), "r"(a1), "r"(a2), "r"(a3), "r"(b0), "r"(b1));
}

__device__ __forceinline__ void ldsm_x4(uint32_t& r0, uint32_t& r1,
                                        uint32_t& r2, uint32_t& r3, uint32_t a)
{
    asm volatile("ldmatrix.sync.aligned.m8n8.x4.shared.b16 {%0,%1,%2,%3}, [%4];"
                 : "=r"(r0), "=r"(r1), "=r"(r2), "=r"(r3) : "r"(a));
}

__device__ __forceinline__ void ldsm_x4_t(uint32_t& r0, uint32_t& r1,
                                          uint32_t& r2, uint32_t& r3, uint32_t a)
{
    asm volatile("ldmatrix.sync.aligned.m8n8.x4.trans.shared.b16 {%0,%1,%2,%3}, [%4];"
                 : "=r"(r0), "=r"(r1), "=r"(r2), "=r"(r3) : "r"(a));
}

__device__ __forceinline__ uint32_t smem_u32(const void* p) {
    uint32_t a;
    asm("{ .reg .u64 t; cvta.to.shared.u64 t, %1; cvt.u32.u64 %0, t; }"
        : "=r"(a) : "l"(p));
    return a;
}

// pack (lo,hi) floats to f16x2 then exp2 in fp16 (MUFU.EX2 on both halves)
__device__ __forceinline__ uint32_t exp2_pack(float lo, float hi) {
    uint32_t r;
    asm("cvt.rn.f16x2.f32 %0, %1, %2;" : "=r"(r) : "f"(hi), "f"(lo));
    asm("ex2.approx.f16x2 %0, %0;" : "+r"(r));
    return r;
}

#define CP_ASYNC16(dst, src) \
    asm volatile("cp.async.cg.shared.global [%0], [%1], 16;" \
                 :: "r"(dst), "l"(src) : "memory")
#define CP_COMMIT() asm volatile("cp.async.commit_group;" ::: "memory")
#define CP_WAIT(n)  asm volatile("cp.async.wait_group %0;" :: "n"(n) : "memory")

// ---------------------------------------------------------------------------
// Split-bf16 GEMM: 3-stage cp.async, XOR swizzle, one sync/stage, ldmatrix
// frags, 2 CTAs/SM. D = hh + hl + lh. Optional fp16 mirror output (Hout).
// ---------------------------------------------------------------------------
#define MM_TILE_B (128 * 64)
#define MM_STAGE_B (4 * MM_TILE_B)
#define MM_SMEM_BYTES (3 * MM_STAGE_B)         // 98304

__global__ __launch_bounds__(256, 2) void mm_gemm(
    const __nv_bfloat16* __restrict__ Ah, const __nv_bfloat16* __restrict__ Al,
    const __nv_bfloat16* __restrict__ Bh, const __nv_bfloat16* __restrict__ Bl,
    float* __restrict__ Cout, __half* __restrict__ Hout, int K, int ldc)
{
    extern __shared__ __nv_bfloat16 smd[];

    const int tid  = threadIdx.x;
    const int wid  = tid >> 5;
    const int lane = tid & 31;
    const int g8   = lane >> 2;
    const int t4   = lane & 3;
    const int m0   = blockIdx.y * 128;
    const int n0   = blockIdx.x * 128;
    const int ms   = wid & 3;
    const int ws   = wid >> 2;

    const int lrow  = (lane & 7) + ((lane >> 3) & 1) * 8;
    const int lcol8 = (lane >> 4) * 8;

    const __nv_bfloat16* srcs[4] = {
        Ah + (size_t)m0 * K, Al + (size_t)m0 * K,
        Bh + (size_t)n0 * K, Bl + (size_t)n0 * K };

    const int f_row = tid >> 2;
    const int f_ch  = tid & 3;

    // Precomputed cp.async dst offsets (element units within a stage)
    uint32_t dsto[8];
    #pragma unroll
    for (int t = 0; t < 8; ++t) {
        const int tl  = t >> 1;
        const int row = ((t & 1) << 6) + f_row;
        const int cs  = f_ch ^ ((row >> 1) & 3);
        dsto[t] = (uint32_t)((tl * 128 + row) * 32 + cs * 8);
    }
    const uint32_t smb0 = smem_u32(smd);

    auto issue_stage = [&](int s, int st) {
        const int k0 = s << 5;
        const uint32_t base = smb0 + (uint32_t)st * MM_STAGE_B;
        #pragma unroll
        for (int t = 0; t < 8; ++t) {
            const int tl  = t >> 1;
            const int row = ((t & 1) << 6) + f_row;
            const __nv_bfloat16* src = srcs[tl] + (size_t)row * K + k0 + f_ch * 8;
            CP_ASYNC16(base + dsto[t] * 2, src);
        }
        CP_COMMIT();
    };

    float acc[2][8][4];
    #pragma unroll
    for (int mf = 0; mf < 2; mf++)
        #pragma unroll
        for (int nf = 0; nf < 8; nf++)
            #pragma unroll
            for (int i = 0; i < 4; i++) acc[mf][nf][i] = 0.f;

    const int nst = K >> 5;
    issue_stage(0, 0);
    if (nst > 1) issue_stage(1, 1);

    int st = 0;
    for (int s = 0; s < nst; ++s) {
        if (s + 1 < nst) CP_WAIT(1);
        else             CP_WAIT(0);
        __syncthreads();
        if (s + 2 < nst) {
            int st2 = st + 2; if (st2 >= 3) st2 -= 3;
            issue_stage(s + 2, st2);
        }

        const uint32_t smb = smb0 + (uint32_t)st * MM_STAGE_B;

        #pragma unroll
        for (int ks = 0; ks < 2; ++ks) {
            const int cb = ks * 2 + (lcol8 >> 3);

            uint32_t ah[2][4], al[2][4];
            #pragma unroll
            for (int mf = 0; mf < 2; ++mf) {
                const int row = ms * 32 + mf * 16 + lrow;
                const uint32_t off = (uint32_t)(row * 64
                                   + ((cb ^ ((row >> 1) & 3)) << 4));
                ldsm_x4(ah[mf][0], ah[mf][1], ah[mf][2], ah[mf][3],
                        smb + 0 * MM_TILE_B + off);
                ldsm_x4(al[mf][0], al[mf][1], al[mf][2], al[mf][3],
                        smb + 1 * MM_TILE_B + off);
            }

            #pragma unroll
            for (int np = 0; np < 4; ++np) {
                const int row = ws * 64 + np * 16 + lrow;
                const uint32_t off = (uint32_t)(row * 64
                                   + ((cb ^ ((row >> 1) & 3)) << 4));
                uint32_t bh[4], bl[4];
                ldsm_x4(bh[0], bh[1], bh[2], bh[3], smb + 2 * MM_TILE_B + off);
                ldsm_x4(bl[0], bl[1], bl[2], bl[3], smb + 3 * MM_TILE_B + off);
                #pragma unroll
                for (int e = 0; e < 2; ++e) {
                    const int nf = np * 2 + e;
                    const uint32_t bh0 = bh[e], bh1 = bh[2 + e];
                    const uint32_t bl0 = bl[e], bl1 = bl[2 + e];
                    #pragma unroll
                    for (int mf = 0; mf < 2; ++mf) {
                        float* d = acc[mf][nf];
                        mma_bf16(d[0], d[1], d[2], d[3],
                                 ah[mf][0], ah[mf][1], ah[mf][2], ah[mf][3],
                                 bh0, bh1);
                        mma_bf16(d[0], d[1], d[2], d[3],
                                 ah[mf][0], ah[mf][1], ah[mf][2], ah[mf][3],
                                 bl0, bl1);
                        mma_bf16(d[0], d[1], d[2], d[3],
                                 al[mf][0], al[mf][1], al[mf][2], al[mf][3],
                                 bh0, bh1);
                    }
                }
            }
        }
        if (++st >= 3) st -= 3;
    }

    #pragma unroll
    for (int mf = 0; mf < 2; ++mf) {
        const int r = m0 + ms * 32 + mf * 16 + g8;
        #pragma unroll
        for (int nf = 0; nf < 8; ++nf) {
            const int c = n0 + ws * 64 + nf * 8 + 2 * t4;
            *(float2*)(Cout + (size_t)r * ldc + c) =
                make_float2(acc[mf][nf][0], acc[mf][nf][1]);
            *(float2*)(Cout + (size_t)(r + 8) * ldc + c) =
                make_float2(acc[mf][nf][2], acc[mf][nf][3]);
            if (Hout) {
                *(__half2*)(Hout + (size_t)r * ldc + c) =
                    __floats2half2_rn(acc[mf][nf][0], acc[mf][nf][1]);
                *(__half2*)(Hout + (size_t)(r + 8) * ldc + c) =
                    __floats2half2_rn(acc[mf][nf][2], acc[mf][nf][3]);
            }
        }
    }
}

// ---------------------------------------------------------------------------
// Conversion / packing kernels
// ---------------------------------------------------------------------------
// Vectorized split: 4 floats per thread (n must be multiple of 4)
__global__ void cvt_split(const float* __restrict__ in,
                          __nv_bfloat16* __restrict__ hi,
                          __nv_bfloat16* __restrict__ lo, int n4)
{
    const int i = blockIdx.x * blockDim.x + threadIdx.x;
    if (i >= n4) return;
    const float4 v = ((const float4*)in)[i];
    const __nv_bfloat16 h0 = __float2bfloat16(v.x);
    const __nv_bfloat16 h1 = __float2bfloat16(v.y);
    const __nv_bfloat16 h2 = __float2bfloat16(v.z);
    const __nv_bfloat16 h3 = __float2bfloat16(v.w);
    ((__nv_bfloat162*)hi)[2*i]   = __nv_bfloat162(h0, h1);
    ((__nv_bfloat162*)hi)[2*i+1] = __nv_bfloat162(h2, h3);
    ((__nv_bfloat162*)lo)[2*i] = __nv_bfloat162(
        __float2bfloat16(v.x - __bfloat162float(h0)),
        __float2bfloat16(v.y - __bfloat162float(h1)));
    ((__nv_bfloat162*)lo)[2*i+1] = __nv_bfloat162(
        __float2bfloat16(v.z - __bfloat162float(h2)),
        __float2bfloat16(v.w - __bfloat162float(h3)));
}

__global__ void pack_wt_t(const float* __restrict__ Wq,
                          const float* __restrict__ Wk,
                          const float* __restrict__ Wv)
{
    __shared__ float tile[32][33];
    const int tx = threadIdx.x, ty = threadIdx.y;
    const int k0 = blockIdx.x * 32;
    const int n0 = blockIdx.y * 32;

    const float* W; int nw, noff;
    if (n0 < KOFF)      { W = Wq; nw = H_*DQK_; noff = n0; }
    else if (n0 < VOFF) { W = Wk; nw = G_*DQK_; noff = n0 - KOFF; }
    else                { W = Wv; nw = G_*DV_;  noff = n0 - VOFF; }

    #pragma unroll
    for (int j = 0; j < 4; ++j)
        tile[ty + j * 8][tx] = W[(size_t)(k0 + ty + j * 8) * nw + noff + tx];
    __syncthreads();
    #pragma unroll
    for (int j = 0; j < 4; ++j) {
        const float v = tile[tx][ty + j * 8];
        const __nv_bfloat16 h = __float2bfloat16(v);
        const size_t o = (size_t)(n0 + ty + j * 8) * C_ + k0 + tx;
        g_wth[o] = h;
        g_wtl[o] = __float2bfloat16(v - __bfloat162float(h));
    }
}

__global__ void pack_pt(const float* __restrict__ Wp)
{
    const int i = blockIdx.x * blockDim.x + threadIdx.x;
    if (i >= C_ * DV_) return;
    const int nn = i / DV_;
    const int k  = i % DV_;
    const float v = Wp[(size_t)k * C_ + nn];
    const __nv_bfloat16 h = __float2bfloat16(v);
    g_pth[i] = h;
    g_ptl[i] = __float2bfloat16(v - __bfloat162float(h));
}

// Head-sum + bf16 split of attention output, 4 elems/thread
__global__ void sum_split_y()
{
    const int i = blockIdx.x * blockDim.x + threadIdx.x;
    if (i >= (NT_ * DV_) / 4) return;
    float4 s = make_float4(0.f, 0.f, 0.f, 0.f);
    #pragma unroll
    for (int h = 0; h < H_; ++h) {
        const float4 v = ((const float4*)(g_yp + (size_t)h * NT_ * DV_))[i];
        s.x += v.x; s.y += v.y; s.z += v.z; s.w += v.w;
    }
    const __nv_bfloat16 h0 = __float2bfloat16(s.x);
    const __nv_bfloat16 h1 = __float2bfloat16(s.y);
    const __nv_bfloat16 h2 = __float2bfloat16(s.z);
    const __nv_bfloat16 h3 = __float2bfloat16(s.w);
    ((__nv_bfloat162*)g_yh)[2*i]   = __nv_bfloat162(h0, h1);
    ((__nv_bfloat162*)g_yh)[2*i+1] = __nv_bfloat162(h2, h3);
    ((__nv_bfloat162*)g_yl)[2*i] = __nv_bfloat162(
        __float2bfloat16(s.x - __bfloat162float(h0)),
        __float2bfloat16(s.y - __bfloat162float(h1)));
    ((__nv_bfloat162*)g_yl)[2*i+1] = __nv_bfloat162(
        __float2bfloat16(s.z - __bfloat162float(h2)),
        __float2bfloat16(s.w - __bfloat162float(h3)));
}

// ---------------------------------------------------------------------------
// RoPE table + RoPE/norm kernel (base-2 logit scale folded into q)
// ---------------------------------------------------------------------------
__global__ void gen_rope()
{
    const int i = blockIdx.x * blockDim.x + threadIdx.x;
    if (i >= T_ * 32) return;
    const int t = i >> 5, lane = i & 31;
    const float inv = __expf(-(float)lane * 0.28782313662425574f); // ln(1e4)/32
    const float ang = (float)t * inv;
    float s, c;
    sincosf(ang, &s, &c);
    g_rope[i] = make_float2(c, s);
}

__global__ void rope_norm_kernel(const float* __restrict__ qnf)
{
    const int warp = (blockIdx.x * blockDim.x + threadIdx.x) >> 5;
    const int lane = threadIdx.x & 31;
    if (warp >= NT_ * 20) return;
    const int token = warp / 20;
    const int slot  = warp % 20;
    const int t     = token & (T_ - 1);

    const size_t off = (size_t)token * NQKV
                     + ((slot < 16) ? slot * DQK_ : KOFF + (slot - 16) * DQK_);
    const float* src = g_qkv + off;
    __half* dst = g_qkvh + off;

    const float x0 = src[lane];
    const float x1 = src[lane + 32];

    const float2 cs = g_rope[(t << 5) + lane];
    const float c = cs.x, s = cs.y;

    const float r0 = x0 * c - x1 * s;
    const float r1 = x1 * c + x0 * s;

    float ss = r0 * r0 + r1 * r1;
    #pragma unroll
    for (int o = 16; o > 0; o >>= 1) ss += __shfl_xor_sync(0xFFFFFFFFu, ss, o);

    float scale = 1.f / (sqrtf(ss) + 1e-6f);
    if (slot < 16) scale *= qnf[0] * LOG2E_;

    dst[lane]      = __float2half(r0 * scale);
    dst[lane + 32] = __float2half(r1 * scale);
}

// ---------------------------------------------------------------------------
// Flash attention, FA2 register softmax (exp2 domain), cp.async double-buffer
// with ONE sync per iteration (fill kt+1 issued right after top barrier; its
// target stage's readers all completed before that barrier). 128 thr / 4
// warps; Q-tile 64, K-tile 64, 3 CTAs/SM.
// ---------------------------------------------------------------------------
struct AttnSmem {
    __half Qs[64][72];
    __half Ks[2][64][72];
    __half Vs[2][64][136];
};
#define ATTN_SMEM ((int)sizeof(AttnSmem))

__global__ __launch_bounds__(128, 3) void attn_kernel(const float* __restrict__ lobo)
{
    extern __shared__ char smem_raw[];
    AttnSmem& S = *reinterpret_cast<AttnSmem*>(smem_raw);

    const int tid  = threadIdx.x;
    const int wid  = tid >> 5;
    const int lane = tid & 31;
    const int g8   = lane >> 2;
    const int t4   = lane & 3;

    const int qt = (gridDim.x - 1 - blockIdx.x);  // long blocks first
    const int h  = blockIdx.y;
    const int b  = blockIdx.z;
    const int gq = h >> 2;
    const int q0 = qt * 64;
    const size_t tokbase = (size_t)b * T_;

    const int krow  = lane & 7;
    const int kcol8 = (lane >> 3) * 8;
    const int vrow  = (lane & 7) + ((lane >> 3) & 1) * 8;
    const int vcol8 = (lane >> 4) * 8;

    // Fill Q tile (64 x 64 halves)
    #pragma unroll
    for (int i = 0; i < 16; ++i) {
        const int cid = tid + i * 128;
        const int row = cid >> 5;
        const int dp  = cid & 31;
        const uint32_t v = *(const uint32_t*)
            (g_qkvh + (tokbase + q0 + row) * NQKV + h * DQK_ + 2 * dp);
        *(uint32_t*)&S.Qs[row][2 * dp] = v;
    }

    const int rbase = (wid << 4);
    const int rg0 = q0 + rbase + g8;
    const int rg1 = rg0 + 8;

    float m0 = lobo[h] * LOG2E_, m1 = m0;
    float l0 = 1.f, l1 = 1.f;
    float o[16][4];
    #pragma unroll
    for (int nf = 0; nf < 16; nf++)
        #pragma unroll
        for (int i = 0; i < 4; i++) o[nf][i] = 0.f;

    uint32_t qf[4][4];
    const uint32_t ONES = 0x3C003C00u;   // half2(1,1)

    const int nkt = qt + 1;

    auto issue_kv = [&](int kt) {
        const int st = kt & 1;
        const int k0 = kt * 64;
        #pragma unroll
        for (int j = 0; j < 4; ++j) {
            const int idx = tid + j * 128;
            const int row = idx >> 3, c = idx & 7;
            CP_ASYNC16(smem_u32(&S.Ks[st][row][c * 8]),
                g_qkvh + (tokbase + k0 + row) * NQKV + KOFF + gq * DQK_ + c * 8);
        }
        #pragma unroll
        for (int j = 0; j < 8; ++j) {
            const int idx = tid + j * 128;
            const int row = idx >> 4, c = idx & 15;
            CP_ASYNC16(smem_u32(&S.Vs[st][row][c * 8]),
                g_qkvh + (tokbase + k0 + row) * NQKV + VOFF + gq * DV_ + c * 8);
        }
        CP_COMMIT();
    };

    issue_kv(0);

    for (int kt = 0; kt < nkt; ++kt) {
        const int st = kt & 1;
        CP_WAIT(0);
        __syncthreads();        // stage kt ready; prev-iter readers done
        if (kt + 1 < nkt) issue_kv(kt + 1);   // fills the other stage

        if (kt == 0) {
            #pragma unroll
            for (int kf = 0; kf < 4; ++kf) {
                const int cb = kf * 16 + 2 * t4;
                qf[kf][0] = *(const uint32_t*)&S.Qs[rbase + g8    ][cb];
                qf[kf][1] = *(const uint32_t*)&S.Qs[rbase + g8 + 8][cb];
                qf[kf][2] = *(const uint32_t*)&S.Qs[rbase + g8    ][cb + 8];
                qf[kf][3] = *(const uint32_t*)&S.Qs[rbase + g8 + 8][cb + 8];
            }
        }

        // --- S = Q K^T ---
        float s[8][4];
        #pragma unroll
        for (int nf = 0; nf < 8; nf++)
            #pragma unroll
            for (int i = 0; i < 4; i++) s[nf][i] = 0.f;

        const uint32_t ksb = smem_u32(&S.Ks[st][0][0]);
        #pragma unroll
        for (int kp = 0; kp < 2; ++kp) {
            #pragma unroll
            for (int nf = 0; nf < 8; ++nf) {
                uint32_t b0a, b1a, b0b, b1b;
                ldsm_x4(b0a, b1a, b0b, b1b,
                        ksb + (uint32_t)(((nf * 8 + krow) * 72
                                          + kp * 32 + kcol8) * 2));
                mma_f16(s[nf][0], s[nf][1], s[nf][2], s[nf][3],
                        qf[2*kp][0], qf[2*kp][1], qf[2*kp][2], qf[2*kp][3],
                        b0a, b1a);
                mma_f16(s[nf][0], s[nf][1], s[nf][2], s[nf][3],
                        qf[2*kp+1][0], qf[2*kp+1][1], qf[2*kp+1][2], qf[2*kp+1][3],
                        b0b, b1b);
            }
        }

        if (kt == nkt - 1) {   // diagonal tile
            const int k0 = kt * 64;
            #pragma unroll
            for (int nf = 0; nf < 8; ++nf) {
                const int c = k0 + nf * 8 + 2 * t4;
                if (c     > rg0) s[nf][0] = -1e30f;
                if (c + 1 > rg0) s[nf][1] = -1e30f;
                if (c     > rg1) s[nf][2] = -1e30f;
                if (c + 1 > rg1) s[nf][3] = -1e30f;
            }
        }

        // Row max
        float mx0 = -1e30f, mx1 = -1e30f;
        #pragma unroll
        for (int nf = 0; nf < 8; ++nf) {
            mx0 = fmaxf(mx0, fmaxf(s[nf][0], s[nf][1]));
            mx1 = fmaxf(mx1, fmaxf(s[nf][2], s[nf][3]));
        }
        mx0 = fmaxf(mx0, __shfl_xor_sync(0xFFFFFFFFu, mx0, 1));
        mx0 = fmaxf(mx0, __shfl_xor_sync(0xFFFFFFFFu, mx0, 2));
        mx1 = fmaxf(mx1, __shfl_xor_sync(0xFFFFFFFFu, mx1, 1));
        mx1 = fmaxf(mx1, __shfl_xor_sync(0xFFFFFFFFu, mx1, 2));

        const float mn0 = fmaxf(m0, mx0);
        const float mn1 = fmaxf(m1, mx1);
        const float cr0 = exp2f(m0 - mn0);
        const float cr1 = exp2f(m1 - mn1);
        m0 = mn0; m1 = mn1;

        // P = exp2(S - m) via packed fp16 MUFU
        uint32_t pa[8], pb[8];
        #pragma unroll
        for (int nf = 0; nf < 8; ++nf) {
            pa[nf] = exp2_pack(s[nf][0] - mn0, s[nf][1] - mn0);
            pb[nf] = exp2_pack(s[nf][2] - mn1, s[nf][3] - mn1);
        }

        // Row sums via ones-MMA
        float sf0 = 0.f, sf1 = 0.f, sf2 = 0.f, sf3 = 0.f;
        #pragma unroll
        for (int kf = 0; kf < 4; ++kf)
            mma_f16(sf0, sf1, sf2, sf3,
                    pa[2*kf], pb[2*kf], pa[2*kf+1], pb[2*kf+1], ONES, ONES);
        l0 = l0 * cr0 + sf0;
        l1 = l1 * cr1 + sf2;

        // Rescale O only if any row's max moved
        if (__ballot_sync(0xFFFFFFFFu, (cr0 < 1.f) || (cr1 < 1.f))) {
            #pragma unroll
            for (int nf = 0; nf < 16; ++nf) {
                o[nf][0] *= cr0; o[nf][1] *= cr0;
                o[nf][2] *= cr1; o[nf][3] *= cr1;
            }
        }

        // O += P V
        const uint32_t vsb = smem_u32(&S.Vs[st][0][0]);
        #pragma unroll
        for (int kf = 0; kf < 4; ++kf) {
            const uint32_t a0 = pa[2 * kf];
            const uint32_t a1 = pb[2 * kf];
            const uint32_t a2 = pa[2 * kf + 1];
            const uint32_t a3 = pb[2 * kf + 1];
            #pragma unroll
            for (int np = 0; np < 8; ++np) {
                uint32_t b0, b1, b2, b3;
                ldsm_x4_t(b0, b1, b2, b3,
                          vsb + (uint32_t)(((kf * 16 + vrow) * 136
                                            + np * 16 + vcol8) * 2));
                mma_f16(o[2*np][0], o[2*np][1], o[2*np][2], o[2*np][3],
                        a0, a1, a2, a3, b0, b1);
                mma_f16(o[2*np+1][0], o[2*np+1][1], o[2*np+1][2], o[2*np+1][3],
                        a0, a1, a2, a3, b2, b3);
            }
        }
    }

    {
        const float inv0 = 1.f / l0;
        const float inv1 = 1.f / l1;
        float* dst0 = g_yp + ((size_t)h * NT_ + tokbase + rg0) * DV_;
        float* dst1 = g_yp + ((size_t)h * NT_ + tokbase + rg1) * DV_;
        #pragma unroll
        for (int nf = 0; nf < 16; ++nf) {
            const int c = nf * 8 + 2 * t4;
            *(float2*)(dst0 + c) = make_float2(o[nf][0] * inv0, o[nf][1] * inv0);
            *(float2*)(dst1 + c) = make_float2(o[nf][2] * inv1, o[nf][3] * inv1);
        }
    }
}

// ---------------------------------------------------------------------------
// Launch
// ---------------------------------------------------------------------------
extern "C" void kernel_launch(void* const* d_in, const int* in_sizes, int n_in,
                              void* d_out, int out_size)
{
    const float* x     = (const float*)d_in[0];
    // d_in[1] = iter_num (unused)
    const float* Wq    = (const float*)d_in[2];
    const float* Wk    = (const float*)d_in[3];
    const float* Wv    = (const float*)d_in[4];
    const float* Wproj = (const float*)d_in[5];
    const float* lobo  = (const float*)d_in[6];
    const float* qnf   = (const float*)d_in[7];
    float* out = (float*)d_out;

    __nv_bfloat16 *xh, *xl, *wth, *wtl, *yh, *yl, *pth, *ptl;
    float *qkv_ptr;
    __half *qkvh_ptr;
    cudaGetSymbolAddress((void**)&xh, g_xh);
    cudaGetSymbolAddress((void**)&xl, g_xl);
    cudaGetSymbolAddress((void**)&wth, g_wth);
    cudaGetSymbolAddress((void**)&wtl, g_wtl);
    cudaGetSymbolAddress((void**)&yh, g_yh);
    cudaGetSymbolAddress((void**)&yl, g_yl);
    cudaGetSymbolAddress((void**)&pth, g_pth);
    cudaGetSymbolAddress((void**)&ptl, g_ptl);
    cudaGetSymbolAddress((void**)&qkv_ptr, g_qkv);
    cudaGetSymbolAddress((void**)&qkvh_ptr, g_qkvh);

    cudaFuncSetAttribute(mm_gemm, cudaFuncAttributeMaxDynamicSharedMemorySize,
                         MM_SMEM_BYTES);
    cudaFuncSetAttribute(attn_kernel, cudaFuncAttributeMaxDynamicSharedMemorySize,
                         ATTN_SMEM);

    // Pack/convert inputs to split-bf16; build rope table
    gen_rope<<<(T_ * 32 + 255) / 256, 256>>>();
    pack_wt_t<<<dim3(C_ / 32, NQKV / 32), dim3(32, 8)>>>(Wq, Wk, Wv);
    pack_pt<<<(C_ * DV_ + 255) / 256, 256>>>(Wproj);
    cvt_split<<<(NT_ * C_ / 4 + 255) / 256, 256>>>(x, xh, xl, NT_ * C_ / 4);

    // Fused QKV projection -> fp32 g_qkv + fp16 mirror (V region usable as-is)
    mm_gemm<<<dim3(NQKV / 128, NT_ / 128), 256, MM_SMEM_BYTES>>>(
        xh, xl, wth, wtl, qkv_ptr, qkvh_ptr, C_, NQKV);

    // RoPE + qk-norm + logit scale (base-2) -> fp16 q/k (overwrites mirror)
    rope_norm_kernel<<<(NT_ * 20) / 8, 256>>>(qnf);

    // Attention (register-softmax FA2, one-sync pipeline, 3 CTAs/SM)
    attn_kernel<<<dim3(T_ / 64, H_, B_), 128, ATTN_SMEM>>>(lobo);

    // Head-sum + split, then output projection
    sum_split_y<<<(NT_ * DV_ / 4 + 255) / 256, 256>>>();
    mm_gemm<<<dim3(C_ / 128, NT_ / 128), 256, MM_SMEM_BYTES>>>(
        yh, yl, pth, ptl, out, nullptr, DV_, C_);
}